// round 6
// baseline (speedup 1.0000x reference)
#include <cuda_runtime.h>
#include <cuda_bf16.h>

#define N_NODES 50000
#define N_EDGES 500000
#define H 128
#define G_GRAPHS 100
#define NPG 500
#define NPROT 400
#define PN 35
#define LN 11
#define NLAYERS 4
#define EPS 1e-5f
#define NE_TILE 64
#define TP 66   // transposed smem row pad (floats) — node/proj kernels

// ---------------- scratch ----------------
__device__ float g_h[N_NODES * H];
__device__ float g_P1[N_NODES * H];
__device__ float g_P2[N_NODES * H];
__device__ float g_agg[N_NODES * H];
__device__ float g_U[N_NODES * H];
__device__ float g_pos[N_NODES * 3];
__device__ float g_posdelta[N_NODES * 3];
__device__ float g_deg[N_NODES];
__device__ float g_bnstats[2 * H];
__device__ float g_gfeat[G_GRAPHS * 2 * H];
__device__ int g_rowcur[N_NODES];
__device__ int g_srow[N_EDGES];
__device__ int g_scol[N_EDGES];
__device__ int g_sperm[N_EDGES];

__device__ __forceinline__ float silu_f(float x) {
    return x / (1.f + __expf(-x));
}

// ---- packed f32x2 helpers (FFMA2 path for node/proj kernels) ----
__device__ __forceinline__ unsigned long long fma2(unsigned long long a,
                                                   unsigned long long b,
                                                   unsigned long long c) {
    unsigned long long d;
    asm("fma.rn.f32x2 %0, %1, %2, %3;" : "=l"(d) : "l"(a), "l"(b), "l"(c));
    return d;
}
__device__ __forceinline__ unsigned long long dup2(float x) {
    unsigned long long d;
    unsigned int xi = __float_as_uint(x);
    asm("mov.b64 %0, {%1, %1};" : "=l"(d) : "r"(xi));
    return d;
}
__device__ __forceinline__ float2 unpack2(unsigned long long v) {
    unsigned int lo, hi;
    asm("mov.b64 {%0, %1}, %2;" : "=r"(lo), "=r"(hi) : "l"(v));
    float2 r;
    r.x = __uint_as_float(lo);
    r.y = __uint_as_float(hi);
    return r;
}

// ---- tf32 mma helpers ----
__device__ __forceinline__ float tf32f(float f) {
    unsigned int u;
    asm("cvt.rna.tf32.f32 %0, %1;" : "=r"(u) : "f"(f));
    return __uint_as_float(u);
}
__device__ __forceinline__ void mma_tf32(float* c, const uint4& a, const uint2& b) {
    asm volatile(
        "mma.sync.aligned.m16n8k8.row.col.f32.tf32.tf32.f32 "
        "{%0,%1,%2,%3}, {%4,%5,%6,%7}, {%8,%9}, {%0,%1,%2,%3};"
        : "+f"(c[0]), "+f"(c[1]), "+f"(c[2]), "+f"(c[3])
        : "r"(a.x), "r"(a.y), "r"(a.z), "r"(a.w), "r"(b.x), "r"(b.y));
}
// A-fragment flat index for value at (row e in 0..63, col k in 0..127)
__device__ __forceinline__ int fragA_idx(int e, int k) {
    int lane = ((e & 7) << 2) | (k & 3);
    int reg = ((e >> 3) & 1) | (((k >> 2) & 1) << 1);
    return ((((e >> 4) * 16 + (k >> 3)) << 7)) + (lane << 2) + reg;
}

// ---------------- K1: embed ----------------
__global__ void k_embed(const float* __restrict__ x, const float* __restrict__ pos_in,
                        const float* __restrict__ Wp, const float* __restrict__ bp,
                        const float* __restrict__ Wl, const float* __restrict__ bl) {
    __shared__ float xs[PN];
    const int i = blockIdx.x;
    const int t = threadIdx.x;
    if (t < PN) xs[t] = x[i * PN + t];
    if (t == 0) g_deg[i] = 0.f;
    if (t < 3) g_pos[i * 3 + t] = pos_in[i * 3 + t];
    if (i == 0 && t < H) { g_bnstats[t] = 0.f; g_bnstats[H + t] = 0.f; }
    __syncthreads();
    const bool isp = (i % NPG) < NPROT;
    const float* W = isp ? Wp : Wl;
    const float* b = isp ? bp : bl;
    const int nk = isp ? PN : LN;
    float acc = b[t];
    for (int k = 0; k < nk; k++) acc += xs[k] * W[k * H + t];
    g_h[i * H + t] = acc;
}

// ---------------- K2: bnstats + degree ----------------
#define DEG_BLOCKS ((N_EDGES + 511) / 512)
__global__ __launch_bounds__(512) void k_stats_deg(const int* __restrict__ ei) {
    const int t = threadIdx.x;
    if (blockIdx.x < 256) {
        const int j = t & 127;
        const int g2 = t >> 7;
        float s = 0.f, s2 = 0.f;
        for (int i = blockIdx.x * 4 + g2; i < N_NODES; i += 1024) {
            float v = g_h[i * H + j];
            s += v; s2 += v * v;
        }
        atomicAdd(&g_bnstats[j], s);
        atomicAdd(&g_bnstats[H + j], s2);
    } else {
        const int e = (blockIdx.x - 256) * 512 + t;
        if (e < N_EDGES) atomicAdd(&g_deg[ei[e]], 1.0f);
    }
}

// ---------------- K3: bnapply + degree scan ----------------
#define BNA_BLOCKS ((N_NODES * H) / 512)
__global__ __launch_bounds__(512) void k_bnapply_scan(const float* __restrict__ gamma,
                                                      const float* __restrict__ beta) {
    const int t = threadIdx.x;
    if (blockIdx.x < BNA_BLOCKS) {
        const int idx = blockIdx.x * 512 + t;
        const int j = idx & (H - 1);
        const float inv_n = 1.f / (float)N_NODES;
        float mu = g_bnstats[j] * inv_n;
        float var = g_bnstats[H + j] * inv_n - mu * mu;
        g_h[idx] = (g_h[idx] - mu) * rsqrtf(var + EPS) * gamma[j] + beta[j];
    } else {
        __shared__ int sums[512];
        const int chunk = 98;
        int base = t * chunk;
        int lim = min(base + chunk, N_NODES);
        int s = 0;
        for (int i = base; i < lim; i++) s += (int)g_deg[i];
        sums[t] = s;
        __syncthreads();
        for (int off = 1; off < 512; off <<= 1) {
            int v = (t >= off) ? sums[t - off] : 0;
            __syncthreads();
            sums[t] += v;
            __syncthreads();
        }
        int run = (t == 0) ? 0 : sums[t - 1];
        for (int i = base; i < lim; i++) {
            g_rowcur[i] = run;
            run += (int)g_deg[i];
        }
    }
}

// ---------------- counting-sort scatter ----------------
__global__ __launch_bounds__(512) void k_perm(const int* __restrict__ ei) {
    const int e = blockIdx.x * 512 + threadIdx.x;
    if (e >= N_EDGES) return;
    int r = ei[e];
    int p = atomicAdd(&g_rowcur[r], 1);
    g_srow[p] = r;
    g_scol[p] = ei[N_EDGES + e];
    g_sperm[p] = e;
}

// ---------------- per-layer node projection (FFMA2, 1024 thr) ----------------
__global__ __launch_bounds__(1024, 1) void k_proj(const float* __restrict__ w,
                                                  const float* __restrict__ b1) {
    extern __shared__ float sm[];
    float* w_s = sm;            // [128][256]
    float* a_t = sm + 32768;    // [128 k][TP]
    const int t = threadIdx.x;
    const int n0 = blockIdx.x * 64;

    for (int i = t; i < 32768; i += 1024) {
        int k = i >> 8, jj = i & 255;
        int srcrow = (jj < 128) ? k : (128 + k);
        w_s[i] = w[srcrow * H + (jj & 127)];
    }
    for (int i = t; i < 8192; i += 1024) {
        int n = i >> 7, k = i & 127;
        int gi = n0 + n;
        a_t[k * TP + n] = (gi < N_NODES) ? g_h[gi * H + k] : 0.f;
    }
    for (int i = t; i < 64 * H; i += 1024) {
        int gi = n0 + (i >> 7);
        if (gi < N_NODES) g_agg[gi * H + (i & 127)] = 0.f;
    }
    if (t < 192) {
        int gi = n0 + t / 3;
        if (gi < N_NODES) g_posdelta[gi * 3 + t % 3] = 0.f;
    }
    __syncthreads();

    const int j0 = (t & 127) * 2;
    const int eh = t >> 7;
    const int nb = eh * 8;
    unsigned long long acc0[4], acc1[4];
#pragma unroll
    for (int p = 0; p < 4; p++) { acc0[p] = 0ull; acc1[p] = 0ull; }

#pragma unroll 4
    for (int k = 0; k < 128; k++) {
        float2 wp = *(const float2*)&w_s[k * 256 + j0];
        unsigned long long bd0 = dup2(wp.x), bd1 = dup2(wp.y);
        const float* ar = &a_t[k * TP + nb];
#pragma unroll
        for (int p = 0; p < 4; p++) {
            unsigned long long av = *(const unsigned long long*)&ar[2 * p];
            acc0[p] = fma2(av, bd0, acc0[p]);
            acc1[p] = fma2(av, bd1, acc1[p]);
        }
    }

    const int half = j0 >> 7;
    const int j = j0 & 127;
    float* outp = half ? g_P2 : g_P1;
    const float bb0 = half ? 0.f : b1[j];
    const float bb1 = half ? 0.f : b1[j + 1];
#pragma unroll
    for (int p = 0; p < 4; p++) {
        float2 a0 = unpack2(acc0[p]);
        float2 a1 = unpack2(acc1[p]);
        int n0g = n0 + nb + 2 * p;
        if (n0g < N_NODES) {
            float2 v = make_float2(a0.x + bb0, a1.x + bb1);
            *(float2*)&outp[n0g * H + j] = v;
        }
        if (n0g + 1 < N_NODES) {
            float2 v = make_float2(a0.y + bb0, a1.y + bb1);
            *(float2*)&outp[(n0g + 1) * H + j] = v;
        }
    }
}

// ---------------- fused edge kernel: split-precision tf32 mma ----------------
// Activations are exact (hi+lo tf32 pair, 2 MMAs); only weights carry tf32 rounding.
__global__ __launch_bounds__(1024, 1) void k_edge(
    const float* __restrict__ eattr,
    const float* __restrict__ w2, const float* __restrict__ b2,
    const float* __restrict__ cw1, const float* __restrict__ cb1,
    const float* __restrict__ cw2, const float* __restrict__ ew1) {
    extern __shared__ float sm[];
    float* w2F   = sm;                 // 16384 (B-fragment order, tf32)
    float* c1F   = w2F + 16384;        // 16384
    float* aX    = c1F + 16384;        // 8192  A-fragment hi (hid, then m)
    float* aY    = aX + 8192;          // 8192  A-fragment lo (hid, then m)
    float* b2_s  = aY + 8192;          // 128
    float* cb1_s = b2_s + 128;         // 128
    float* c2_s  = cb1_s + 128;        // 128
    float* wd2_s = c2_s + 128;         // 128
    float* wea_s = wd2_s + 128;        // 512
    float* d2_s  = wea_s + 512;        // 64
    float* rel_s = d2_s + 64;          // 192
    float* ea_s  = rel_s + 192;        // 256
    float* wsum_s = ea_s + 256;        // 64
    int* row_s = (int*)(wsum_s + 64);  // 64
    int* col_s = row_s + 64;           // 64

    const int t = threadIdx.x;
    // prepack weights into B-fragment order (tf32 rounded)
    for (int i = t; i < 16384; i += 1024) {
        int r = i & 1;
        int lanei = (i >> 1) & 31;
        int ks = (i >> 6) & 15;
        int nt = i >> 10;
        int k = ks * 8 + (lanei & 3) + r * 4;
        int n = nt * 8 + (lanei >> 2);
        w2F[i] = tf32f(w2[k * H + n]);
        c1F[i] = tf32f(cw1[k * H + n]);
    }
    if (t < 128) {
        b2_s[t] = b2[t]; cb1_s[t] = cb1[t]; c2_s[t] = cw2[t];
        wd2_s[t] = ew1[256 * H + t];
    }
    if (t >= 128 && t < 640) wea_s[t - 128] = ew1[257 * H + (t - 128)];
    __syncthreads();

    const int w = t >> 5;
    const int lane = t & 31;
    const int mt = w >> 3;         // 0..3
    const int nt0 = (w & 7) * 2;   // 0..14
    const int grp = lane >> 2;     // 0..7
    const int thr = lane & 3;      // 0..3
    const int ntiles = (N_EDGES + NE_TILE - 1) / NE_TILE;

    for (int tile = blockIdx.x; tile < ntiles; tile += gridDim.x) {
        const int e0 = tile * NE_TILE;
        if (t < NE_TILE) {
            wsum_s[t] = 0.f;
            int sidx = e0 + t;
            int r = -1, c = 0, pe = 0;
            if (sidx < N_EDGES) { r = g_srow[sidx]; c = g_scol[sidx]; pe = g_sperm[sidx]; }
            row_s[t] = r; col_s[t] = c;
            float4 a = make_float4(0.f, 0.f, 0.f, 0.f);
            if (r >= 0) a = *(const float4*)&eattr[pe * 4];
            int rr = r < 0 ? 0 : r;
            float rx = g_pos[rr * 3 + 0] - g_pos[c * 3 + 0];
            float ry = g_pos[rr * 3 + 1] - g_pos[c * 3 + 1];
            float rz = g_pos[rr * 3 + 2] - g_pos[c * 3 + 2];
            rel_s[t * 3 + 0] = rx; rel_s[t * 3 + 1] = ry; rel_s[t * 3 + 2] = rz;
            d2_s[t] = rx * rx + ry * ry + rz * rz;
            ea_s[t * 4 + 0] = a.x; ea_s[t * 4 + 1] = a.y;
            ea_s[t * 4 + 2] = a.z; ea_s[t * 4 + 3] = a.w;
        }
        __syncthreads();

        // Phase A: hidden -> (hi, lo) A-fragments
#pragma unroll
        for (int rep = 0; rep < 8; rep++) {
            int idx = t + rep * 1024;
            int e = idx >> 7, j = idx & 127;
            int r = row_s[e], c = col_s[e];
            int rr = r < 0 ? 0 : r;
            float v = g_P1[rr * H + j] + g_P2[c * H + j] + d2_s[e] * wd2_s[j];
#pragma unroll
            for (int a2 = 0; a2 < 4; a2++) v += ea_s[e * 4 + a2] * wea_s[a2 * H + j];
            float s = silu_f(v);
            float hi = tf32f(s);
            int fi = fragA_idx(e, j);
            aX[fi] = hi;
            aY[fi] = tf32f(s - hi);
        }
        __syncthreads();

        // Phase B: m = silu(hid @ W2 + b2) — 2 MMAs per k-step (exact activations)
        float mh[8], ml[8];
        {
            float c0[4], c1[4];
            {
                int jc0 = nt0 * 8 + 2 * thr;
                int jc1 = (nt0 + 1) * 8 + 2 * thr;
                c0[0] = b2_s[jc0]; c0[1] = b2_s[jc0 + 1]; c0[2] = c0[0]; c0[3] = c0[1];
                c1[0] = b2_s[jc1]; c1[1] = b2_s[jc1 + 1]; c1[2] = c1[0]; c1[3] = c1[1];
            }
#pragma unroll
            for (int ks = 0; ks < 16; ks++) {
                int aoff = (((mt * 16 + ks) << 5) + lane) << 2;
                uint4 ah = *(const uint4*)&aX[aoff];
                uint4 al = *(const uint4*)&aY[aoff];
                uint2 b0 = *(const uint2*)&w2F[((((nt0) * 16 + ks) << 5) + lane) << 1];
                uint2 b1 = *(const uint2*)&c1F[0];  // placeholder avoided below
                b1 = *(const uint2*)&w2F[((((nt0 + 1) * 16 + ks) << 5) + lane) << 1];
                mma_tf32(c0, ah, b0);
                mma_tf32(c0, al, b0);
                mma_tf32(c1, ah, b1);
                mma_tf32(c1, al, b1);
            }
#pragma unroll
            for (int q = 0; q < 4; q++) {
                float m0 = silu_f(c0[q]);
                float m1 = silu_f(c1[q]);
                mh[q] = tf32f(m0); ml[q] = tf32f(m0 - mh[q]);
                mh[4 + q] = tf32f(m1); ml[4 + q] = tf32f(m1 - mh[4 + q]);
            }
        }
        __syncthreads();   // all warps done reading aX/aY
        {
            int ee0 = mt * 16 + grp, ee1 = ee0 + 8;
            int j00 = nt0 * 8 + 2 * thr;
            int j10 = (nt0 + 1) * 8 + 2 * thr;
            int i00 = fragA_idx(ee0, j00), i01 = fragA_idx(ee0, j00 + 1);
            int i10 = fragA_idx(ee1, j00), i11 = fragA_idx(ee1, j00 + 1);
            int i20 = fragA_idx(ee0, j10), i21 = fragA_idx(ee0, j10 + 1);
            int i30 = fragA_idx(ee1, j10), i31 = fragA_idx(ee1, j10 + 1);
            aX[i00] = mh[0]; aY[i00] = ml[0];
            aX[i01] = mh[1]; aY[i01] = ml[1];
            aX[i10] = mh[2]; aY[i10] = ml[2];
            aX[i11] = mh[3]; aY[i11] = ml[3];
            aX[i20] = mh[4]; aY[i20] = ml[4];
            aX[i21] = mh[5]; aY[i21] = ml[5];
            aX[i30] = mh[6]; aY[i30] = ml[6];
            aX[i31] = mh[7]; aY[i31] = ml[7];
        }
        __syncthreads();

        // Phase C: w = silu(m@C1 + cb1) @ C2 — 2 MMAs per k-step
        {
            float c0[4], c1[4];
            int j00 = nt0 * 8 + 2 * thr;
            int j10 = (nt0 + 1) * 8 + 2 * thr;
            c0[0] = cb1_s[j00]; c0[1] = cb1_s[j00 + 1]; c0[2] = c0[0]; c0[3] = c0[1];
            c1[0] = cb1_s[j10]; c1[1] = cb1_s[j10 + 1]; c1[2] = c1[0]; c1[3] = c1[1];
#pragma unroll
            for (int ks = 0; ks < 16; ks++) {
                int aoff = (((mt * 16 + ks) << 5) + lane) << 2;
                uint4 ah = *(const uint4*)&aX[aoff];
                uint4 al = *(const uint4*)&aY[aoff];
                uint2 b0 = *(const uint2*)&c1F[((((nt0) * 16 + ks) << 5) + lane) << 1];
                uint2 b1 = *(const uint2*)&c1F[((((nt0 + 1) * 16 + ks) << 5) + lane) << 1];
                mma_tf32(c0, ah, b0);
                mma_tf32(c0, al, b0);
                mma_tf32(c1, ah, b1);
                mma_tf32(c1, al, b1);
            }
            float sl = silu_f(c0[0]) * c2_s[j00] + silu_f(c0[1]) * c2_s[j00 + 1]
                     + silu_f(c1[0]) * c2_s[j10] + silu_f(c1[1]) * c2_s[j10 + 1];
            float sh = silu_f(c0[2]) * c2_s[j00] + silu_f(c0[3]) * c2_s[j00 + 1]
                     + silu_f(c1[2]) * c2_s[j10] + silu_f(c1[3]) * c2_s[j10 + 1];
            sl += __shfl_xor_sync(0xffffffffu, sl, 1);
            sl += __shfl_xor_sync(0xffffffffu, sl, 2);
            sh += __shfl_xor_sync(0xffffffffu, sh, 1);
            sh += __shfl_xor_sync(0xffffffffu, sh, 2);
            if (thr == 0) {
                atomicAdd(&wsum_s[mt * 16 + grp], sl);
                atomicAdd(&wsum_s[mt * 16 + grp + 8], sh);
            }
        }
        __syncthreads();

        // Phase D: segment-scan scatter of m (= hi + lo) into agg; posdelta
        {
            const int j = t & 127;
            const int q = t >> 7;          // 0..7
            const int ebeg = q * 8;
            float acc = 0.f;
            int cur = row_s[ebeg];
#pragma unroll
            for (int i = 0; i < 8; i++) {
                int e = ebeg + i;
                int r = row_s[e];
                int fi = fragA_idx(e, j);
                float v = aX[fi] + aY[fi];
                if (r != cur) {
                    if (cur >= 0) atomicAdd(&g_agg[cur * H + j], acc);
                    acc = 0.f;
                    cur = r;
                }
                acc += v;
            }
            if (cur >= 0) atomicAdd(&g_agg[cur * H + j], acc);
        }
        if (t < 192) {
            int e = t / 3, k = t % 3;
            int r = row_s[e];
            if (r >= 0)
                atomicAdd(&g_posdelta[r * 3 + k], rel_s[e * 3 + k] * wsum_s[e]);
        }
        __syncthreads();
    }
}

// ---------------- pos update ----------------
__global__ void k_pos() {
    const int idx = blockIdx.x * blockDim.x + threadIdx.x;
    if (idx >= N_NODES * 3) return;
    const int i = idx / 3;
    float d = fmaxf(g_deg[i], 1.0f);
    g_pos[idx] += g_posdelta[idx] / d;
}

// ---------------- node stage 1 (FFMA2, 1024 thr) ----------------
__global__ __launch_bounds__(1024, 1) void k_node1(const float* __restrict__ w,
                                                   const float* __restrict__ b) {
    extern __shared__ float sm[];
    float* w_s = sm;              // [256][128]
    float* a_t = sm + 32768;      // [256][TP]
    const int t = threadIdx.x;
    const int n0 = blockIdx.x * 64;
    for (int i = t; i < 32768; i += 1024) w_s[i] = w[i];
    for (int i = t; i < 16384; i += 1024) {
        int n = i >> 8, k = i & 255;
        int gi = n0 + n;
        float v = 0.f;
        if (gi < N_NODES) v = (k < 128) ? g_h[gi * H + k] : g_agg[gi * H + (k - 128)];
        a_t[k * TP + n] = v;
    }
    __syncthreads();

    const int j0 = (t & 63) * 2;
    const int eh = t >> 6;
    const int nb = eh * 4;
    unsigned long long acc0[2], acc1[2];
#pragma unroll
    for (int p = 0; p < 2; p++) { acc0[p] = 0ull; acc1[p] = 0ull; }
#pragma unroll 4
    for (int k = 0; k < 256; k++) {
        float2 wp = *(const float2*)&w_s[k * H + j0];
        unsigned long long bd0 = dup2(wp.x), bd1 = dup2(wp.y);
        const float* ar = &a_t[k * TP + nb];
#pragma unroll
        for (int p = 0; p < 2; p++) {
            unsigned long long av = *(const unsigned long long*)&ar[2 * p];
            acc0[p] = fma2(av, bd0, acc0[p]);
            acc1[p] = fma2(av, bd1, acc1[p]);
        }
    }
    float b0 = b[j0], b1v = b[j0 + 1];
#pragma unroll
    for (int p = 0; p < 2; p++) {
        float2 a0 = unpack2(acc0[p]);
        float2 a1 = unpack2(acc1[p]);
        int n0g = n0 + nb + 2 * p;
        if (n0g < N_NODES) {
            float2 u = make_float2(silu_f(a0.x + b0), silu_f(a1.x + b1v));
            *(float2*)&g_U[n0g * H + j0] = u;
        }
        if (n0g + 1 < N_NODES) {
            float2 u = make_float2(silu_f(a0.y + b0), silu_f(a1.y + b1v));
            *(float2*)&g_U[(n0g + 1) * H + j0] = u;
        }
    }
}

// ---------------- node stage 2 (FFMA2, 1024 thr) ----------------
__global__ __launch_bounds__(1024, 1) void k_node2(const float* __restrict__ w,
                                                   const float* __restrict__ b) {
    extern __shared__ float sm[];
    float* w_s = sm;              // [128][128]
    float* a_t = sm + 16384;      // [128][TP]
    const int t = threadIdx.x;
    const int n0 = blockIdx.x * 64;
    for (int i = t; i < 16384; i += 1024) w_s[i] = w[i];
    for (int i = t; i < 8192; i += 1024) {
        int n = i >> 7, k = i & 127;
        int gi = n0 + n;
        a_t[k * TP + n] = (gi < N_NODES) ? g_U[gi * H + k] : 0.f;
    }
    __syncthreads();

    const int j0 = (t & 63) * 2;
    const int eh = t >> 6;
    const int nb = eh * 4;
    unsigned long long acc0[2], acc1[2];
#pragma unroll
    for (int p = 0; p < 2; p++) { acc0[p] = 0ull; acc1[p] = 0ull; }
#pragma unroll 4
    for (int k = 0; k < 128; k++) {
        float2 wp = *(const float2*)&w_s[k * H + j0];
        unsigned long long bd0 = dup2(wp.x), bd1 = dup2(wp.y);
        const float* ar = &a_t[k * TP + nb];
#pragma unroll
        for (int p = 0; p < 2; p++) {
            unsigned long long av = *(const unsigned long long*)&ar[2 * p];
            acc0[p] = fma2(av, bd0, acc0[p]);
            acc1[p] = fma2(av, bd1, acc1[p]);
        }
    }
    float b0 = b[j0], b1v = b[j0 + 1];
#pragma unroll
    for (int p = 0; p < 2; p++) {
        float2 a0 = unpack2(acc0[p]);
        float2 a1 = unpack2(acc1[p]);
        int n0g = n0 + nb + 2 * p;
        if (n0g < N_NODES) {
            float2 hv = *(float2*)&g_h[n0g * H + j0];
            hv.x += a0.x + b0; hv.y += a1.x + b1v;
            *(float2*)&g_h[n0g * H + j0] = hv;
        }
        if (n0g + 1 < N_NODES) {
            float2 hv = *(float2*)&g_h[(n0g + 1) * H + j0];
            hv.x += a0.y + b0; hv.y += a1.y + b1v;
            *(float2*)&g_h[(n0g + 1) * H + j0] = hv;
        }
    }
}

// ---------------- pooling ----------------
__global__ __launch_bounds__(512) void k_pool() {
    __shared__ float red[512];
    const int g = blockIdx.x, t = threadIdx.x;
    const int j = t & 127, w = t >> 7;
    float s = 0.f;
    for (int n = w; n < NPG; n += 4) s += g_h[(g * NPG + n) * H + j];
    red[t] = s;
    __syncthreads();
    if (w == 0) {
        float tot = red[j] + red[128 + j] + red[256 + j] + red[384 + j];
        g_gfeat[g * 256 + j] = tot;
        g_gfeat[g * 256 + 128 + j] = tot * (1.f / (float)NPG);
    }
}

// ---------------- readout head ----------------
__global__ void k_head(const float* __restrict__ h1_w, const float* __restrict__ h1_b,
                       const float* __restrict__ h2_w, const float* __restrict__ h2_b,
                       const float* __restrict__ h3_w, const float* __restrict__ h3_b,
                       float* __restrict__ out) {
    __shared__ float gf[256], z1[128], z2[64];
    const int g = blockIdx.x, t = threadIdx.x;
    gf[t] = g_gfeat[g * 256 + t];
    gf[128 + t] = g_gfeat[g * 256 + 128 + t];
    __syncthreads();
    float a = h1_b[t];
    for (int k = 0; k < 256; k++) a += gf[k] * h1_w[k * 128 + t];
    z1[t] = fmaxf(a, 0.f);
    __syncthreads();
    if (t < 64) {
        float a2 = h2_b[t];
        for (int k = 0; k < 128; k++) a2 += z1[k] * h2_w[k * 64 + t];
        z2[t] = fmaxf(a2, 0.f);
    }
    __syncthreads();
    if (t == 0) {
        float a3 = h3_b[0];
        for (int k = 0; k < 64; k++) a3 += z2[k] * h3_w[k];
        out[g] = a3;
    }
}

// ---------------- launch ----------------
extern "C" void kernel_launch(void* const* d_in, const int* in_sizes, int n_in,
                              void* d_out, int out_size) {
    const float* x     = (const float*)d_in[0];
    const float* pos   = (const float*)d_in[1];
    const int*   ei    = (const int*)d_in[2];
    const float* eattr = (const float*)d_in[3];
    const float* Wp    = (const float*)d_in[6];
    const float* bp    = (const float*)d_in[7];
    const float* Wl    = (const float*)d_in[8];
    const float* bl    = (const float*)d_in[9];
    const float* gamma = (const float*)d_in[10];
    const float* beta  = (const float*)d_in[11];
    const float* e_w1  = (const float*)d_in[12];
    const float* e_b1  = (const float*)d_in[13];
    const float* e_w2  = (const float*)d_in[14];
    const float* e_b2  = (const float*)d_in[15];
    const float* c_w1  = (const float*)d_in[16];
    const float* c_b1  = (const float*)d_in[17];
    const float* c_w2  = (const float*)d_in[18];
    const float* n_w1  = (const float*)d_in[19];
    const float* n_b1  = (const float*)d_in[20];
    const float* n_w2  = (const float*)d_in[21];
    const float* n_b2  = (const float*)d_in[22];
    const float* h1_w  = (const float*)d_in[23];
    const float* h1_b  = (const float*)d_in[24];
    const float* h2_w  = (const float*)d_in[25];
    const float* h2_b  = (const float*)d_in[26];
    const float* h3_w  = (const float*)d_in[27];
    const float* h3_b  = (const float*)d_in[28];
    float* out = (float*)d_out;

    const int PROJ_SMEM = (32768 + 128 * TP) * 4;
    const int EDGE_SMEM = (16384 + 16384 + 8192 + 8192
                           + 128 * 4 + 512 + 64 + 192 + 256 + 64 + 64 + 64) * 4;
    const int N1_SMEM = (32768 + 256 * TP) * 4;
    const int N2_SMEM = (16384 + 128 * TP) * 4;
    cudaFuncSetAttribute(k_proj,  cudaFuncAttributeMaxDynamicSharedMemorySize, PROJ_SMEM);
    cudaFuncSetAttribute(k_edge,  cudaFuncAttributeMaxDynamicSharedMemorySize, EDGE_SMEM);
    cudaFuncSetAttribute(k_node1, cudaFuncAttributeMaxDynamicSharedMemorySize, N1_SMEM);
    cudaFuncSetAttribute(k_node2, cudaFuncAttributeMaxDynamicSharedMemorySize, N2_SMEM);

    const int nblocks64 = (N_NODES + 63) / 64;   // 782

    k_embed<<<N_NODES, 128>>>(x, pos, Wp, bp, Wl, bl);
    k_stats_deg<<<256 + DEG_BLOCKS, 512>>>(ei);
    k_bnapply_scan<<<BNA_BLOCKS + 1, 512>>>(gamma, beta);

    for (int l = 0; l < NLAYERS; l++) {
        k_proj<<<nblocks64, 1024, PROJ_SMEM>>>(e_w1 + l * 261 * H, e_b1 + l * H);
        if (l == 0) k_perm<<<(N_EDGES + 511) / 512, 512>>>(ei);
        k_edge<<<148, 1024, EDGE_SMEM>>>(eattr,
                                         e_w2 + l * H * H, e_b2 + l * H,
                                         c_w1 + l * H * H, c_b1 + l * H,
                                         c_w2 + l * H, e_w1 + l * 261 * H);
        k_node1<<<nblocks64, 1024, N1_SMEM>>>(n_w1 + l * 256 * H, n_b1 + l * H);
        k_node2<<<nblocks64, 1024, N2_SMEM>>>(n_w2 + l * H * H, n_b2 + l * H);
        k_pos<<<(N_NODES * 3 + 511) / 512, 512>>>();
    }

    k_pool<<<G_GRAPHS, 512>>>();
    k_head<<<G_GRAPHS, 128>>>(h1_w, h1_b, h2_w, h2_b, h3_w, h3_b, out);
}

// round 8
// speedup vs baseline: 1.2456x; 1.2456x over previous
#include <cuda_runtime.h>
#include <cuda_bf16.h>

#define N_NODES 50000
#define N_EDGES 500000
#define H 128
#define G_GRAPHS 100
#define NPG 500
#define NPROT 400
#define PN 35
#define LN 11
#define NLAYERS 4
#define EPS 1e-5f
#define NE_TILE 64

// ---------------- scratch ----------------
__device__ float g_h[N_NODES * H];
__device__ float g_P1[N_NODES * H];
__device__ float g_P2[N_NODES * H];
__device__ float g_agg[N_NODES * H];
__device__ float g_U[N_NODES * H];
__device__ float g_pos[N_NODES * 3];
__device__ float g_posdelta[N_NODES * 3];
__device__ float g_deg[N_NODES];
__device__ float g_bnstats[2 * H];
__device__ float g_gfeat[G_GRAPHS * 2 * H];
__device__ int g_rowcur[N_NODES];
__device__ int g_srow[N_EDGES];
__device__ int g_scol[N_EDGES];
__device__ int g_sperm[N_EDGES];

__device__ __forceinline__ float silu_f(float x) {
    return x / (1.f + __expf(-x));
}

// ---- tf32 mma helpers ----
__device__ __forceinline__ float tf32f(float f) {
    unsigned int u;
    asm("cvt.rna.tf32.f32 %0, %1;" : "=r"(u) : "f"(f));
    return __uint_as_float(u);
}
__device__ __forceinline__ void mma_tf32(float* c, const uint4& a, const uint2& b) {
    asm volatile(
        "mma.sync.aligned.m16n8k8.row.col.f32.tf32.tf32.f32 "
        "{%0,%1,%2,%3}, {%4,%5,%6,%7}, {%8,%9}, {%0,%1,%2,%3};"
        : "+f"(c[0]), "+f"(c[1]), "+f"(c[2]), "+f"(c[3])
        : "r"(a.x), "r"(a.y), "r"(a.z), "r"(a.w), "r"(b.x), "r"(b.y));
}
// weight packed as (bf16 hi << 16) | bf16 lo, hi+lo ≈ w to ~2^-16
__device__ __forceinline__ unsigned pack_w(float w) {
    __nv_bfloat16 h = __float2bfloat16(w);
    float hf = __bfloat162float(h);
    __nv_bfloat16 l = __float2bfloat16(w - hf);
    return ((unsigned)__bfloat16_as_ushort(h) << 16) | (unsigned)__bfloat16_as_ushort(l);
}
// 2-MMA: split weight, single-tf32 act
__device__ __forceinline__ void mma_split(float* c, const uint4& a, const uint2& p) {
    uint2 bh = make_uint2(p.x & 0xFFFF0000u, p.y & 0xFFFF0000u);
    uint2 bl = make_uint2(p.x << 16, p.y << 16);
    mma_tf32(c, a, bh);
    mma_tf32(c, a, bl);
}
// 3-MMA: split weight AND split act (drop lo*lo term)
__device__ __forceinline__ void mma_split3(float* c, const uint4& ah, const uint4& al,
                                           const uint2& p) {
    uint2 bh = make_uint2(p.x & 0xFFFF0000u, p.y & 0xFFFF0000u);
    uint2 bl = make_uint2(p.x << 16, p.y << 16);
    mma_tf32(c, ah, bh);
    mma_tf32(c, ah, bl);
    mma_tf32(c, al, bh);
}
// A-fragment flat index (16 k-tiles per m-tile row)
__device__ __forceinline__ int fragA16(int e, int k) {
    int lane = ((e & 7) << 2) | (k & 3);
    int reg = ((e >> 3) & 1) | (((k >> 2) & 1) << 1);
    return (((e >> 4) * 16 + (k >> 3)) << 7) + (lane << 2) + reg;
}

// ---------------- K1: embed ----------------
__global__ void k_embed(const float* __restrict__ x, const float* __restrict__ pos_in,
                        const float* __restrict__ Wp, const float* __restrict__ bp,
                        const float* __restrict__ Wl, const float* __restrict__ bl) {
    __shared__ float xs[PN];
    const int i = blockIdx.x;
    const int t = threadIdx.x;
    if (t < PN) xs[t] = x[i * PN + t];
    if (t == 0) g_deg[i] = 0.f;
    if (t < 3) g_pos[i * 3 + t] = pos_in[i * 3 + t];
    if (i == 0 && t < H) { g_bnstats[t] = 0.f; g_bnstats[H + t] = 0.f; }
    __syncthreads();
    const bool isp = (i % NPG) < NPROT;
    const float* W = isp ? Wp : Wl;
    const float* b = isp ? bp : bl;
    const int nk = isp ? PN : LN;
    float acc = b[t];
    for (int k = 0; k < nk; k++) acc += xs[k] * W[k * H + t];
    g_h[i * H + t] = acc;
}

// ---------------- K2: bnstats + degree ----------------
#define DEG_BLOCKS ((N_EDGES + 511) / 512)
__global__ __launch_bounds__(512) void k_stats_deg(const int* __restrict__ ei) {
    const int t = threadIdx.x;
    if (blockIdx.x < 256) {
        const int j = t & 127;
        const int g2 = t >> 7;
        float s = 0.f, s2 = 0.f;
        for (int i = blockIdx.x * 4 + g2; i < N_NODES; i += 1024) {
            float v = g_h[i * H + j];
            s += v; s2 += v * v;
        }
        atomicAdd(&g_bnstats[j], s);
        atomicAdd(&g_bnstats[H + j], s2);
    } else {
        const int e = (blockIdx.x - 256) * 512 + t;
        if (e < N_EDGES) atomicAdd(&g_deg[ei[e]], 1.0f);
    }
}

// ---------------- K3: bnapply + degree scan ----------------
#define BNA_BLOCKS ((N_NODES * H) / 512)
__global__ __launch_bounds__(512) void k_bnapply_scan(const float* __restrict__ gamma,
                                                      const float* __restrict__ beta) {
    const int t = threadIdx.x;
    if (blockIdx.x < BNA_BLOCKS) {
        const int idx = blockIdx.x * 512 + t;
        const int j = idx & (H - 1);
        const float inv_n = 1.f / (float)N_NODES;
        float mu = g_bnstats[j] * inv_n;
        float var = g_bnstats[H + j] * inv_n - mu * mu;
        g_h[idx] = (g_h[idx] - mu) * rsqrtf(var + EPS) * gamma[j] + beta[j];
    } else {
        __shared__ int sums[512];
        const int chunk = 98;
        int base = t * chunk;
        int lim = min(base + chunk, N_NODES);
        int s = 0;
        for (int i = base; i < lim; i++) s += (int)g_deg[i];
        sums[t] = s;
        __syncthreads();
        for (int off = 1; off < 512; off <<= 1) {
            int v = (t >= off) ? sums[t - off] : 0;
            __syncthreads();
            sums[t] += v;
            __syncthreads();
        }
        int run = (t == 0) ? 0 : sums[t - 1];
        for (int i = base; i < lim; i++) {
            g_rowcur[i] = run;
            run += (int)g_deg[i];
        }
    }
}

// ---------------- counting-sort scatter ----------------
__global__ __launch_bounds__(512) void k_perm(const int* __restrict__ ei) {
    const int e = blockIdx.x * 512 + threadIdx.x;
    if (e >= N_EDGES) return;
    int r = ei[e];
    int p = atomicAdd(&g_rowcur[r], 1);
    g_srow[p] = r;
    g_scol[p] = ei[N_EDGES + e];
    g_sperm[p] = e;
}

// ---------------- proj: P1 = h@W1a + b1, P2 = h@W1b  (3-MMA split-split) ----------------
__global__ __launch_bounds__(1024, 1) void k_proj(const float* __restrict__ w,
                                                  const float* __restrict__ b1) {
    extern __shared__ float sm[];
    unsigned* wF = (unsigned*)sm;   // 32768 packed
    float* aH = sm + 32768;         // 8192 A-fragments hi
    float* aL = aH + 8192;          // 8192 A-fragments lo
    const int t = threadIdx.x;
    const int n0 = blockIdx.x * 64;

    for (int i = t; i < 32768; i += 1024) {
        int r = i & 1, lane = (i >> 1) & 31, ks = (i >> 6) & 15, nt = i >> 10;
        int k = ks * 8 + (lane & 3) + r * 4;
        int jj = nt * 8 + (lane >> 2);
        int srcrow = (jj < 128) ? k : (128 + k);
        wF[i] = pack_w(w[srcrow * H + (jj & 127)]);
    }
    for (int i = t; i < 8192; i += 1024) {
        int n = i >> 7, k = i & 127;
        int gi = n0 + n;
        float v = (gi < N_NODES) ? g_h[gi * H + k] : 0.f;
        float hi = tf32f(v);
        int fi = fragA16(n, k);
        aH[fi] = hi;
        aL[fi] = tf32f(v - hi);
    }
    for (int i = t; i < 8192; i += 1024) {
        int gi = n0 + (i >> 7);
        if (gi < N_NODES) g_agg[gi * H + (i & 127)] = 0.f;
    }
    if (t < 192) {
        int gi = n0 + t / 3;
        if (gi < N_NODES) g_posdelta[gi * 3 + t % 3] = 0.f;
    }
    __syncthreads();

    const int wid = t >> 5, lane = t & 31;
    const int mt = wid >> 3;       // 0..3
    const int ng = wid & 7;        // 0..7, 4 n-tiles each
    const int grp = lane >> 2, thr = lane & 3;
    float c[4][4];
#pragma unroll
    for (int q = 0; q < 4; q++)
#pragma unroll
        for (int r = 0; r < 4; r++) c[q][r] = 0.f;

#pragma unroll
    for (int ks = 0; ks < 16; ks++) {
        int aoff = (((mt * 16 + ks) << 5) + lane) << 2;
        uint4 ah = *(const uint4*)&aH[aoff];
        uint4 al = *(const uint4*)&aL[aoff];
#pragma unroll
        for (int q = 0; q < 4; q++) {
            int nt = ng * 4 + q;
            uint2 p = *(const uint2*)&wF[(((nt * 16 + ks) << 5) + lane) << 1];
            mma_split3(c[q], ah, al, p);
        }
    }

    const int ee0 = mt * 16 + grp, ee1 = ee0 + 8;
    const int g0 = n0 + ee0, g1 = n0 + ee1;
#pragma unroll
    for (int q = 0; q < 4; q++) {
        int nt = ng * 4 + q;
        int jj0 = nt * 8 + 2 * thr;
        int half = jj0 >> 7;
        int j = jj0 & 127;
        float* outp = half ? g_P2 : g_P1;
        float bb0 = half ? 0.f : __ldg(&b1[j]);
        float bb1 = half ? 0.f : __ldg(&b1[j + 1]);
        if (g0 < N_NODES)
            *(float2*)&outp[g0 * H + j] = make_float2(c[q][0] + bb0, c[q][1] + bb1);
        if (g1 < N_NODES)
            *(float2*)&outp[g1 * H + j] = make_float2(c[q][2] + bb0, c[q][3] + bb1);
    }
}

// ---------------- fused edge kernel: split-weight tf32 mma (2-MMA) ----------------
__global__ __launch_bounds__(1024, 1) void k_edge(
    const float* __restrict__ eattr,
    const float* __restrict__ w2, const float* __restrict__ b2,
    const float* __restrict__ cw1, const float* __restrict__ cb1,
    const float* __restrict__ cw2, const float* __restrict__ ew1) {
    extern __shared__ float sm[];
    unsigned* w2F = (unsigned*)sm;      // 16384 packed
    unsigned* c1F = w2F + 16384;        // 16384 packed
    float* hidF  = (float*)(c1F + 16384);  // 8192 A-fragments
    float* mF    = hidF + 8192;         // 8192
    float* b2_s  = mF + 8192;           // 128
    float* cb1_s = b2_s + 128;          // 128
    float* c2_s  = cb1_s + 128;         // 128
    float* wd2_s = c2_s + 128;          // 128
    float* wea_s = wd2_s + 128;         // 512
    float* d2_s  = wea_s + 512;         // 64
    float* rel_s = d2_s + 64;           // 192
    float* ea_s  = rel_s + 192;         // 256
    float* wsum_s = ea_s + 256;         // 64
    int* row_s = (int*)(wsum_s + 64);   // 64
    int* col_s = row_s + 64;            // 64

    const int t = threadIdx.x;
    for (int i = t; i < 16384; i += 1024) {
        int r = i & 1, lanei = (i >> 1) & 31, ks = (i >> 6) & 15, nt = i >> 10;
        int k = ks * 8 + (lanei & 3) + r * 4;
        int n = nt * 8 + (lanei >> 2);
        w2F[i] = pack_w(w2[k * H + n]);
        c1F[i] = pack_w(cw1[k * H + n]);
    }
    if (t < 128) {
        b2_s[t] = b2[t]; cb1_s[t] = cb1[t]; c2_s[t] = cw2[t];
        wd2_s[t] = ew1[256 * H + t];
    }
    if (t >= 128 && t < 640) wea_s[t - 128] = ew1[257 * H + (t - 128)];
    __syncthreads();

    const int w = t >> 5;
    const int lane = t & 31;
    const int mt = w >> 3;         // 0..3
    const int nt0 = (w & 7) * 2;   // 0..14
    const int grp = lane >> 2;     // 0..7
    const int thr = lane & 3;      // 0..3
    const int ntiles = (N_EDGES + NE_TILE - 1) / NE_TILE;

    for (int tile = blockIdx.x; tile < ntiles; tile += gridDim.x) {
        const int e0 = tile * NE_TILE;
        if (t < NE_TILE) {
            wsum_s[t] = 0.f;
            int sidx = e0 + t;
            int r = -1, c = 0, pe = 0;
            if (sidx < N_EDGES) { r = g_srow[sidx]; c = g_scol[sidx]; pe = g_sperm[sidx]; }
            row_s[t] = r; col_s[t] = c;
            float4 a = make_float4(0.f, 0.f, 0.f, 0.f);
            if (r >= 0) a = *(const float4*)&eattr[pe * 4];
            int rr = r < 0 ? 0 : r;
            float rx = g_pos[rr * 3 + 0] - g_pos[c * 3 + 0];
            float ry = g_pos[rr * 3 + 1] - g_pos[c * 3 + 1];
            float rz = g_pos[rr * 3 + 2] - g_pos[c * 3 + 2];
            rel_s[t * 3 + 0] = rx; rel_s[t * 3 + 1] = ry; rel_s[t * 3 + 2] = rz;
            d2_s[t] = rx * rx + ry * ry + rz * rz;
            ea_s[t * 4 + 0] = a.x; ea_s[t * 4 + 1] = a.y;
            ea_s[t * 4 + 2] = a.z; ea_s[t * 4 + 3] = a.w;
        }
        __syncthreads();

        // Phase A: hidden -> A-fragments (single tf32)
#pragma unroll
        for (int rep = 0; rep < 8; rep++) {
            int idx = t + rep * 1024;
            int e = idx >> 7, j = idx & 127;
            int r = row_s[e], c = col_s[e];
            int rr = r < 0 ? 0 : r;
            float v = g_P1[rr * H + j] + g_P2[c * H + j] + d2_s[e] * wd2_s[j];
#pragma unroll
            for (int a2 = 0; a2 < 4; a2++) v += ea_s[e * 4 + a2] * wea_s[a2 * H + j];
            hidF[fragA16(e, j)] = tf32f(silu_f(v));
        }
        __syncthreads();

        // Phase B: m = silu(hid @ W2 + b2)
        {
            float c0[4], c1[4];
            {
                int jc0 = nt0 * 8 + 2 * thr;
                int jc1 = (nt0 + 1) * 8 + 2 * thr;
                c0[0] = b2_s[jc0]; c0[1] = b2_s[jc0 + 1]; c0[2] = c0[0]; c0[3] = c0[1];
                c1[0] = b2_s[jc1]; c1[1] = b2_s[jc1 + 1]; c1[2] = c1[0]; c1[3] = c1[1];
            }
#pragma unroll
            for (int ks = 0; ks < 16; ks++) {
                uint4 a = *(const uint4*)&hidF[(((mt * 16 + ks) << 5) + lane) << 2];
                uint2 p0 = *(const uint2*)&w2F[(((nt0 * 16 + ks) << 5) + lane) << 1];
                uint2 p1 = *(const uint2*)&w2F[((((nt0 + 1) * 16 + ks) << 5) + lane) << 1];
                mma_split(c0, a, p0);
                mma_split(c1, a, p1);
            }
            int ee0 = mt * 16 + grp, ee1 = ee0 + 8;
            int j00 = nt0 * 8 + 2 * thr;
            int j10 = (nt0 + 1) * 8 + 2 * thr;
            mF[fragA16(ee0, j00)]     = tf32f(silu_f(c0[0]));
            mF[fragA16(ee0, j00 + 1)] = tf32f(silu_f(c0[1]));
            mF[fragA16(ee1, j00)]     = tf32f(silu_f(c0[2]));
            mF[fragA16(ee1, j00 + 1)] = tf32f(silu_f(c0[3]));
            mF[fragA16(ee0, j10)]     = tf32f(silu_f(c1[0]));
            mF[fragA16(ee0, j10 + 1)] = tf32f(silu_f(c1[1]));
            mF[fragA16(ee1, j10)]     = tf32f(silu_f(c1[2]));
            mF[fragA16(ee1, j10 + 1)] = tf32f(silu_f(c1[3]));
        }
        __syncthreads();

        // Phase C: w = silu(m@C1 + cb1) @ C2
        {
            float c0[4], c1[4];
            int j00 = nt0 * 8 + 2 * thr;
            int j10 = (nt0 + 1) * 8 + 2 * thr;
            c0[0] = cb1_s[j00]; c0[1] = cb1_s[j00 + 1]; c0[2] = c0[0]; c0[3] = c0[1];
            c1[0] = cb1_s[j10]; c1[1] = cb1_s[j10 + 1]; c1[2] = c1[0]; c1[3] = c1[1];
#pragma unroll
            for (int ks = 0; ks < 16; ks++) {
                uint4 a = *(const uint4*)&mF[(((mt * 16 + ks) << 5) + lane) << 2];
                uint2 p0 = *(const uint2*)&c1F[(((nt0 * 16 + ks) << 5) + lane) << 1];
                uint2 p1 = *(const uint2*)&c1F[((((nt0 + 1) * 16 + ks) << 5) + lane) << 1];
                mma_split(c0, a, p0);
                mma_split(c1, a, p1);
            }
            float sl = silu_f(c0[0]) * c2_s[j00] + silu_f(c0[1]) * c2_s[j00 + 1]
                     + silu_f(c1[0]) * c2_s[j10] + silu_f(c1[1]) * c2_s[j10 + 1];
            float sh = silu_f(c0[2]) * c2_s[j00] + silu_f(c0[3]) * c2_s[j00 + 1]
                     + silu_f(c1[2]) * c2_s[j10] + silu_f(c1[3]) * c2_s[j10 + 1];
            sl += __shfl_xor_sync(0xffffffffu, sl, 1);
            sl += __shfl_xor_sync(0xffffffffu, sl, 2);
            sh += __shfl_xor_sync(0xffffffffu, sh, 1);
            sh += __shfl_xor_sync(0xffffffffu, sh, 2);
            if (thr == 0) {
                atomicAdd(&wsum_s[mt * 16 + grp], sl);
                atomicAdd(&wsum_s[mt * 16 + grp + 8], sh);
            }
        }
        __syncthreads();

        // Phase D: segment-scan scatter
        {
            const int j = t & 127;
            const int q = t >> 7;          // 0..7
            const int ebeg = q * 8;
            float acc = 0.f;
            int cur = row_s[ebeg];
#pragma unroll
            for (int i = 0; i < 8; i++) {
                int e = ebeg + i;
                int r = row_s[e];
                float v = mF[fragA16(e, j)];
                if (r != cur) {
                    if (cur >= 0) atomicAdd(&g_agg[cur * H + j], acc);
                    acc = 0.f;
                    cur = r;
                }
                acc += v;
            }
            if (cur >= 0) atomicAdd(&g_agg[cur * H + j], acc);
        }
        if (t < 192) {
            int e = t / 3, k = t % 3;
            int r = row_s[e];
            if (r >= 0)
                atomicAdd(&g_posdelta[r * 3 + k], rel_s[e * 3 + k] * wsum_s[e]);
        }
        __syncthreads();
    }
}

// ---------------- pos update ----------------
__global__ void k_pos() {
    const int idx = blockIdx.x * blockDim.x + threadIdx.x;
    if (idx >= N_NODES * 3) return;
    const int i = idx / 3;
    float d = fmaxf(g_deg[i], 1.0f);
    g_pos[idx] += g_posdelta[idx] / d;
}

// ---------------- node1: U = silu([h|agg] @ n_w1 + b1)  (3-MMA, two K-half passes) ------
__global__ __launch_bounds__(1024, 1) void k_node1(const float* __restrict__ w,
                                                   const float* __restrict__ b) {
    extern __shared__ float sm[];
    unsigned* wF = (unsigned*)sm;   // 16384 packed (one K-half)
    float* aH = sm + 16384;         // 8192
    float* aL = aH + 8192;          // 8192
    const int t = threadIdx.x;
    const int n0 = blockIdx.x * 64;
    const int wid = t >> 5, lane = t & 31;
    const int mt = wid >> 3, nt0 = (wid & 7) * 2;
    const int grp = lane >> 2, thr = lane & 3;
    float c0[4] = {0.f, 0.f, 0.f, 0.f}, c1[4] = {0.f, 0.f, 0.f, 0.f};

    for (int halfk = 0; halfk < 2; halfk++) {
        __syncthreads();
        for (int i = t; i < 16384; i += 1024) {
            int r = i & 1, lane2 = (i >> 1) & 31, ks = (i >> 6) & 15, nt = i >> 10;
            int k = halfk * 128 + ks * 8 + (lane2 & 3) + r * 4;
            int n = nt * 8 + (lane2 >> 2);
            wF[i] = pack_w(w[k * H + n]);
        }
        const float* src = halfk ? g_agg : g_h;
        for (int i = t; i < 8192; i += 1024) {
            int n = i >> 7, kk = i & 127;
            int gi = n0 + n;
            float v = (gi < N_NODES) ? src[gi * H + kk] : 0.f;
            float hi = tf32f(v);
            int fi = fragA16(n, kk);
            aH[fi] = hi;
            aL[fi] = tf32f(v - hi);
        }
        __syncthreads();
#pragma unroll
        for (int ks = 0; ks < 16; ks++) {
            int aoff = (((mt * 16 + ks) << 5) + lane) << 2;
            uint4 ah = *(const uint4*)&aH[aoff];
            uint4 al = *(const uint4*)&aL[aoff];
            uint2 p0 = *(const uint2*)&wF[(((nt0 * 16 + ks) << 5) + lane) << 1];
            uint2 p1 = *(const uint2*)&wF[((((nt0 + 1) * 16 + ks) << 5) + lane) << 1];
            mma_split3(c0, ah, al, p0);
            mma_split3(c1, ah, al, p1);
        }
    }
    const int ee0 = mt * 16 + grp, ee1 = ee0 + 8;
    const int g0 = n0 + ee0, g1 = n0 + ee1;
    const int j00 = nt0 * 8 + 2 * thr, j10 = (nt0 + 1) * 8 + 2 * thr;
    float b00 = __ldg(&b[j00]), b01 = __ldg(&b[j00 + 1]);
    float b10 = __ldg(&b[j10]), b11 = __ldg(&b[j10 + 1]);
    if (g0 < N_NODES) {
        *(float2*)&g_U[g0 * H + j00] = make_float2(silu_f(c0[0] + b00), silu_f(c0[1] + b01));
        *(float2*)&g_U[g0 * H + j10] = make_float2(silu_f(c1[0] + b10), silu_f(c1[1] + b11));
    }
    if (g1 < N_NODES) {
        *(float2*)&g_U[g1 * H + j00] = make_float2(silu_f(c0[2] + b00), silu_f(c0[3] + b01));
        *(float2*)&g_U[g1 * H + j10] = make_float2(silu_f(c1[2] + b10), silu_f(c1[3] + b11));
    }
}

// ---------------- node2: h += U @ n_w2 + b2  (3-MMA split-split) ----------------
__global__ __launch_bounds__(1024, 1) void k_node2(const float* __restrict__ w,
                                                   const float* __restrict__ b) {
    extern __shared__ float sm[];
    unsigned* wF = (unsigned*)sm;   // 16384 packed
    float* aH = sm + 16384;         // 8192
    float* aL = aH + 8192;          // 8192
    const int t = threadIdx.x;
    const int n0 = blockIdx.x * 64;
    for (int i = t; i < 16384; i += 1024) {
        int r = i & 1, lane = (i >> 1) & 31, ks = (i >> 6) & 15, nt = i >> 10;
        int k = ks * 8 + (lane & 3) + r * 4;
        int n = nt * 8 + (lane >> 2);
        wF[i] = pack_w(w[k * H + n]);
    }
    for (int i = t; i < 8192; i += 1024) {
        int n = i >> 7, k = i & 127;
        int gi = n0 + n;
        float v = (gi < N_NODES) ? g_U[gi * H + k] : 0.f;
        float hi = tf32f(v);
        int fi = fragA16(n, k);
        aH[fi] = hi;
        aL[fi] = tf32f(v - hi);
    }
    __syncthreads();

    const int wid = t >> 5, lane = t & 31;
    const int mt = wid >> 3, nt0 = (wid & 7) * 2;
    const int grp = lane >> 2, thr = lane & 3;
    float c0[4] = {0.f, 0.f, 0.f, 0.f}, c1[4] = {0.f, 0.f, 0.f, 0.f};
#pragma unroll
    for (int ks = 0; ks < 16; ks++) {
        int aoff = (((mt * 16 + ks) << 5) + lane) << 2;
        uint4 ah = *(const uint4*)&aH[aoff];
        uint4 al = *(const uint4*)&aL[aoff];
        uint2 p0 = *(const uint2*)&wF[(((nt0 * 16 + ks) << 5) + lane) << 1];
        uint2 p1 = *(const uint2*)&wF[((((nt0 + 1) * 16 + ks) << 5) + lane) << 1];
        mma_split3(c0, ah, al, p0);
        mma_split3(c1, ah, al, p1);
    }
    const int ee0 = mt * 16 + grp, ee1 = ee0 + 8;
    const int g0 = n0 + ee0, g1 = n0 + ee1;
    const int j00 = nt0 * 8 + 2 * thr, j10 = (nt0 + 1) * 8 + 2 * thr;
    float b00 = __ldg(&b[j00]), b01 = __ldg(&b[j00 + 1]);
    float b10 = __ldg(&b[j10]), b11 = __ldg(&b[j10 + 1]);
    if (g0 < N_NODES) {
        float2 h0 = *(float2*)&g_h[g0 * H + j00];
        h0.x += c0[0] + b00; h0.y += c0[1] + b01;
        *(float2*)&g_h[g0 * H + j00] = h0;
        float2 h1 = *(float2*)&g_h[g0 * H + j10];
        h1.x += c1[0] + b10; h1.y += c1[1] + b11;
        *(float2*)&g_h[g0 * H + j10] = h1;
    }
    if (g1 < N_NODES) {
        float2 h0 = *(float2*)&g_h[g1 * H + j00];
        h0.x += c0[2] + b00; h0.y += c0[3] + b01;
        *(float2*)&g_h[g1 * H + j00] = h0;
        float2 h1 = *(float2*)&g_h[g1 * H + j10];
        h1.x += c1[2] + b10; h1.y += c1[3] + b11;
        *(float2*)&g_h[g1 * H + j10] = h1;
    }
}

// ---------------- pooling ----------------
__global__ __launch_bounds__(512) void k_pool() {
    __shared__ float red[512];
    const int g = blockIdx.x, t = threadIdx.x;
    const int j = t & 127, w = t >> 7;
    float s = 0.f;
    for (int n = w; n < NPG; n += 4) s += g_h[(g * NPG + n) * H + j];
    red[t] = s;
    __syncthreads();
    if (w == 0) {
        float tot = red[j] + red[128 + j] + red[256 + j] + red[384 + j];
        g_gfeat[g * 256 + j] = tot;
        g_gfeat[g * 256 + 128 + j] = tot * (1.f / (float)NPG);
    }
}

// ---------------- readout head ----------------
__global__ void k_head(const float* __restrict__ h1_w, const float* __restrict__ h1_b,
                       const float* __restrict__ h2_w, const float* __restrict__ h2_b,
                       const float* __restrict__ h3_w, const float* __restrict__ h3_b,
                       float* __restrict__ out) {
    __shared__ float gf[256], z1[128], z2[64];
    const int g = blockIdx.x, t = threadIdx.x;
    gf[t] = g_gfeat[g * 256 + t];
    gf[128 + t] = g_gfeat[g * 256 + 128 + t];
    __syncthreads();
    float a = h1_b[t];
    for (int k = 0; k < 256; k++) a += gf[k] * h1_w[k * 128 + t];
    z1[t] = fmaxf(a, 0.f);
    __syncthreads();
    if (t < 64) {
        float a2 = h2_b[t];
        for (int k = 0; k < 128; k++) a2 += z1[k] * h2_w[k * 64 + t];
        z2[t] = fmaxf(a2, 0.f);
    }
    __syncthreads();
    if (t == 0) {
        float a3 = h3_b[0];
        for (int k = 0; k < 64; k++) a3 += z2[k] * h3_w[k];
        out[g] = a3;
    }
}

// ---------------- launch ----------------
extern "C" void kernel_launch(void* const* d_in, const int* in_sizes, int n_in,
                              void* d_out, int out_size) {
    const float* x     = (const float*)d_in[0];
    const float* pos   = (const float*)d_in[1];
    const int*   ei    = (const int*)d_in[2];
    const float* eattr = (const float*)d_in[3];
    const float* Wp    = (const float*)d_in[6];
    const float* bp    = (const float*)d_in[7];
    const float* Wl    = (const float*)d_in[8];
    const float* bl    = (const float*)d_in[9];
    const float* gamma = (const float*)d_in[10];
    const float* beta  = (const float*)d_in[11];
    const float* e_w1  = (const float*)d_in[12];
    const float* e_b1  = (const float*)d_in[13];
    const float* e_w2  = (const float*)d_in[14];
    const float* e_b2  = (const float*)d_in[15];
    const float* c_w1  = (const float*)d_in[16];
    const float* c_b1  = (const float*)d_in[17];
    const float* c_w2  = (const float*)d_in[18];
    const float* n_w1  = (const float*)d_in[19];
    const float* n_b1  = (const float*)d_in[20];
    const float* n_w2  = (const float*)d_in[21];
    const float* n_b2  = (const float*)d_in[22];
    const float* h1_w  = (const float*)d_in[23];
    const float* h1_b  = (const float*)d_in[24];
    const float* h2_w  = (const float*)d_in[25];
    const float* h2_b  = (const float*)d_in[26];
    const float* h3_w  = (const float*)d_in[27];
    const float* h3_b  = (const float*)d_in[28];
    float* out = (float*)d_out;

    const int PROJ_SMEM = (32768 + 16384) * 4;
    const int EDGE_SMEM = (16384 * 2 + 8192 * 2 + 128 * 4 + 512
                           + 64 + 192 + 256 + 64 + 64 + 64) * 4;
    const int N1_SMEM = (16384 + 16384) * 4;
    const int N2_SMEM = (16384 + 16384) * 4;
    cudaFuncSetAttribute(k_proj,  cudaFuncAttributeMaxDynamicSharedMemorySize, PROJ_SMEM);
    cudaFuncSetAttribute(k_edge,  cudaFuncAttributeMaxDynamicSharedMemorySize, EDGE_SMEM);
    cudaFuncSetAttribute(k_node1, cudaFuncAttributeMaxDynamicSharedMemorySize, N1_SMEM);
    cudaFuncSetAttribute(k_node2, cudaFuncAttributeMaxDynamicSharedMemorySize, N2_SMEM);

    const int nblocks64 = (N_NODES + 63) / 64;   // 782

    k_embed<<<N_NODES, 128>>>(x, pos, Wp, bp, Wl, bl);
    k_stats_deg<<<256 + DEG_BLOCKS, 512>>>(ei);
    k_bnapply_scan<<<BNA_BLOCKS + 1, 512>>>(gamma, beta);

    for (int l = 0; l < NLAYERS; l++) {
        k_proj<<<nblocks64, 1024, PROJ_SMEM>>>(e_w1 + l * 261 * H, e_b1 + l * H);
        if (l == 0) k_perm<<<(N_EDGES + 511) / 512, 512>>>(ei);
        k_edge<<<148, 1024, EDGE_SMEM>>>(eattr,
                                         e_w2 + l * H * H, e_b2 + l * H,
                                         c_w1 + l * H * H, c_b1 + l * H,
                                         c_w2 + l * H, e_w1 + l * 261 * H);
        k_node1<<<nblocks64, 1024, N1_SMEM>>>(n_w1 + l * 256 * H, n_b1 + l * H);
        k_node2<<<nblocks64, 1024, N2_SMEM>>>(n_w2 + l * H * H, n_b2 + l * H);
        k_pos<<<(N_NODES * 3 + 511) / 512, 512>>>();
    }

    k_pool<<<G_GRAPHS, 512>>>();
    k_head<<<G_GRAPHS, 128>>>(h1_w, h1_b, h2_w, h2_b, h3_w, h3_b, out);
}

// round 9
// speedup vs baseline: 1.3477x; 1.0819x over previous
#include <cuda_runtime.h>
#include <cuda_bf16.h>

#define N_NODES 50000
#define N_EDGES 500000
#define H 128
#define G_GRAPHS 100
#define NPG 500
#define NPROT 400
#define PN 35
#define LN 11
#define NLAYERS 4
#define EPS 1e-5f
#define NE_TILE 128

// ---------------- scratch ----------------
__device__ float g_h[N_NODES * H];
__device__ float g_P1[N_NODES * H];
__device__ float g_P2[N_NODES * H];
__device__ float g_agg[N_NODES * H];
__device__ float g_U[N_NODES * H];
__device__ float g_pos[N_NODES * 3];
__device__ float g_posdelta[N_NODES * 3];
__device__ float g_deg[N_NODES];
__device__ float g_bnstats[2 * H];
__device__ float g_gfeat[G_GRAPHS * 2 * H];
__device__ int g_rowcur[N_NODES];
__device__ int g_srow[N_EDGES];
__device__ int g_scol[N_EDGES];
__device__ int g_sperm[N_EDGES];
// pre-packed weights (bf16 hi|lo fragments), filled by k_pack each launch
__device__ unsigned g_pk_proj[NLAYERS * 32768];
__device__ unsigned g_pk_w2[NLAYERS * 16384];
__device__ unsigned g_pk_c1[NLAYERS * 16384];
__device__ unsigned g_pk_n1[NLAYERS * 32768];
__device__ unsigned g_pk_n2[NLAYERS * 16384];

__device__ __forceinline__ float silu_f(float x) {
    return x / (1.f + __expf(-x));
}

// ---- tf32 mma helpers ----
__device__ __forceinline__ float tf32f(float f) {
    unsigned int u;
    asm("cvt.rna.tf32.f32 %0, %1;" : "=r"(u) : "f"(f));
    return __uint_as_float(u);
}
__device__ __forceinline__ void mma_tf32(float* c, const uint4& a, const uint2& b) {
    asm volatile(
        "mma.sync.aligned.m16n8k8.row.col.f32.tf32.tf32.f32 "
        "{%0,%1,%2,%3}, {%4,%5,%6,%7}, {%8,%9}, {%0,%1,%2,%3};"
        : "+f"(c[0]), "+f"(c[1]), "+f"(c[2]), "+f"(c[3])
        : "r"(a.x), "r"(a.y), "r"(a.z), "r"(a.w), "r"(b.x), "r"(b.y));
}
__device__ __forceinline__ unsigned pack_w(float w) {
    __nv_bfloat16 h = __float2bfloat16(w);
    float hf = __bfloat162float(h);
    __nv_bfloat16 l = __float2bfloat16(w - hf);
    return ((unsigned)__bfloat16_as_ushort(h) << 16) | (unsigned)__bfloat16_as_ushort(l);
}
__device__ __forceinline__ void mma_split(float* c, const uint4& a, const uint2& p) {
    uint2 bh = make_uint2(p.x & 0xFFFF0000u, p.y & 0xFFFF0000u);
    uint2 bl = make_uint2(p.x << 16, p.y << 16);
    mma_tf32(c, a, bh);
    mma_tf32(c, a, bl);
}
__device__ __forceinline__ void mma_split3(float* c, const uint4& ah, const uint4& al,
                                           const uint2& p) {
    uint2 bh = make_uint2(p.x & 0xFFFF0000u, p.y & 0xFFFF0000u);
    uint2 bl = make_uint2(p.x << 16, p.y << 16);
    mma_tf32(c, ah, bh);
    mma_tf32(c, ah, bl);
    mma_tf32(c, al, bh);
}
__device__ __forceinline__ int fragA16(int e, int k) {
    int lane = ((e & 7) << 2) | (k & 3);
    int reg = ((e >> 3) & 1) | (((k >> 2) & 1) << 1);
    return (((e >> 4) * 16 + (k >> 3)) << 7) + (lane << 2) + reg;
}

// ---------------- k_pack: pack all layer weights once per launch ----------------
#define PACK_PER_LAYER (32768 + 16384 + 16384 + 32768 + 16384)  // 114688
__global__ __launch_bounds__(256) void k_pack(const float* __restrict__ ew1,
                                              const float* __restrict__ ew2,
                                              const float* __restrict__ cw1,
                                              const float* __restrict__ nw1,
                                              const float* __restrict__ nw2) {
    int idx = blockIdx.x * 256 + threadIdx.x;
    if (idx >= NLAYERS * PACK_PER_LAYER) return;
    int l = idx / PACK_PER_LAYER;
    int o = idx - l * PACK_PER_LAYER;
    if (o < 32768) {
        int i = o;
        int r = i & 1, lane = (i >> 1) & 31, ks = (i >> 6) & 15, nt = i >> 10;
        int k = ks * 8 + (lane & 3) + r * 4;
        int jj = nt * 8 + (lane >> 2);
        int srcrow = (jj < 128) ? k : (128 + k);
        g_pk_proj[l * 32768 + i] = pack_w(ew1[l * 261 * H + srcrow * H + (jj & 127)]);
    } else if (o < 49152) {
        int i = o - 32768;
        int r = i & 1, lane = (i >> 1) & 31, ks = (i >> 6) & 15, nt = i >> 10;
        int k = ks * 8 + (lane & 3) + r * 4;
        int n = nt * 8 + (lane >> 2);
        g_pk_w2[l * 16384 + i] = pack_w(ew2[l * H * H + k * H + n]);
    } else if (o < 65536) {
        int i = o - 49152;
        int r = i & 1, lane = (i >> 1) & 31, ks = (i >> 6) & 15, nt = i >> 10;
        int k = ks * 8 + (lane & 3) + r * 4;
        int n = nt * 8 + (lane >> 2);
        g_pk_c1[l * 16384 + i] = pack_w(cw1[l * H * H + k * H + n]);
    } else if (o < 98304) {
        int i = o - 65536;
        int hk = i >> 14, i2 = i & 16383;
        int r = i2 & 1, lane = (i2 >> 1) & 31, ks = (i2 >> 6) & 15, nt = i2 >> 10;
        int k = hk * 128 + ks * 8 + (lane & 3) + r * 4;
        int n = nt * 8 + (lane >> 2);
        g_pk_n1[l * 32768 + i] = pack_w(nw1[l * 2 * H * H + k * H + n]);
    } else {
        int i = o - 98304;
        int r = i & 1, lane = (i >> 1) & 31, ks = (i >> 6) & 15, nt = i >> 10;
        int k = ks * 8 + (lane & 3) + r * 4;
        int n = nt * 8 + (lane >> 2);
        g_pk_n2[l * 16384 + i] = pack_w(nw2[l * H * H + k * H + n]);
    }
}

// ---------------- K1: embed ----------------
__global__ void k_embed(const float* __restrict__ x, const float* __restrict__ pos_in,
                        const float* __restrict__ Wp, const float* __restrict__ bp,
                        const float* __restrict__ Wl, const float* __restrict__ bl) {
    __shared__ float xs[PN];
    const int i = blockIdx.x;
    const int t = threadIdx.x;
    if (t < PN) xs[t] = x[i * PN + t];
    if (t == 0) g_deg[i] = 0.f;
    if (t < 3) g_pos[i * 3 + t] = pos_in[i * 3 + t];
    if (i == 0 && t < H) { g_bnstats[t] = 0.f; g_bnstats[H + t] = 0.f; }
    __syncthreads();
    const bool isp = (i % NPG) < NPROT;
    const float* W = isp ? Wp : Wl;
    const float* b = isp ? bp : bl;
    const int nk = isp ? PN : LN;
    float acc = b[t];
    for (int k = 0; k < nk; k++) acc += xs[k] * W[k * H + t];
    g_h[i * H + t] = acc;
}

// ---------------- K2: bnstats + degree ----------------
#define DEG_BLOCKS ((N_EDGES + 511) / 512)
__global__ __launch_bounds__(512) void k_stats_deg(const int* __restrict__ ei) {
    const int t = threadIdx.x;
    if (blockIdx.x < 256) {
        const int j = t & 127;
        const int g2 = t >> 7;
        float s = 0.f, s2 = 0.f;
        for (int i = blockIdx.x * 4 + g2; i < N_NODES; i += 1024) {
            float v = g_h[i * H + j];
            s += v; s2 += v * v;
        }
        atomicAdd(&g_bnstats[j], s);
        atomicAdd(&g_bnstats[H + j], s2);
    } else {
        const int e = (blockIdx.x - 256) * 512 + t;
        if (e < N_EDGES) atomicAdd(&g_deg[ei[e]], 1.0f);
    }
}

// ---------------- K3: bnapply + degree scan ----------------
#define BNA_BLOCKS ((N_NODES * H) / 512)
__global__ __launch_bounds__(512) void k_bnapply_scan(const float* __restrict__ gamma,
                                                      const float* __restrict__ beta) {
    const int t = threadIdx.x;
    if (blockIdx.x < BNA_BLOCKS) {
        const int idx = blockIdx.x * 512 + t;
        const int j = idx & (H - 1);
        const float inv_n = 1.f / (float)N_NODES;
        float mu = g_bnstats[j] * inv_n;
        float var = g_bnstats[H + j] * inv_n - mu * mu;
        g_h[idx] = (g_h[idx] - mu) * rsqrtf(var + EPS) * gamma[j] + beta[j];
    } else {
        __shared__ int sums[512];
        const int chunk = 98;
        int base = t * chunk;
        int lim = min(base + chunk, N_NODES);
        int s = 0;
        for (int i = base; i < lim; i++) s += (int)g_deg[i];
        sums[t] = s;
        __syncthreads();
        for (int off = 1; off < 512; off <<= 1) {
            int v = (t >= off) ? sums[t - off] : 0;
            __syncthreads();
            sums[t] += v;
            __syncthreads();
        }
        int run = (t == 0) ? 0 : sums[t - 1];
        for (int i = base; i < lim; i++) {
            g_rowcur[i] = run;
            run += (int)g_deg[i];
        }
    }
}

// ---------------- counting-sort scatter ----------------
__global__ __launch_bounds__(512) void k_perm(const int* __restrict__ ei) {
    const int e = blockIdx.x * 512 + threadIdx.x;
    if (e >= N_EDGES) return;
    int r = ei[e];
    int p = atomicAdd(&g_rowcur[r], 1);
    g_srow[p] = r;
    g_scol[p] = ei[N_EDGES + e];
    g_sperm[p] = e;
}

// ---------------- proj: 3-MMA split-split, pre-packed weights ----------------
__global__ __launch_bounds__(1024, 1) void k_proj(int l, const float* __restrict__ b1) {
    extern __shared__ float sm[];
    unsigned* wF = (unsigned*)sm;   // 32768
    float* aH = sm + 32768;         // 8192
    float* aL = aH + 8192;          // 8192
    const int t = threadIdx.x;
    const int n0 = blockIdx.x * 64;

    {
        const uint4* s = (const uint4*)(g_pk_proj + l * 32768);
        uint4* d = (uint4*)wF;
        for (int i = t; i < 8192; i += 1024) d[i] = s[i];
    }
    for (int i = t; i < 8192; i += 1024) {
        int n = i >> 7, k = i & 127;
        int gi = n0 + n;
        float v = (gi < N_NODES) ? g_h[gi * H + k] : 0.f;
        float hi = tf32f(v);
        int fi = fragA16(n, k);
        aH[fi] = hi;
        aL[fi] = tf32f(v - hi);
    }
    for (int i = t; i < 8192; i += 1024) {
        int gi = n0 + (i >> 7);
        if (gi < N_NODES) g_agg[gi * H + (i & 127)] = 0.f;
    }
    if (t < 192) {
        int gi = n0 + t / 3;
        if (gi < N_NODES) g_posdelta[gi * 3 + t % 3] = 0.f;
    }
    __syncthreads();

    const int wid = t >> 5, lane = t & 31;
    const int mt = wid >> 3;       // 0..3
    const int ng = wid & 7;        // 0..7, 4 n-tiles each
    const int grp = lane >> 2, thr = lane & 3;
    float c[4][4];
#pragma unroll
    for (int q = 0; q < 4; q++)
#pragma unroll
        for (int r = 0; r < 4; r++) c[q][r] = 0.f;

#pragma unroll
    for (int ks = 0; ks < 16; ks++) {
        int aoff = (((mt * 16 + ks) << 5) + lane) << 2;
        uint4 ah = *(const uint4*)&aH[aoff];
        uint4 al = *(const uint4*)&aL[aoff];
#pragma unroll
        for (int q = 0; q < 4; q++) {
            int nt = ng * 4 + q;
            uint2 p = *(const uint2*)&wF[(((nt * 16 + ks) << 5) + lane) << 1];
            mma_split3(c[q], ah, al, p);
        }
    }

    const int ee0 = mt * 16 + grp, ee1 = ee0 + 8;
    const int g0 = n0 + ee0, g1 = n0 + ee1;
#pragma unroll
    for (int q = 0; q < 4; q++) {
        int nt = ng * 4 + q;
        int jj0 = nt * 8 + 2 * thr;
        int half = jj0 >> 7;
        int j = jj0 & 127;
        float* outp = half ? g_P2 : g_P1;
        float bb0 = half ? 0.f : __ldg(&b1[j]);
        float bb1 = half ? 0.f : __ldg(&b1[j + 1]);
        if (g0 < N_NODES)
            *(float2*)&outp[g0 * H + j] = make_float2(c[q][0] + bb0, c[q][1] + bb1);
        if (g1 < N_NODES)
            *(float2*)&outp[g1 * H + j] = make_float2(c[q][2] + bb0, c[q][3] + bb1);
    }
}

// ---------------- fused edge kernel: 128-edge tiles, in-place hid->m ----------------
__global__ __launch_bounds__(1024, 1) void k_edge(
    const float* __restrict__ eattr, int l,
    const float* __restrict__ b2, const float* __restrict__ cb1,
    const float* __restrict__ cw2, const float* __restrict__ ew1) {
    extern __shared__ float sm[];
    unsigned* w2F = (unsigned*)sm;         // 16384
    unsigned* c1F = w2F + 16384;           // 16384
    float* actF  = (float*)(c1F + 16384);  // 16384 (hid, then m; frag order)
    float* b2_s  = actF + 16384;           // 128
    float* cb1_s = b2_s + 128;             // 128
    float* c2_s  = cb1_s + 128;            // 128
    float* wd2_s = c2_s + 128;             // 128
    float* wea_s = wd2_s + 128;            // 512
    float* d2_s  = wea_s + 512;            // 128
    float* rel_s = d2_s + 128;             // 384
    float* ea_s  = rel_s + 384;            // 512
    float* wsum_s = ea_s + 512;            // 128
    int* row_s = (int*)(wsum_s + 128);     // 128
    int* col_s = row_s + 128;              // 128

    const int t = threadIdx.x;
    {
        const uint4* s2 = (const uint4*)(g_pk_w2 + l * 16384);
        const uint4* s1 = (const uint4*)(g_pk_c1 + l * 16384);
        uint4* d2 = (uint4*)w2F;
        uint4* d1 = (uint4*)c1F;
        for (int i = t; i < 4096; i += 1024) { d2[i] = s2[i]; d1[i] = s1[i]; }
    }
    if (t < 128) {
        b2_s[t] = b2[t]; cb1_s[t] = cb1[t]; c2_s[t] = cw2[t];
        wd2_s[t] = ew1[256 * H + t];
    }
    if (t >= 128 && t < 640) wea_s[t - 128] = ew1[257 * H + (t - 128)];
    __syncthreads();

    const int w = t >> 5;
    const int lane = t & 31;
    const int mt = w >> 2;         // 0..7
    const int ng = w & 3;          // 0..3 -> n-tiles ng*4..ng*4+3
    const int grp = lane >> 2;     // 0..7
    const int thr = lane & 3;      // 0..3
    const int ee0 = mt * 16 + grp, ee1 = ee0 + 8;
    const int ntiles = (N_EDGES + NE_TILE - 1) / NE_TILE;

    for (int tile = blockIdx.x; tile < ntiles; tile += gridDim.x) {
        const int e0 = tile * NE_TILE;
        if (t < NE_TILE) {
            wsum_s[t] = 0.f;
            int sidx = e0 + t;
            int r = -1, c = 0, pe = 0;
            if (sidx < N_EDGES) { r = g_srow[sidx]; c = g_scol[sidx]; pe = g_sperm[sidx]; }
            row_s[t] = r; col_s[t] = c;
            float4 a = make_float4(0.f, 0.f, 0.f, 0.f);
            if (r >= 0) a = *(const float4*)&eattr[pe * 4];
            int rr = r < 0 ? 0 : r;
            float rx = g_pos[rr * 3 + 0] - g_pos[c * 3 + 0];
            float ry = g_pos[rr * 3 + 1] - g_pos[c * 3 + 1];
            float rz = g_pos[rr * 3 + 2] - g_pos[c * 3 + 2];
            rel_s[t * 3 + 0] = rx; rel_s[t * 3 + 1] = ry; rel_s[t * 3 + 2] = rz;
            d2_s[t] = rx * rx + ry * ry + rz * rz;
            ea_s[t * 4 + 0] = a.x; ea_s[t * 4 + 1] = a.y;
            ea_s[t * 4 + 2] = a.z; ea_s[t * 4 + 3] = a.w;
        }
        __syncthreads();

        // Phase A: hidden -> actF
#pragma unroll
        for (int rep = 0; rep < 16; rep++) {
            int idx = t + rep * 1024;
            int e = idx >> 7, j = idx & 127;
            int r = row_s[e], c = col_s[e];
            int rr = r < 0 ? 0 : r;
            float v = g_P1[rr * H + j] + g_P2[c * H + j] + d2_s[e] * wd2_s[j];
#pragma unroll
            for (int a2 = 0; a2 < 4; a2++) v += ea_s[e * 4 + a2] * wea_s[a2 * H + j];
            actF[fragA16(e, j)] = tf32f(silu_f(v));
        }
        __syncthreads();

        // Phase B: m = silu(hid @ W2 + b2), results in regs
        float cB[4][4];
#pragma unroll
        for (int q = 0; q < 4; q++) {
            int jc = (ng * 4 + q) * 8 + 2 * thr;
            cB[q][0] = b2_s[jc]; cB[q][1] = b2_s[jc + 1];
            cB[q][2] = cB[q][0]; cB[q][3] = cB[q][1];
        }
#pragma unroll
        for (int ks = 0; ks < 16; ks++) {
            uint4 a = *(const uint4*)&actF[(((mt * 16 + ks) << 5) + lane) << 2];
#pragma unroll
            for (int q = 0; q < 4; q++) {
                uint2 p = *(const uint2*)&w2F[((((ng * 4 + q) * 16 + ks) << 5) + lane) << 1];
                mma_split(cB[q], a, p);
            }
        }
        __syncthreads();   // all reads of hid complete
        // writeback m into actF (in place)
#pragma unroll
        for (int q = 0; q < 4; q++) {
            int jq = (ng * 4 + q) * 8 + 2 * thr;
            actF[fragA16(ee0, jq)]     = tf32f(silu_f(cB[q][0]));
            actF[fragA16(ee0, jq + 1)] = tf32f(silu_f(cB[q][1]));
            actF[fragA16(ee1, jq)]     = tf32f(silu_f(cB[q][2]));
            actF[fragA16(ee1, jq + 1)] = tf32f(silu_f(cB[q][3]));
        }
        __syncthreads();

        // Phase C: w = silu(m@C1 + cb1) @ C2
        {
            float cC[4][4];
#pragma unroll
            for (int q = 0; q < 4; q++) {
                int jc = (ng * 4 + q) * 8 + 2 * thr;
                cC[q][0] = cb1_s[jc]; cC[q][1] = cb1_s[jc + 1];
                cC[q][2] = cC[q][0]; cC[q][3] = cC[q][1];
            }
#pragma unroll
            for (int ks = 0; ks < 16; ks++) {
                uint4 a = *(const uint4*)&actF[(((mt * 16 + ks) << 5) + lane) << 2];
#pragma unroll
                for (int q = 0; q < 4; q++) {
                    uint2 p = *(const uint2*)&c1F[((((ng * 4 + q) * 16 + ks) << 5) + lane) << 1];
                    mma_split(cC[q], a, p);
                }
            }
            float sl = 0.f, sh = 0.f;
#pragma unroll
            for (int q = 0; q < 4; q++) {
                int jq = (ng * 4 + q) * 8 + 2 * thr;
                sl += silu_f(cC[q][0]) * c2_s[jq] + silu_f(cC[q][1]) * c2_s[jq + 1];
                sh += silu_f(cC[q][2]) * c2_s[jq] + silu_f(cC[q][3]) * c2_s[jq + 1];
            }
            sl += __shfl_xor_sync(0xffffffffu, sl, 1);
            sl += __shfl_xor_sync(0xffffffffu, sl, 2);
            sh += __shfl_xor_sync(0xffffffffu, sh, 1);
            sh += __shfl_xor_sync(0xffffffffu, sh, 2);
            if (thr == 0) {
                atomicAdd(&wsum_s[ee0], sl);
                atomicAdd(&wsum_s[ee1], sh);
            }
        }
        __syncthreads();

        // Phase D: segment-scan scatter of m; posdelta from wsum
        {
            const int j = t & 127;
            const int q = t >> 7;          // 0..7
            const int ebeg = q * 16;
            float acc = 0.f;
            int cur = row_s[ebeg];
#pragma unroll
            for (int i = 0; i < 16; i++) {
                int e = ebeg + i;
                int r = row_s[e];
                float v = actF[fragA16(e, j)];
                if (r != cur) {
                    if (cur >= 0) atomicAdd(&g_agg[cur * H + j], acc);
                    acc = 0.f;
                    cur = r;
                }
                acc += v;
            }
            if (cur >= 0) atomicAdd(&g_agg[cur * H + j], acc);
        }
        if (t < 384) {
            int e = t / 3, k = t % 3;
            int r = row_s[e];
            if (r >= 0)
                atomicAdd(&g_posdelta[r * 3 + k], rel_s[e * 3 + k] * wsum_s[e]);
        }
        __syncthreads();
    }
}

// ---------------- pos update ----------------
__global__ void k_pos() {
    const int idx = blockIdx.x * blockDim.x + threadIdx.x;
    if (idx >= N_NODES * 3) return;
    const int i = idx / 3;
    float d = fmaxf(g_deg[i], 1.0f);
    g_pos[idx] += g_posdelta[idx] / d;
}

// ---------------- node1: 3-MMA, two K-half passes, pre-packed ----------------
__global__ __launch_bounds__(1024, 1) void k_node1(int l, const float* __restrict__ b) {
    extern __shared__ float sm[];
    unsigned* wF = (unsigned*)sm;   // 16384 (one K-half)
    float* aH = sm + 16384;         // 8192
    float* aL = aH + 8192;          // 8192
    const int t = threadIdx.x;
    const int n0 = blockIdx.x * 64;
    const int wid = t >> 5, lane = t & 31;
    const int mt = wid >> 3, nt0 = (wid & 7) * 2;
    const int grp = lane >> 2, thr = lane & 3;
    float c0[4] = {0.f, 0.f, 0.f, 0.f}, c1[4] = {0.f, 0.f, 0.f, 0.f};

    for (int halfk = 0; halfk < 2; halfk++) {
        __syncthreads();
        {
            const uint4* s = (const uint4*)(g_pk_n1 + l * 32768 + halfk * 16384);
            uint4* d = (uint4*)wF;
            for (int i = t; i < 4096; i += 1024) d[i] = s[i];
        }
        const float* src = halfk ? g_agg : g_h;
        for (int i = t; i < 8192; i += 1024) {
            int n = i >> 7, kk = i & 127;
            int gi = n0 + n;
            float v = (gi < N_NODES) ? src[gi * H + kk] : 0.f;
            float hi = tf32f(v);
            int fi = fragA16(n, kk);
            aH[fi] = hi;
            aL[fi] = tf32f(v - hi);
        }
        __syncthreads();
#pragma unroll
        for (int ks = 0; ks < 16; ks++) {
            int aoff = (((mt * 16 + ks) << 5) + lane) << 2;
            uint4 ah = *(const uint4*)&aH[aoff];
            uint4 al = *(const uint4*)&aL[aoff];
            uint2 p0 = *(const uint2*)&wF[(((nt0 * 16 + ks) << 5) + lane) << 1];
            uint2 p1 = *(const uint2*)&wF[((((nt0 + 1) * 16 + ks) << 5) + lane) << 1];
            mma_split3(c0, ah, al, p0);
            mma_split3(c1, ah, al, p1);
        }
    }
    const int ee0 = mt * 16 + grp, ee1 = ee0 + 8;
    const int g0 = n0 + ee0, g1 = n0 + ee1;
    const int j00 = nt0 * 8 + 2 * thr, j10 = (nt0 + 1) * 8 + 2 * thr;
    float b00 = __ldg(&b[j00]), b01 = __ldg(&b[j00 + 1]);
    float b10 = __ldg(&b[j10]), b11 = __ldg(&b[j10 + 1]);
    if (g0 < N_NODES) {
        *(float2*)&g_U[g0 * H + j00] = make_float2(silu_f(c0[0] + b00), silu_f(c0[1] + b01));
        *(float2*)&g_U[g0 * H + j10] = make_float2(silu_f(c1[0] + b10), silu_f(c1[1] + b11));
    }
    if (g1 < N_NODES) {
        *(float2*)&g_U[g1 * H + j00] = make_float2(silu_f(c0[2] + b00), silu_f(c0[3] + b01));
        *(float2*)&g_U[g1 * H + j10] = make_float2(silu_f(c1[2] + b10), silu_f(c1[3] + b11));
    }
}

// ---------------- node2: 3-MMA split-split, pre-packed ----------------
__global__ __launch_bounds__(1024, 1) void k_node2(int l, const float* __restrict__ b) {
    extern __shared__ float sm[];
    unsigned* wF = (unsigned*)sm;   // 16384
    float* aH = sm + 16384;         // 8192
    float* aL = aH + 8192;          // 8192
    const int t = threadIdx.x;
    const int n0 = blockIdx.x * 64;
    {
        const uint4* s = (const uint4*)(g_pk_n2 + l * 16384);
        uint4* d = (uint4*)wF;
        for (int i = t; i < 4096; i += 1024) d[i] = s[i];
    }
    for (int i = t; i < 8192; i += 1024) {
        int n = i >> 7, k = i & 127;
        int gi = n0 + n;
        float v = (gi < N_NODES) ? g_U[gi * H + k] : 0.f;
        float hi = tf32f(v);
        int fi = fragA16(n, k);
        aH[fi] = hi;
        aL[fi] = tf32f(v - hi);
    }
    __syncthreads();

    const int wid = t >> 5, lane = t & 31;
    const int mt = wid >> 3, nt0 = (wid & 7) * 2;
    const int grp = lane >> 2, thr = lane & 3;
    float c0[4] = {0.f, 0.f, 0.f, 0.f}, c1[4] = {0.f, 0.f, 0.f, 0.f};
#pragma unroll
    for (int ks = 0; ks < 16; ks++) {
        int aoff = (((mt * 16 + ks) << 5) + lane) << 2;
        uint4 ah = *(const uint4*)&aH[aoff];
        uint4 al = *(const uint4*)&aL[aoff];
        uint2 p0 = *(const uint2*)&wF[(((nt0 * 16 + ks) << 5) + lane) << 1];
        uint2 p1 = *(const uint2*)&wF[((((nt0 + 1) * 16 + ks) << 5) + lane) << 1];
        mma_split3(c0, ah, al, p0);
        mma_split3(c1, ah, al, p1);
    }
    const int ee0 = mt * 16 + grp, ee1 = ee0 + 8;
    const int g0 = n0 + ee0, g1 = n0 + ee1;
    const int j00 = nt0 * 8 + 2 * thr, j10 = (nt0 + 1) * 8 + 2 * thr;
    float b00 = __ldg(&b[j00]), b01 = __ldg(&b[j00 + 1]);
    float b10 = __ldg(&b[j10]), b11 = __ldg(&b[j10 + 1]);
    if (g0 < N_NODES) {
        float2 h0 = *(float2*)&g_h[g0 * H + j00];
        h0.x += c0[0] + b00; h0.y += c0[1] + b01;
        *(float2*)&g_h[g0 * H + j00] = h0;
        float2 h1 = *(float2*)&g_h[g0 * H + j10];
        h1.x += c1[0] + b10; h1.y += c1[1] + b11;
        *(float2*)&g_h[g0 * H + j10] = h1;
    }
    if (g1 < N_NODES) {
        float2 h0 = *(float2*)&g_h[g1 * H + j00];
        h0.x += c0[2] + b00; h0.y += c0[3] + b01;
        *(float2*)&g_h[g1 * H + j00] = h0;
        float2 h1 = *(float2*)&g_h[g1 * H + j10];
        h1.x += c1[2] + b10; h1.y += c1[3] + b11;
        *(float2*)&g_h[g1 * H + j10] = h1;
    }
}

// ---------------- pooling ----------------
__global__ __launch_bounds__(512) void k_pool() {
    __shared__ float red[512];
    const int g = blockIdx.x, t = threadIdx.x;
    const int j = t & 127, w = t >> 7;
    float s = 0.f;
    for (int n = w; n < NPG; n += 4) s += g_h[(g * NPG + n) * H + j];
    red[t] = s;
    __syncthreads();
    if (w == 0) {
        float tot = red[j] + red[128 + j] + red[256 + j] + red[384 + j];
        g_gfeat[g * 256 + j] = tot;
        g_gfeat[g * 256 + 128 + j] = tot * (1.f / (float)NPG);
    }
}

// ---------------- readout head ----------------
__global__ void k_head(const float* __restrict__ h1_w, const float* __restrict__ h1_b,
                       const float* __restrict__ h2_w, const float* __restrict__ h2_b,
                       const float* __restrict__ h3_w, const float* __restrict__ h3_b,
                       float* __restrict__ out) {
    __shared__ float gf[256], z1[128], z2[64];
    const int g = blockIdx.x, t = threadIdx.x;
    gf[t] = g_gfeat[g * 256 + t];
    gf[128 + t] = g_gfeat[g * 256 + 128 + t];
    __syncthreads();
    float a = h1_b[t];
    for (int k = 0; k < 256; k++) a += gf[k] * h1_w[k * 128 + t];
    z1[t] = fmaxf(a, 0.f);
    __syncthreads();
    if (t < 64) {
        float a2 = h2_b[t];
        for (int k = 0; k < 128; k++) a2 += z1[k] * h2_w[k * 64 + t];
        z2[t] = fmaxf(a2, 0.f);
    }
    __syncthreads();
    if (t == 0) {
        float a3 = h3_b[0];
        for (int k = 0; k < 64; k++) a3 += z2[k] * h3_w[k];
        out[g] = a3;
    }
}

// ---------------- launch ----------------
extern "C" void kernel_launch(void* const* d_in, const int* in_sizes, int n_in,
                              void* d_out, int out_size) {
    const float* x     = (const float*)d_in[0];
    const float* pos   = (const float*)d_in[1];
    const int*   ei    = (const int*)d_in[2];
    const float* eattr = (const float*)d_in[3];
    const float* Wp    = (const float*)d_in[6];
    const float* bp    = (const float*)d_in[7];
    const float* Wl    = (const float*)d_in[8];
    const float* bl    = (const float*)d_in[9];
    const float* gamma = (const float*)d_in[10];
    const float* beta  = (const float*)d_in[11];
    const float* e_w1  = (const float*)d_in[12];
    const float* e_b1  = (const float*)d_in[13];
    const float* e_w2  = (const float*)d_in[14];
    const float* e_b2  = (const float*)d_in[15];
    const float* c_w1  = (const float*)d_in[16];
    const float* c_b1  = (const float*)d_in[17];
    const float* c_w2  = (const float*)d_in[18];
    const float* n_w1  = (const float*)d_in[19];
    const float* n_b1  = (const float*)d_in[20];
    const float* n_w2  = (const float*)d_in[21];
    const float* n_b2  = (const float*)d_in[22];
    const float* h1_w  = (const float*)d_in[23];
    const float* h1_b  = (const float*)d_in[24];
    const float* h2_w  = (const float*)d_in[25];
    const float* h2_b  = (const float*)d_in[26];
    const float* h3_w  = (const float*)d_in[27];
    const float* h3_b  = (const float*)d_in[28];
    float* out = (float*)d_out;

    const int PROJ_SMEM = (32768 + 8192 + 8192) * 4;
    const int EDGE_SMEM = (16384 * 3 + 128 * 4 + 512 + 128 + 384 + 512 + 128 + 128 + 128) * 4;
    const int N1_SMEM = (16384 + 8192 + 8192) * 4;
    const int N2_SMEM = (16384 + 8192 + 8192) * 4;
    cudaFuncSetAttribute(k_proj,  cudaFuncAttributeMaxDynamicSharedMemorySize, PROJ_SMEM);
    cudaFuncSetAttribute(k_edge,  cudaFuncAttributeMaxDynamicSharedMemorySize, EDGE_SMEM);
    cudaFuncSetAttribute(k_node1, cudaFuncAttributeMaxDynamicSharedMemorySize, N1_SMEM);
    cudaFuncSetAttribute(k_node2, cudaFuncAttributeMaxDynamicSharedMemorySize, N2_SMEM);

    const int nblocks64 = (N_NODES + 63) / 64;   // 782

    k_embed<<<N_NODES, 128>>>(x, pos, Wp, bp, Wl, bl);
    k_pack<<<(NLAYERS * PACK_PER_LAYER + 255) / 256, 256>>>(e_w1, e_w2, c_w1, n_w1, n_w2);
    k_stats_deg<<<256 + DEG_BLOCKS, 512>>>(ei);
    k_bnapply_scan<<<BNA_BLOCKS + 1, 512>>>(gamma, beta);

    for (int l = 0; l < NLAYERS; l++) {
        k_proj<<<nblocks64, 1024, PROJ_SMEM>>>(l, e_b1 + l * H);
        if (l == 0) k_perm<<<(N_EDGES + 511) / 512, 512>>>(ei);
        k_edge<<<148, 1024, EDGE_SMEM>>>(eattr, l, e_b2 + l * H, c_b1 + l * H,
                                         c_w2 + l * H, e_w1 + l * 261 * H);
        k_node1<<<nblocks64, 1024, N1_SMEM>>>(l, n_b1 + l * H);
        k_node2<<<nblocks64, 1024, N2_SMEM>>>(l, n_b2 + l * H);
        k_pos<<<(N_NODES * 3 + 511) / 512, 512>>>();
    }

    k_pool<<<G_GRAPHS, 512>>>();
    k_head<<<G_GRAPHS, 128>>>(h1_w, h1_b, h2_w, h2_b, h3_w, h3_b, out);
}

// round 10
// speedup vs baseline: 1.6050x; 1.1909x over previous
#include <cuda_runtime.h>
#include <cuda_bf16.h>

#define N_NODES 50000
#define N_EDGES 500000
#define H 128
#define G_GRAPHS 100
#define NPG 500
#define NPROT 400
#define PN 35
#define LN 11
#define NLAYERS 4
#define EPS 1e-5f
#define NE_TILE 128

// ---------------- scratch ----------------
__device__ float g_h[N_NODES * H];
__device__ float g_P1[N_NODES * H];
__device__ float g_P2[N_NODES * H];
__device__ float g_agg[N_NODES * H];
__device__ float g_U[N_NODES * H];
__device__ float g_pos[N_NODES * 3];
__device__ float g_posdelta[N_NODES * 3];
__device__ float g_deg[N_NODES];
__device__ float g_bnstats[2 * H];
__device__ float g_gfeat[G_GRAPHS * 2 * H];
__device__ int g_rowcur[N_NODES];
__device__ int g_srow[N_EDGES];
__device__ int g_scol[N_EDGES];
__device__ int g_sperm[N_EDGES];
// pre-packed bf16 hi/lo weight fragments (packed per-launch by k_pack)
__device__ unsigned g_pk_proj[NLAYERS * 32768];  // hi 16384 | lo 16384
__device__ unsigned g_pk_w2[NLAYERS * 16384];    // hi 8192 | lo 8192
__device__ unsigned g_pk_c1[NLAYERS * 16384];
__device__ unsigned g_pk_n1[NLAYERS * 32768];    // [half0: hi|lo][half1: hi|lo]
__device__ unsigned g_pk_n2[NLAYERS * 16384];

__device__ __forceinline__ float silu_f(float x) {
    return x / (1.f + __expf(-x));
}

// ---- bf16 m16n8k16 mma ----
__device__ __forceinline__ void mma_bf16(float* c, const uint4& a, const uint2& b) {
    asm volatile(
        "mma.sync.aligned.m16n8k16.row.col.f32.bf16.bf16.f32 "
        "{%0,%1,%2,%3}, {%4,%5,%6,%7}, {%8,%9}, {%0,%1,%2,%3};"
        : "+f"(c[0]), "+f"(c[1]), "+f"(c[2]), "+f"(c[3])
        : "r"(a.x), "r"(a.y), "r"(a.z), "r"(a.w), "r"(b.x), "r"(b.y));
}
// split (v0,v1) into bf16x2 hi word + bf16x2 lo (residual) word
__device__ __forceinline__ unsigned split2(float v0, float v1, unsigned& lo) {
    __nv_bfloat16 h0 = __float2bfloat16(v0);
    __nv_bfloat16 h1 = __float2bfloat16(v1);
    __nv_bfloat16 l0 = __float2bfloat16(v0 - __bfloat162float(h0));
    __nv_bfloat16 l1 = __float2bfloat16(v1 - __bfloat162float(h1));
    lo = (unsigned)__bfloat16_as_ushort(l0) | ((unsigned)__bfloat16_as_ushort(l1) << 16);
    return (unsigned)__bfloat16_as_ushort(h0) | ((unsigned)__bfloat16_as_ushort(h1) << 16);
}
// 3-term split-split MMA (drops lo*lo ~2^-18)
__device__ __forceinline__ void mma3(float* c, const uint4& ah, const uint4& al,
                                     const uint2& bh, const uint2& bl) {
    mma_bf16(c, ah, bh);
    mma_bf16(c, ah, bl);
    mma_bf16(c, al, bh);
}
// A-fragment word index for value pair (e, j0..j0+1), j0 even; KT = K/16 tiles
__device__ __forceinline__ int fragAb(int e, int j0, int KT) {
    int jin = j0 & 15;
    int tid = (jin & 7) >> 1;
    int reg = ((jin >> 3) << 1) | ((e >> 3) & 1);
    int lane = ((e & 7) << 2) | tid;
    return (((e >> 4) * KT + (j0 >> 4)) << 7) + (lane << 2) + reg;
}

// ---------------- k_pack ----------------
// hi-word index decode (per segment): i = ((nt*KT + kt)*32 + lane)*2 + rb
// k0 = kt*16 + tid*2 + rb*8 ; n = nt*8 + (lane>>2)
#define PACK_PER_LAYER (16384 + 8192 + 8192 + 16384 + 8192)  // 57344
__global__ __launch_bounds__(256) void k_pack(const float* __restrict__ ew1,
                                              const float* __restrict__ ew2,
                                              const float* __restrict__ cw1,
                                              const float* __restrict__ nw1,
                                              const float* __restrict__ nw2) {
    int idx = blockIdx.x * 256 + threadIdx.x;
    if (idx >= NLAYERS * PACK_PER_LAYER) return;
    int l = idx / PACK_PER_LAYER;
    int o = idx - l * PACK_PER_LAYER;
    float w0, w1;
    unsigned* hip;
    unsigned* lop;
    if (o < 16384) {            // proj: NT=32, KT=8, src e_w1 (261xH, rows 0..255)
        int i = o;
        int rb = i & 1, lane = (i >> 1) & 31, kt = (i >> 6) & 7, nt = i >> 9;
        int tid = lane & 3, g = lane >> 2;
        int k0 = kt * 16 + tid * 2 + rb * 8;
        int jj = nt * 8 + g;
        const float* W = ew1 + l * 261 * H;
        int srcrow = (jj < 128) ? k0 : (128 + k0);
        int col = jj & 127;
        w0 = W[srcrow * H + col];
        w1 = W[(srcrow + 1) * H + col];
        hip = g_pk_proj + l * 32768 + i;
        lop = hip + 16384;
    } else if (o < 24576) {     // w2: NT=16, KT=8
        int i = o - 16384;
        int rb = i & 1, lane = (i >> 1) & 31, kt = (i >> 6) & 7, nt = i >> 9;
        int tid = lane & 3, g = lane >> 2;
        int k0 = kt * 16 + tid * 2 + rb * 8;
        int n = nt * 8 + g;
        const float* W = ew2 + l * H * H;
        w0 = W[k0 * H + n];
        w1 = W[(k0 + 1) * H + n];
        hip = g_pk_w2 + l * 16384 + i;
        lop = hip + 8192;
    } else if (o < 32768) {     // c1
        int i = o - 24576;
        int rb = i & 1, lane = (i >> 1) & 31, kt = (i >> 6) & 7, nt = i >> 9;
        int tid = lane & 3, g = lane >> 2;
        int k0 = kt * 16 + tid * 2 + rb * 8;
        int n = nt * 8 + g;
        const float* W = cw1 + l * H * H;
        w0 = W[k0 * H + n];
        w1 = W[(k0 + 1) * H + n];
        hip = g_pk_c1 + l * 16384 + i;
        lop = hip + 8192;
    } else if (o < 49152) {     // n1: two K-halves, each NT=16 KT=8
        int i2 = o - 32768;
        int hk = i2 >> 13;      // 0..1
        int i = i2 & 8191;
        int rb = i & 1, lane = (i >> 1) & 31, kt = (i >> 6) & 7, nt = i >> 9;
        int tid = lane & 3, g = lane >> 2;
        int k0 = hk * 128 + kt * 16 + tid * 2 + rb * 8;
        int n = nt * 8 + g;
        const float* W = nw1 + l * 2 * H * H;
        w0 = W[k0 * H + n];
        w1 = W[(k0 + 1) * H + n];
        hip = g_pk_n1 + l * 32768 + hk * 16384 + i;
        lop = hip + 8192;
    } else {                    // n2
        int i = o - 49152;
        int rb = i & 1, lane = (i >> 1) & 31, kt = (i >> 6) & 7, nt = i >> 9;
        int tid = lane & 3, g = lane >> 2;
        int k0 = kt * 16 + tid * 2 + rb * 8;
        int n = nt * 8 + g;
        const float* W = nw2 + l * H * H;
        w0 = W[k0 * H + n];
        w1 = W[(k0 + 1) * H + n];
        hip = g_pk_n2 + l * 16384 + i;
        lop = hip + 8192;
    }
    unsigned lo;
    unsigned hi = split2(w0, w1, lo);
    *hip = hi;
    *lop = lo;
}

// ---------------- K1: embed ----------------
__global__ void k_embed(const float* __restrict__ x, const float* __restrict__ pos_in,
                        const float* __restrict__ Wp, const float* __restrict__ bp,
                        const float* __restrict__ Wl, const float* __restrict__ bl) {
    __shared__ float xs[PN];
    const int i = blockIdx.x;
    const int t = threadIdx.x;
    if (t < PN) xs[t] = x[i * PN + t];
    if (t == 0) g_deg[i] = 0.f;
    if (t < 3) g_pos[i * 3 + t] = pos_in[i * 3 + t];
    if (i == 0 && t < H) { g_bnstats[t] = 0.f; g_bnstats[H + t] = 0.f; }
    __syncthreads();
    const bool isp = (i % NPG) < NPROT;
    const float* W = isp ? Wp : Wl;
    const float* b = isp ? bp : bl;
    const int nk = isp ? PN : LN;
    float acc = b[t];
    for (int k = 0; k < nk; k++) acc += xs[k] * W[k * H + t];
    g_h[i * H + t] = acc;
}

// ---------------- K2: bnstats + degree ----------------
#define DEG_BLOCKS ((N_EDGES + 511) / 512)
__global__ __launch_bounds__(512) void k_stats_deg(const int* __restrict__ ei) {
    const int t = threadIdx.x;
    if (blockIdx.x < 256) {
        const int j = t & 127;
        const int g2 = t >> 7;
        float s = 0.f, s2 = 0.f;
        for (int i = blockIdx.x * 4 + g2; i < N_NODES; i += 1024) {
            float v = g_h[i * H + j];
            s += v; s2 += v * v;
        }
        atomicAdd(&g_bnstats[j], s);
        atomicAdd(&g_bnstats[H + j], s2);
    } else {
        const int e = (blockIdx.x - 256) * 512 + t;
        if (e < N_EDGES) atomicAdd(&g_deg[ei[e]], 1.0f);
    }
}

// ---------------- K3: bnapply + degree scan ----------------
#define BNA_BLOCKS ((N_NODES * H) / 512)
__global__ __launch_bounds__(512) void k_bnapply_scan(const float* __restrict__ gamma,
                                                      const float* __restrict__ beta) {
    const int t = threadIdx.x;
    if (blockIdx.x < BNA_BLOCKS) {
        const int idx = blockIdx.x * 512 + t;
        const int j = idx & (H - 1);
        const float inv_n = 1.f / (float)N_NODES;
        float mu = g_bnstats[j] * inv_n;
        float var = g_bnstats[H + j] * inv_n - mu * mu;
        g_h[idx] = (g_h[idx] - mu) * rsqrtf(var + EPS) * gamma[j] + beta[j];
    } else {
        __shared__ int sums[512];
        const int chunk = 98;
        int base = t * chunk;
        int lim = min(base + chunk, N_NODES);
        int s = 0;
        for (int i = base; i < lim; i++) s += (int)g_deg[i];
        sums[t] = s;
        __syncthreads();
        for (int off = 1; off < 512; off <<= 1) {
            int v = (t >= off) ? sums[t - off] : 0;
            __syncthreads();
            sums[t] += v;
            __syncthreads();
        }
        int run = (t == 0) ? 0 : sums[t - 1];
        for (int i = base; i < lim; i++) {
            g_rowcur[i] = run;
            run += (int)g_deg[i];
        }
    }
}

// ---------------- counting-sort scatter ----------------
__global__ __launch_bounds__(512) void k_perm(const int* __restrict__ ei) {
    const int e = blockIdx.x * 512 + threadIdx.x;
    if (e >= N_EDGES) return;
    int r = ei[e];
    int p = atomicAdd(&g_rowcur[r], 1);
    g_srow[p] = r;
    g_scol[p] = ei[N_EDGES + e];
    g_sperm[p] = e;
}

// ---------------- proj: bf16 3-MMA, pre-packed ----------------
__global__ __launch_bounds__(1024, 1) void k_proj(int l, const float* __restrict__ b1) {
    extern __shared__ float sm[];
    unsigned* wF = (unsigned*)sm;       // 32768 (hi 16384 | lo 16384)
    unsigned* aH = wF + 32768;          // 4096
    unsigned* aL = aH + 4096;           // 4096
    const int t = threadIdx.x;
    const int n0 = blockIdx.x * 64;

    {
        const uint4* s = (const uint4*)(g_pk_proj + l * 32768);
        uint4* d = (uint4*)wF;
        for (int i = t; i < 8192; i += 1024) d[i] = s[i];
    }
    for (int i = t; i < 4096; i += 1024) {
        int n = i >> 6, jp = i & 63;
        int j0 = jp * 2;
        int gi = n0 + n;
        float2 v = make_float2(0.f, 0.f);
        if (gi < N_NODES) v = *(const float2*)&g_h[gi * H + j0];
        unsigned lo;
        unsigned hi = split2(v.x, v.y, lo);
        int fi = fragAb(n, j0, 8);
        aH[fi] = hi;
        aL[fi] = lo;
    }
    for (int i = t; i < 8192; i += 1024) {
        int gi = n0 + (i >> 7);
        if (gi < N_NODES) g_agg[gi * H + (i & 127)] = 0.f;
    }
    if (t < 192) {
        int gi = n0 + t / 3;
        if (gi < N_NODES) g_posdelta[gi * 3 + t % 3] = 0.f;
    }
    __syncthreads();

    const int wid = t >> 5, lane = t & 31;
    const int mt = wid >> 3;       // 0..3
    const int ng = wid & 7;        // 0..7, 4 n-tiles each (of 32)
    const int grp = lane >> 2, thr = lane & 3;
    float c[4][4];
#pragma unroll
    for (int q = 0; q < 4; q++)
#pragma unroll
        for (int r = 0; r < 4; r++) c[q][r] = 0.f;

#pragma unroll
    for (int kt = 0; kt < 8; kt++) {
        int aoff = (((mt * 8 + kt) << 5) + lane) << 2;
        uint4 ah = *(const uint4*)&aH[aoff];
        uint4 al = *(const uint4*)&aL[aoff];
#pragma unroll
        for (int q = 0; q < 4; q++) {
            int nt = ng * 4 + q;
            int bi = (((nt * 8 + kt) << 5) + lane) << 1;
            uint2 bh = *(const uint2*)&wF[bi];
            uint2 bl = *(const uint2*)&wF[16384 + bi];
            mma3(c[q], ah, al, bh, bl);
        }
    }

    const int ee0 = mt * 16 + grp, ee1 = ee0 + 8;
    const int g0 = n0 + ee0, g1 = n0 + ee1;
#pragma unroll
    for (int q = 0; q < 4; q++) {
        int nt = ng * 4 + q;
        int jj0 = nt * 8 + 2 * thr;
        int half = jj0 >> 7;
        int j = jj0 & 127;
        float* outp = half ? g_P2 : g_P1;
        float bb0 = half ? 0.f : __ldg(&b1[j]);
        float bb1 = half ? 0.f : __ldg(&b1[j + 1]);
        if (g0 < N_NODES)
            *(float2*)&outp[g0 * H + j] = make_float2(c[q][0] + bb0, c[q][1] + bb1);
        if (g1 < N_NODES)
            *(float2*)&outp[g1 * H + j] = make_float2(c[q][2] + bb0, c[q][3] + bb1);
    }
}

// ---------------- fused edge kernel: bf16 3-MMA, 128-edge tiles ----------------
__global__ __launch_bounds__(1024, 1) void k_edge(
    const float* __restrict__ eattr, int l,
    const float* __restrict__ b2, const float* __restrict__ cb1,
    const float* __restrict__ cw2, const float* __restrict__ ew1) {
    extern __shared__ float sm[];
    unsigned* w2F = (unsigned*)sm;       // 16384 (hi 8192 | lo 8192)
    unsigned* c1F = w2F + 16384;         // 16384
    unsigned* actH = c1F + 16384;        // 8192 (hid, then m)
    unsigned* actL = actH + 8192;        // 8192
    float* b2_s  = (float*)(actL + 8192);  // 128
    float* cb1_s = b2_s + 128;           // 128
    float* c2_s  = cb1_s + 128;          // 128
    float* wd2_s = c2_s + 128;           // 128
    float* wea_s = wd2_s + 128;          // 512
    float* d2_s  = wea_s + 512;          // 128
    float* rel_s = d2_s + 128;           // 384
    float* ea_s  = rel_s + 384;          // 512
    float* wsum_s = ea_s + 512;          // 128
    int* row_s = (int*)(wsum_s + 128);   // 128
    int* col_s = row_s + 128;            // 128

    const int t = threadIdx.x;
    {
        const uint4* s2 = (const uint4*)(g_pk_w2 + l * 16384);
        const uint4* s1 = (const uint4*)(g_pk_c1 + l * 16384);
        uint4* d2 = (uint4*)w2F;
        uint4* d1 = (uint4*)c1F;
        for (int i = t; i < 4096; i += 1024) { d2[i] = s2[i]; d1[i] = s1[i]; }
    }
    if (t < 128) {
        b2_s[t] = b2[t]; cb1_s[t] = cb1[t]; c2_s[t] = cw2[t];
        wd2_s[t] = ew1[256 * H + t];
    }
    if (t >= 128 && t < 640) wea_s[t - 128] = ew1[257 * H + (t - 128)];
    __syncthreads();

    const int w = t >> 5;
    const int lane = t & 31;
    const int mt = w >> 2;         // 0..7
    const int ng = w & 3;          // 0..3 -> n-tiles ng*4..ng*4+3
    const int grp = lane >> 2;     // 0..7
    const int thr = lane & 3;      // 0..3
    const int ee0 = mt * 16 + grp, ee1 = ee0 + 8;
    const int ntiles = (N_EDGES + NE_TILE - 1) / NE_TILE;

    for (int tile = blockIdx.x; tile < ntiles; tile += gridDim.x) {
        const int e0 = tile * NE_TILE;
        if (t < NE_TILE) {
            wsum_s[t] = 0.f;
            int sidx = e0 + t;
            int r = -1, c = 0, pe = 0;
            if (sidx < N_EDGES) { r = g_srow[sidx]; c = g_scol[sidx]; pe = g_sperm[sidx]; }
            row_s[t] = r; col_s[t] = c;
            float4 a = make_float4(0.f, 0.f, 0.f, 0.f);
            if (r >= 0) a = *(const float4*)&eattr[pe * 4];
            int rr = r < 0 ? 0 : r;
            float rx = g_pos[rr * 3 + 0] - g_pos[c * 3 + 0];
            float ry = g_pos[rr * 3 + 1] - g_pos[c * 3 + 1];
            float rz = g_pos[rr * 3 + 2] - g_pos[c * 3 + 2];
            rel_s[t * 3 + 0] = rx; rel_s[t * 3 + 1] = ry; rel_s[t * 3 + 2] = rz;
            d2_s[t] = rx * rx + ry * ry + rz * rz;
            ea_s[t * 4 + 0] = a.x; ea_s[t * 4 + 1] = a.y;
            ea_s[t * 4 + 2] = a.z; ea_s[t * 4 + 3] = a.w;
        }
        __syncthreads();

        // Phase A: hidden -> (hi,lo) fragments, j-pairs with float2 loads
#pragma unroll
        for (int rep = 0; rep < 8; rep++) {
            int idx = t + rep * 1024;
            int e = idx >> 6, jp = idx & 63;
            int j0 = jp * 2;
            int r = row_s[e], c = col_s[e];
            int rr = r < 0 ? 0 : r;
            float2 p1 = *(const float2*)&g_P1[rr * H + j0];
            float2 p2 = *(const float2*)&g_P2[c * H + j0];
            float dd = d2_s[e];
            float v0 = p1.x + p2.x + dd * wd2_s[j0];
            float v1 = p1.y + p2.y + dd * wd2_s[j0 + 1];
#pragma unroll
            for (int a2 = 0; a2 < 4; a2++) {
                float eav = ea_s[e * 4 + a2];
                v0 += eav * wea_s[a2 * H + j0];
                v1 += eav * wea_s[a2 * H + j0 + 1];
            }
            unsigned lo;
            unsigned hi = split2(silu_f(v0), silu_f(v1), lo);
            int fi = fragAb(e, j0, 8);
            actH[fi] = hi;
            actL[fi] = lo;
        }
        __syncthreads();

        // Phase B: m = silu(hid @ W2 + b2), results in regs
        float cB[4][4];
#pragma unroll
        for (int q = 0; q < 4; q++) {
            int jc = (ng * 4 + q) * 8 + 2 * thr;
            cB[q][0] = b2_s[jc]; cB[q][1] = b2_s[jc + 1];
            cB[q][2] = cB[q][0]; cB[q][3] = cB[q][1];
        }
#pragma unroll
        for (int kt = 0; kt < 8; kt++) {
            int aoff = (((mt * 8 + kt) << 5) + lane) << 2;
            uint4 ah = *(const uint4*)&actH[aoff];
            uint4 al = *(const uint4*)&actL[aoff];
#pragma unroll
            for (int q = 0; q < 4; q++) {
                int bi = ((((ng * 4 + q) * 8 + kt) << 5) + lane) << 1;
                uint2 bh = *(const uint2*)&w2F[bi];
                uint2 bl = *(const uint2*)&w2F[8192 + bi];
                mma3(cB[q], ah, al, bh, bl);
            }
        }
        __syncthreads();   // all reads of hid complete
        // writeback m into actH/actL (in place)
#pragma unroll
        for (int q = 0; q < 4; q++) {
            int jq = (ng * 4 + q) * 8 + 2 * thr;
            unsigned lo0, lo1;
            unsigned hi0 = split2(silu_f(cB[q][0]), silu_f(cB[q][1]), lo0);
            unsigned hi1 = split2(silu_f(cB[q][2]), silu_f(cB[q][3]), lo1);
            int f0 = fragAb(ee0, jq, 8);
            int f1 = fragAb(ee1, jq, 8);
            actH[f0] = hi0; actL[f0] = lo0;
            actH[f1] = hi1; actL[f1] = lo1;
        }
        __syncthreads();

        // Phase C: w = silu(m@C1 + cb1) @ C2
        {
            float cC[4][4];
#pragma unroll
            for (int q = 0; q < 4; q++) {
                int jc = (ng * 4 + q) * 8 + 2 * thr;
                cC[q][0] = cb1_s[jc]; cC[q][1] = cb1_s[jc + 1];
                cC[q][2] = cC[q][0]; cC[q][3] = cC[q][1];
            }
#pragma unroll
            for (int kt = 0; kt < 8; kt++) {
                int aoff = (((mt * 8 + kt) << 5) + lane) << 2;
                uint4 ah = *(const uint4*)&actH[aoff];
                uint4 al = *(const uint4*)&actL[aoff];
#pragma unroll
                for (int q = 0; q < 4; q++) {
                    int bi = ((((ng * 4 + q) * 8 + kt) << 5) + lane) << 1;
                    uint2 bh = *(const uint2*)&c1F[bi];
                    uint2 bl = *(const uint2*)&c1F[8192 + bi];
                    mma3(cC[q], ah, al, bh, bl);
                }
            }
            float sl = 0.f, sh = 0.f;
#pragma unroll
            for (int q = 0; q < 4; q++) {
                int jq = (ng * 4 + q) * 8 + 2 * thr;
                sl += silu_f(cC[q][0]) * c2_s[jq] + silu_f(cC[q][1]) * c2_s[jq + 1];
                sh += silu_f(cC[q][2]) * c2_s[jq] + silu_f(cC[q][3]) * c2_s[jq + 1];
            }
            sl += __shfl_xor_sync(0xffffffffu, sl, 1);
            sl += __shfl_xor_sync(0xffffffffu, sl, 2);
            sh += __shfl_xor_sync(0xffffffffu, sh, 1);
            sh += __shfl_xor_sync(0xffffffffu, sh, 2);
            if (thr == 0) {
                atomicAdd(&wsum_s[ee0], sl);
                atomicAdd(&wsum_s[ee1], sh);
            }
        }
        __syncthreads();

        // Phase D: segment-scan scatter of m (= hi+lo); posdelta from wsum
        {
            const int j = t & 127;
            const int q = t >> 7;          // 0..7
            const int ebeg = q * 16;
            const unsigned short* aHs = (const unsigned short*)actH;
            const unsigned short* aLs = (const unsigned short*)actL;
            const int jbase = j & 126, jsub = j & 1;
            float acc = 0.f;
            int cur = row_s[ebeg];
#pragma unroll
            for (int i = 0; i < 16; i++) {
                int e = ebeg + i;
                int r = row_s[e];
                int fi = fragAb(e, jbase, 8) * 2 + jsub;
                float v = __bfloat162float(__ushort_as_bfloat16(aHs[fi]))
                        + __bfloat162float(__ushort_as_bfloat16(aLs[fi]));
                if (r != cur) {
                    if (cur >= 0) atomicAdd(&g_agg[cur * H + j], acc);
                    acc = 0.f;
                    cur = r;
                }
                acc += v;
            }
            if (cur >= 0) atomicAdd(&g_agg[cur * H + j], acc);
        }
        if (t < 384) {
            int e = t / 3, k = t % 3;
            int r = row_s[e];
            if (r >= 0)
                atomicAdd(&g_posdelta[r * 3 + k], rel_s[e * 3 + k] * wsum_s[e]);
        }
        __syncthreads();
    }
}

// ---------------- pos update ----------------
__global__ void k_pos() {
    const int idx = blockIdx.x * blockDim.x + threadIdx.x;
    if (idx >= N_NODES * 3) return;
    const int i = idx / 3;
    float d = fmaxf(g_deg[i], 1.0f);
    g_pos[idx] += g_posdelta[idx] / d;
}

// ---------------- node1: bf16 3-MMA, two K-half passes ----------------
__global__ __launch_bounds__(1024, 1) void k_node1(int l, const float* __restrict__ b) {
    extern __shared__ float sm[];
    unsigned* wF = (unsigned*)sm;   // 16384 (one K-half: hi 8192 | lo 8192)
    unsigned* aH = wF + 16384;      // 4096
    unsigned* aL = aH + 4096;       // 4096
    const int t = threadIdx.x;
    const int n0 = blockIdx.x * 64;
    const int wid = t >> 5, lane = t & 31;
    const int mt = wid >> 3, nt0 = (wid & 7) * 2;
    const int grp = lane >> 2, thr = lane & 3;
    float c0[4] = {0.f, 0.f, 0.f, 0.f}, c1[4] = {0.f, 0.f, 0.f, 0.f};

    for (int halfk = 0; halfk < 2; halfk++) {
        __syncthreads();
        {
            const uint4* s = (const uint4*)(g_pk_n1 + l * 32768 + halfk * 16384);
            uint4* d = (uint4*)wF;
            for (int i = t; i < 4096; i += 1024) d[i] = s[i];
        }
        const float* src = halfk ? g_agg : g_h;
        for (int i = t; i < 4096; i += 1024) {
            int n = i >> 6, jp = i & 63;
            int j0 = jp * 2;
            int gi = n0 + n;
            float2 v = make_float2(0.f, 0.f);
            if (gi < N_NODES) v = *(const float2*)&src[gi * H + j0];
            unsigned lo;
            unsigned hi = split2(v.x, v.y, lo);
            int fi = fragAb(n, j0, 8);
            aH[fi] = hi;
            aL[fi] = lo;
        }
        __syncthreads();
#pragma unroll
        for (int kt = 0; kt < 8; kt++) {
            int aoff = (((mt * 8 + kt) << 5) + lane) << 2;
            uint4 ah = *(const uint4*)&aH[aoff];
            uint4 al = *(const uint4*)&aL[aoff];
            int bi0 = (((nt0 * 8 + kt) << 5) + lane) << 1;
            int bi1 = ((((nt0 + 1) * 8 + kt) << 5) + lane) << 1;
            uint2 bh0 = *(const uint2*)&wF[bi0];
            uint2 bl0 = *(const uint2*)&wF[8192 + bi0];
            uint2 bh1 = *(const uint2*)&wF[bi1];
            uint2 bl1 = *(const uint2*)&wF[8192 + bi1];
            mma3(c0, ah, al, bh0, bl0);
            mma3(c1, ah, al, bh1, bl1);
        }
    }
    const int ee0 = mt * 16 + grp, ee1 = ee0 + 8;
    const int g0 = n0 + ee0, g1 = n0 + ee1;
    const int j00 = nt0 * 8 + 2 * thr, j10 = (nt0 + 1) * 8 + 2 * thr;
    float b00 = __ldg(&b[j00]), b01 = __ldg(&b[j00 + 1]);
    float b10 = __ldg(&b[j10]), b11 = __ldg(&b[j10 + 1]);
    if (g0 < N_NODES) {
        *(float2*)&g_U[g0 * H + j00] = make_float2(silu_f(c0[0] + b00), silu_f(c0[1] + b01));
        *(float2*)&g_U[g0 * H + j10] = make_float2(silu_f(c1[0] + b10), silu_f(c1[1] + b11));
    }
    if (g1 < N_NODES) {
        *(float2*)&g_U[g1 * H + j00] = make_float2(silu_f(c0[2] + b00), silu_f(c0[3] + b01));
        *(float2*)&g_U[g1 * H + j10] = make_float2(silu_f(c1[2] + b10), silu_f(c1[3] + b11));
    }
}

// ---------------- node2: bf16 3-MMA ----------------
__global__ __launch_bounds__(1024, 1) void k_node2(int l, const float* __restrict__ b) {
    extern __shared__ float sm[];
    unsigned* wF = (unsigned*)sm;   // 16384 (hi 8192 | lo 8192)
    unsigned* aH = wF + 16384;      // 4096
    unsigned* aL = aH + 4096;       // 4096
    const int t = threadIdx.x;
    const int n0 = blockIdx.x * 64;
    {
        const uint4* s = (const uint4*)(g_pk_n2 + l * 16384);
        uint4* d = (uint4*)wF;
        for (int i = t; i < 4096; i += 1024) d[i] = s[i];
    }
    for (int i = t; i < 4096; i += 1024) {
        int n = i >> 6, jp = i & 63;
        int j0 = jp * 2;
        int gi = n0 + n;
        float2 v = make_float2(0.f, 0.f);
        if (gi < N_NODES) v = *(const float2*)&g_U[gi * H + j0];
        unsigned lo;
        unsigned hi = split2(v.x, v.y, lo);
        int fi = fragAb(n, j0, 8);
        aH[fi] = hi;
        aL[fi] = lo;
    }
    __syncthreads();

    const int wid = t >> 5, lane = t & 31;
    const int mt = wid >> 3, nt0 = (wid & 7) * 2;
    const int grp = lane >> 2, thr = lane & 3;
    float c0[4] = {0.f, 0.f, 0.f, 0.f}, c1[4] = {0.f, 0.f, 0.f, 0.f};
#pragma unroll
    for (int kt = 0; kt < 8; kt++) {
        int aoff = (((mt * 8 + kt) << 5) + lane) << 2;
        uint4 ah = *(const uint4*)&aH[aoff];
        uint4 al = *(const uint4*)&aL[aoff];
        int bi0 = (((nt0 * 8 + kt) << 5) + lane) << 1;
        int bi1 = ((((nt0 + 1) * 8 + kt) << 5) + lane) << 1;
        uint2 bh0 = *(const uint2*)&wF[bi0];
        uint2 bl0 = *(const uint2*)&wF[8192 + bi0];
        uint2 bh1 = *(const uint2*)&wF[bi1];
        uint2 bl1 = *(const uint2*)&wF[8192 + bi1];
        mma3(c0, ah, al, bh0, bl0);
        mma3(c1, ah, al, bh1, bl1);
    }
    const int ee0 = mt * 16 + grp, ee1 = ee0 + 8;
    const int g0 = n0 + ee0, g1 = n0 + ee1;
    const int j00 = nt0 * 8 + 2 * thr, j10 = (nt0 + 1) * 8 + 2 * thr;
    float b00 = __ldg(&b[j00]), b01 = __ldg(&b[j00 + 1]);
    float b10 = __ldg(&b[j10]), b11 = __ldg(&b[j10 + 1]);
    if (g0 < N_NODES) {
        float2 h0 = *(float2*)&g_h[g0 * H + j00];
        h0.x += c0[0] + b00; h0.y += c0[1] + b01;
        *(float2*)&g_h[g0 * H + j00] = h0;
        float2 h1 = *(float2*)&g_h[g0 * H + j10];
        h1.x += c1[0] + b10; h1.y += c1[1] + b11;
        *(float2*)&g_h[g0 * H + j10] = h1;
    }
    if (g1 < N_NODES) {
        float2 h0 = *(float2*)&g_h[g1 * H + j00];
        h0.x += c0[2] + b00; h0.y += c0[3] + b01;
        *(float2*)&g_h[g1 * H + j00] = h0;
        float2 h1 = *(float2*)&g_h[g1 * H + j10];
        h1.x += c1[2] + b10; h1.y += c1[3] + b11;
        *(float2*)&g_h[g1 * H + j10] = h1;
    }
}

// ---------------- pooling ----------------
__global__ __launch_bounds__(512) void k_pool() {
    __shared__ float red[512];
    const int g = blockIdx.x, t = threadIdx.x;
    const int j = t & 127, w = t >> 7;
    float s = 0.f;
    for (int n = w; n < NPG; n += 4) s += g_h[(g * NPG + n) * H + j];
    red[t] = s;
    __syncthreads();
    if (w == 0) {
        float tot = red[j] + red[128 + j] + red[256 + j] + red[384 + j];
        g_gfeat[g * 256 + j] = tot;
        g_gfeat[g * 256 + 128 + j] = tot * (1.f / (float)NPG);
    }
}

// ---------------- readout head ----------------
__global__ void k_head(const float* __restrict__ h1_w, const float* __restrict__ h1_b,
                       const float* __restrict__ h2_w, const float* __restrict__ h2_b,
                       const float* __restrict__ h3_w, const float* __restrict__ h3_b,
                       float* __restrict__ out) {
    __shared__ float gf[256], z1[128], z2[64];
    const int g = blockIdx.x, t = threadIdx.x;
    gf[t] = g_gfeat[g * 256 + t];
    gf[128 + t] = g_gfeat[g * 256 + 128 + t];
    __syncthreads();
    float a = h1_b[t];
    for (int k = 0; k < 256; k++) a += gf[k] * h1_w[k * 128 + t];
    z1[t] = fmaxf(a, 0.f);
    __syncthreads();
    if (t < 64) {
        float a2 = h2_b[t];
        for (int k = 0; k < 128; k++) a2 += z1[k] * h2_w[k * 64 + t];
        z2[t] = fmaxf(a2, 0.f);
    }
    __syncthreads();
    if (t == 0) {
        float a3 = h3_b[0];
        for (int k = 0; k < 64; k++) a3 += z2[k] * h3_w[k];
        out[g] = a3;
    }
}

// ---------------- launch ----------------
extern "C" void kernel_launch(void* const* d_in, const int* in_sizes, int n_in,
                              void* d_out, int out_size) {
    const float* x     = (const float*)d_in[0];
    const float* pos   = (const float*)d_in[1];
    const int*   ei    = (const int*)d_in[2];
    const float* eattr = (const float*)d_in[3];
    const float* Wp    = (const float*)d_in[6];
    const float* bp    = (const float*)d_in[7];
    const float* Wl    = (const float*)d_in[8];
    const float* bl    = (const float*)d_in[9];
    const float* gamma = (const float*)d_in[10];
    const float* beta  = (const float*)d_in[11];
    const float* e_w1  = (const float*)d_in[12];
    const float* e_b1  = (const float*)d_in[13];
    const float* e_w2  = (const float*)d_in[14];
    const float* e_b2  = (const float*)d_in[15];
    const float* c_w1  = (const float*)d_in[16];
    const float* c_b1  = (const float*)d_in[17];
    const float* c_w2  = (const float*)d_in[18];
    const float* n_w1  = (const float*)d_in[19];
    const float* n_b1  = (const float*)d_in[20];
    const float* n_w2  = (const float*)d_in[21];
    const float* n_b2  = (const float*)d_in[22];
    const float* h1_w  = (const float*)d_in[23];
    const float* h1_b  = (const float*)d_in[24];
    const float* h2_w  = (const float*)d_in[25];
    const float* h2_b  = (const float*)d_in[26];
    const float* h3_w  = (const float*)d_in[27];
    const float* h3_b  = (const float*)d_in[28];
    float* out = (float*)d_out;

    const int PROJ_SMEM = (32768 + 4096 + 4096) * 4;
    const int EDGE_SMEM = (16384 * 2 + 8192 * 2 + 128 * 4 + 512
                           + 128 + 384 + 512 + 128 + 128 + 128) * 4;
    const int N1_SMEM = (16384 + 4096 + 4096) * 4;
    const int N2_SMEM = (16384 + 4096 + 4096) * 4;
    cudaFuncSetAttribute(k_proj,  cudaFuncAttributeMaxDynamicSharedMemorySize, PROJ_SMEM);
    cudaFuncSetAttribute(k_edge,  cudaFuncAttributeMaxDynamicSharedMemorySize, EDGE_SMEM);
    cudaFuncSetAttribute(k_node1, cudaFuncAttributeMaxDynamicSharedMemorySize, N1_SMEM);
    cudaFuncSetAttribute(k_node2, cudaFuncAttributeMaxDynamicSharedMemorySize, N2_SMEM);

    const int nblocks64 = (N_NODES + 63) / 64;   // 782

    k_embed<<<N_NODES, 128>>>(x, pos, Wp, bp, Wl, bl);
    k_pack<<<(NLAYERS * PACK_PER_LAYER + 255) / 256, 256>>>(e_w1, e_w2, c_w1, n_w1, n_w2);
    k_stats_deg<<<256 + DEG_BLOCKS, 512>>>(ei);
    k_bnapply_scan<<<BNA_BLOCKS + 1, 512>>>(gamma, beta);

    for (int l = 0; l < NLAYERS; l++) {
        k_proj<<<nblocks64, 1024, PROJ_SMEM>>>(l, e_b1 + l * H);
        if (l == 0) k_perm<<<(N_EDGES + 511) / 512, 512>>>(ei);
        k_edge<<<148, 1024, EDGE_SMEM>>>(eattr, l, e_b2 + l * H, c_b1 + l * H,
                                         c_w2 + l * H, e_w1 + l * 261 * H);
        k_node1<<<nblocks64, 1024, N1_SMEM>>>(l, n_b1 + l * H);
        k_node2<<<nblocks64, 1024, N2_SMEM>>>(l, n_b2 + l * H);
        k_pos<<<(N_NODES * 3 + 511) / 512, 512>>>();
    }

    k_pool<<<G_GRAPHS, 512>>>();
    k_head<<<G_GRAPHS, 128>>>(h1_w, h1_b, h2_w, h2_b, h3_w, h3_b, out);
}

// round 11
// speedup vs baseline: 1.6606x; 1.0347x over previous
#include <cuda_runtime.h>
#include <cuda_bf16.h>

#define N_NODES 50000
#define N_EDGES 500000
#define H 128
#define G_GRAPHS 100
#define NPG 500
#define NPROT 400
#define PN 35
#define LN 11
#define NLAYERS 4
#define EPS 1e-5f
#define NE_TILE 128

// ---------------- scratch ----------------
__device__ float g_h[N_NODES * H];
__device__ float g_P1[N_NODES * H];
__device__ float g_P2[N_NODES * H];
__device__ float g_agg[N_NODES * H];
__device__ float g_pos[N_NODES * 3];
__device__ float g_posdelta[N_NODES * 3];
__device__ float g_deg[N_NODES];
__device__ float g_bnstats[2 * H];
__device__ int g_rowcur[N_NODES];
__device__ int g_srow[N_EDGES];
__device__ int g_scol[N_EDGES];
__device__ int g_sperm[N_EDGES];
// pre-packed bf16 hi/lo weight fragments
__device__ unsigned g_pk_proj[NLAYERS * 32768];  // hi 16384 | lo 16384
__device__ unsigned g_pk_w2[NLAYERS * 16384];    // hi 8192 | lo 8192
__device__ unsigned g_pk_c1[NLAYERS * 16384];
__device__ unsigned g_pk_n1[NLAYERS * 32768];    // [half0: hi|lo][half1: hi|lo]
__device__ unsigned g_pk_n2[NLAYERS * 16384];

__device__ __forceinline__ float silu_f(float x) {
    return x / (1.f + __expf(-x));
}

// ---- bf16 m16n8k16 mma ----
__device__ __forceinline__ void mma_bf16(float* c, const uint4& a, const uint2& b) {
    asm volatile(
        "mma.sync.aligned.m16n8k16.row.col.f32.bf16.bf16.f32 "
        "{%0,%1,%2,%3}, {%4,%5,%6,%7}, {%8,%9}, {%0,%1,%2,%3};"
        : "+f"(c[0]), "+f"(c[1]), "+f"(c[2]), "+f"(c[3])
        : "r"(a.x), "r"(a.y), "r"(a.z), "r"(a.w), "r"(b.x), "r"(b.y));
}
__device__ __forceinline__ unsigned split2(float v0, float v1, unsigned& lo) {
    __nv_bfloat16 h0 = __float2bfloat16(v0);
    __nv_bfloat16 h1 = __float2bfloat16(v1);
    __nv_bfloat16 l0 = __float2bfloat16(v0 - __bfloat162float(h0));
    __nv_bfloat16 l1 = __float2bfloat16(v1 - __bfloat162float(h1));
    lo = (unsigned)__bfloat16_as_ushort(l0) | ((unsigned)__bfloat16_as_ushort(l1) << 16);
    return (unsigned)__bfloat16_as_ushort(h0) | ((unsigned)__bfloat16_as_ushort(h1) << 16);
}
__device__ __forceinline__ void mma3(float* c, const uint4& ah, const uint4& al,
                                     const uint2& bh, const uint2& bl) {
    mma_bf16(c, ah, bh);
    mma_bf16(c, ah, bl);
    mma_bf16(c, al, bh);
}
__device__ __forceinline__ int fragAb(int e, int j0, int KT) {
    int jin = j0 & 15;
    int tid = (jin & 7) >> 1;
    int reg = ((jin >> 3) << 1) | ((e >> 3) & 1);
    int lane = ((e & 7) << 2) | tid;
    return (((e >> 4) * KT + (j0 >> 4)) << 7) + (lane << 2) + reg;
}
__device__ __forceinline__ float bfsum(unsigned hi, unsigned lo) {
    return __bfloat162float(__ushort_as_bfloat16((unsigned short)(hi & 0xffffu)))
         + __bfloat162float(__ushort_as_bfloat16((unsigned short)(lo & 0xffffu)));
}

// ---------------- K1: embed ----------------
__global__ void k_embed(const float* __restrict__ x, const float* __restrict__ pos_in,
                        const float* __restrict__ Wp, const float* __restrict__ bp,
                        const float* __restrict__ Wl, const float* __restrict__ bl) {
    __shared__ float xs[PN];
    const int i = blockIdx.x;
    const int t = threadIdx.x;
    if (t < PN) xs[t] = x[i * PN + t];
    if (t == 0) g_deg[i] = 0.f;
    if (t < 3) g_pos[i * 3 + t] = pos_in[i * 3 + t];
    if (i == 0 && t < H) { g_bnstats[t] = 0.f; g_bnstats[H + t] = 0.f; }
    __syncthreads();
    const bool isp = (i % NPG) < NPROT;
    const float* W = isp ? Wp : Wl;
    const float* b = isp ? bp : bl;
    const int nk = isp ? PN : LN;
    float acc = b[t];
    for (int k = 0; k < nk; k++) acc += xs[k] * W[k * H + t];
    g_h[i * H + t] = acc;
}

// ---------------- K2: prep = bnstats + deg + weight pack ----------------
#define DEG_BLOCKS ((N_EDGES + 511) / 512)
#define PACK_PER_LAYER (16384 + 8192 + 8192 + 16384 + 8192)  // 57344
#define PACK_ITEMS (NLAYERS * PACK_PER_LAYER)
#define PACK_BLOCKS ((PACK_ITEMS + 511) / 512)
__global__ __launch_bounds__(512) void k_prep(const int* __restrict__ ei,
                                              const float* __restrict__ ew1,
                                              const float* __restrict__ ew2,
                                              const float* __restrict__ cw1,
                                              const float* __restrict__ nw1,
                                              const float* __restrict__ nw2) {
    const int t = threadIdx.x;
    if (blockIdx.x < 256) {
        const int j = t & 127;
        const int g2 = t >> 7;
        float s = 0.f, s2 = 0.f;
        for (int i = blockIdx.x * 4 + g2; i < N_NODES; i += 1024) {
            float v = g_h[i * H + j];
            s += v; s2 += v * v;
        }
        atomicAdd(&g_bnstats[j], s);
        atomicAdd(&g_bnstats[H + j], s2);
        return;
    }
    if (blockIdx.x < 256 + DEG_BLOCKS) {
        const int e = (blockIdx.x - 256) * 512 + t;
        if (e < N_EDGES) atomicAdd(&g_deg[ei[e]], 1.0f);
        return;
    }
    int idx = (blockIdx.x - 256 - DEG_BLOCKS) * 512 + t;
    if (idx >= PACK_ITEMS) return;
    int l = idx / PACK_PER_LAYER;
    int o = idx - l * PACK_PER_LAYER;
    float w0, w1;
    unsigned* hip;
    unsigned* lop;
    if (o < 16384) {            // proj
        int i = o;
        int rb = i & 1, lane = (i >> 1) & 31, kt = (i >> 6) & 7, nt = i >> 9;
        int tid = lane & 3, g = lane >> 2;
        int k0 = kt * 16 + tid * 2 + rb * 8;
        int jj = nt * 8 + g;
        const float* W = ew1 + l * 261 * H;
        int srcrow = (jj < 128) ? k0 : (128 + k0);
        int col = jj & 127;
        w0 = W[srcrow * H + col];
        w1 = W[(srcrow + 1) * H + col];
        hip = g_pk_proj + l * 32768 + i;
        lop = hip + 16384;
    } else if (o < 24576) {     // w2
        int i = o - 16384;
        int rb = i & 1, lane = (i >> 1) & 31, kt = (i >> 6) & 7, nt = i >> 9;
        int tid = lane & 3, g = lane >> 2;
        int k0 = kt * 16 + tid * 2 + rb * 8;
        int n = nt * 8 + g;
        const float* W = ew2 + l * H * H;
        w0 = W[k0 * H + n];
        w1 = W[(k0 + 1) * H + n];
        hip = g_pk_w2 + l * 16384 + i;
        lop = hip + 8192;
    } else if (o < 32768) {     // c1
        int i = o - 24576;
        int rb = i & 1, lane = (i >> 1) & 31, kt = (i >> 6) & 7, nt = i >> 9;
        int tid = lane & 3, g = lane >> 2;
        int k0 = kt * 16 + tid * 2 + rb * 8;
        int n = nt * 8 + g;
        const float* W = cw1 + l * H * H;
        w0 = W[k0 * H + n];
        w1 = W[(k0 + 1) * H + n];
        hip = g_pk_c1 + l * 16384 + i;
        lop = hip + 8192;
    } else if (o < 49152) {     // n1
        int i2 = o - 32768;
        int hk = i2 >> 13;
        int i = i2 & 8191;
        int rb = i & 1, lane = (i >> 1) & 31, kt = (i >> 6) & 7, nt = i >> 9;
        int tid = lane & 3, g = lane >> 2;
        int k0 = hk * 128 + kt * 16 + tid * 2 + rb * 8;
        int n = nt * 8 + g;
        const float* W = nw1 + l * 2 * H * H;
        w0 = W[k0 * H + n];
        w1 = W[(k0 + 1) * H + n];
        hip = g_pk_n1 + l * 32768 + hk * 16384 + i;
        lop = hip + 8192;
    } else {                    // n2
        int i = o - 49152;
        int rb = i & 1, lane = (i >> 1) & 31, kt = (i >> 6) & 7, nt = i >> 9;
        int tid = lane & 3, g = lane >> 2;
        int k0 = kt * 16 + tid * 2 + rb * 8;
        int n = nt * 8 + g;
        const float* W = nw2 + l * H * H;
        w0 = W[k0 * H + n];
        w1 = W[(k0 + 1) * H + n];
        hip = g_pk_n2 + l * 16384 + i;
        lop = hip + 8192;
    }
    unsigned lo;
    unsigned hi = split2(w0, w1, lo);
    *hip = hi;
    *lop = lo;
}

// ---------------- K3: bnapply + degree scan ----------------
#define BNA_BLOCKS ((N_NODES * H) / 512)
__global__ __launch_bounds__(512) void k_bnapply_scan(const float* __restrict__ gamma,
                                                      const float* __restrict__ beta) {
    const int t = threadIdx.x;
    if (blockIdx.x < BNA_BLOCKS) {
        const int idx = blockIdx.x * 512 + t;
        const int j = idx & (H - 1);
        const float inv_n = 1.f / (float)N_NODES;
        float mu = g_bnstats[j] * inv_n;
        float var = g_bnstats[H + j] * inv_n - mu * mu;
        g_h[idx] = (g_h[idx] - mu) * rsqrtf(var + EPS) * gamma[j] + beta[j];
    } else {
        __shared__ int sums[512];
        const int chunk = 98;
        int base = t * chunk;
        int lim = min(base + chunk, N_NODES);
        int s = 0;
        for (int i = base; i < lim; i++) s += (int)g_deg[i];
        sums[t] = s;
        __syncthreads();
        for (int off = 1; off < 512; off <<= 1) {
            int v = (t >= off) ? sums[t - off] : 0;
            __syncthreads();
            sums[t] += v;
            __syncthreads();
        }
        int run = (t == 0) ? 0 : sums[t - 1];
        for (int i = base; i < lim; i++) {
            g_rowcur[i] = run;
            run += (int)g_deg[i];
        }
    }
}

// ---------------- counting-sort scatter ----------------
__global__ __launch_bounds__(512) void k_perm(const int* __restrict__ ei) {
    const int e = blockIdx.x * 512 + threadIdx.x;
    if (e >= N_EDGES) return;
    int r = ei[e];
    int p = atomicAdd(&g_rowcur[r], 1);
    g_srow[p] = r;
    g_scol[p] = ei[N_EDGES + e];
    g_sperm[p] = e;
}

// ---------------- proj: bf16 3-MMA ----------------
__global__ __launch_bounds__(1024, 1) void k_proj(int l, const float* __restrict__ b1) {
    extern __shared__ float sm[];
    unsigned* wF = (unsigned*)sm;       // 32768
    unsigned* aH = wF + 32768;          // 4096
    unsigned* aL = aH + 4096;           // 4096
    const int t = threadIdx.x;
    const int n0 = blockIdx.x * 64;

    {
        const uint4* s = (const uint4*)(g_pk_proj + l * 32768);
        uint4* d = (uint4*)wF;
        for (int i = t; i < 8192; i += 1024) d[i] = s[i];
    }
    for (int i = t; i < 4096; i += 1024) {
        int n = i >> 6, jp = i & 63;
        int j0 = jp * 2;
        int gi = n0 + n;
        float2 v = make_float2(0.f, 0.f);
        if (gi < N_NODES) v = *(const float2*)&g_h[gi * H + j0];
        unsigned lo;
        unsigned hi = split2(v.x, v.y, lo);
        int fi = fragAb(n, j0, 8);
        aH[fi] = hi;
        aL[fi] = lo;
    }
    for (int i = t; i < 8192; i += 1024) {
        int gi = n0 + (i >> 7);
        if (gi < N_NODES) g_agg[gi * H + (i & 127)] = 0.f;
    }
    if (t < 192) {
        int gi = n0 + t / 3;
        if (gi < N_NODES) g_posdelta[gi * 3 + t % 3] = 0.f;
    }
    __syncthreads();

    const int wid = t >> 5, lane = t & 31;
    const int mt = wid >> 3;
    const int ng = wid & 7;
    const int grp = lane >> 2, thr = lane & 3;
    float c[4][4];
#pragma unroll
    for (int q = 0; q < 4; q++)
#pragma unroll
        for (int r = 0; r < 4; r++) c[q][r] = 0.f;

#pragma unroll
    for (int kt = 0; kt < 8; kt++) {
        int aoff = (((mt * 8 + kt) << 5) + lane) << 2;
        uint4 ah = *(const uint4*)&aH[aoff];
        uint4 al = *(const uint4*)&aL[aoff];
#pragma unroll
        for (int q = 0; q < 4; q++) {
            int nt = ng * 4 + q;
            int bi = (((nt * 8 + kt) << 5) + lane) << 1;
            uint2 bh = *(const uint2*)&wF[bi];
            uint2 bl = *(const uint2*)&wF[16384 + bi];
            mma3(c[q], ah, al, bh, bl);
        }
    }

    const int ee0 = mt * 16 + grp, ee1 = ee0 + 8;
    const int g0 = n0 + ee0, g1 = n0 + ee1;
#pragma unroll
    for (int q = 0; q < 4; q++) {
        int nt = ng * 4 + q;
        int jj0 = nt * 8 + 2 * thr;
        int half = jj0 >> 7;
        int j = jj0 & 127;
        float* outp = half ? g_P2 : g_P1;
        float bb0 = half ? 0.f : __ldg(&b1[j]);
        float bb1 = half ? 0.f : __ldg(&b1[j + 1]);
        if (g0 < N_NODES)
            *(float2*)&outp[g0 * H + j] = make_float2(c[q][0] + bb0, c[q][1] + bb1);
        if (g1 < N_NODES)
            *(float2*)&outp[g1 * H + j] = make_float2(c[q][2] + bb0, c[q][3] + bb1);
    }
}

// ---------------- fused edge kernel ----------------
__global__ __launch_bounds__(1024, 1) void k_edge(
    const float* __restrict__ eattr, int l,
    const float* __restrict__ b2, const float* __restrict__ cb1,
    const float* __restrict__ cw2, const float* __restrict__ ew1) {
    extern __shared__ float sm[];
    unsigned* w2F = (unsigned*)sm;       // 16384
    unsigned* c1F = w2F + 16384;         // 16384
    unsigned* actH = c1F + 16384;        // 8192
    unsigned* actL = actH + 8192;        // 8192
    float* b2_s  = (float*)(actL + 8192);  // 128
    float* cb1_s = b2_s + 128;           // 128
    float* c2_s  = cb1_s + 128;          // 128
    float* wd2_s = c2_s + 128;           // 128
    float* wea_s = wd2_s + 128;          // 512
    float* d2_s  = wea_s + 512;          // 128
    float* rel_s = d2_s + 128;           // 384
    float* ea_s  = rel_s + 384;          // 512
    float* wsum_s = ea_s + 512;          // 128
    int* row_s = (int*)(wsum_s + 128);   // 128
    int* col_s = row_s + 128;            // 128

    const int t = threadIdx.x;
    {
        const uint4* s2 = (const uint4*)(g_pk_w2 + l * 16384);
        const uint4* s1 = (const uint4*)(g_pk_c1 + l * 16384);
        uint4* d2 = (uint4*)w2F;
        uint4* d1 = (uint4*)c1F;
        for (int i = t; i < 4096; i += 1024) { d2[i] = s2[i]; d1[i] = s1[i]; }
    }
    if (t < 128) {
        b2_s[t] = b2[t]; cb1_s[t] = cb1[t]; c2_s[t] = cw2[t];
        wd2_s[t] = ew1[256 * H + t];
    }
    if (t >= 128 && t < 640) wea_s[t - 128] = ew1[257 * H + (t - 128)];
    __syncthreads();

    const int w = t >> 5;
    const int lane = t & 31;
    const int mt = w >> 2;         // 0..7
    const int ng = w & 3;          // 0..3
    const int grp = lane >> 2;
    const int thr = lane & 3;
    const int ee0 = mt * 16 + grp, ee1 = ee0 + 8;
    const int ntiles = (N_EDGES + NE_TILE - 1) / NE_TILE;

    for (int tile = blockIdx.x; tile < ntiles; tile += gridDim.x) {
        const int e0 = tile * NE_TILE;
        if (t < NE_TILE) {
            wsum_s[t] = 0.f;
            int sidx = e0 + t;
            int r = -1, c = 0, pe = 0;
            if (sidx < N_EDGES) { r = g_srow[sidx]; c = g_scol[sidx]; pe = g_sperm[sidx]; }
            row_s[t] = r; col_s[t] = c;
            float4 a = make_float4(0.f, 0.f, 0.f, 0.f);
            if (r >= 0) a = *(const float4*)&eattr[pe * 4];
            int rr = r < 0 ? 0 : r;
            float rx = g_pos[rr * 3 + 0] - g_pos[c * 3 + 0];
            float ry = g_pos[rr * 3 + 1] - g_pos[c * 3 + 1];
            float rz = g_pos[rr * 3 + 2] - g_pos[c * 3 + 2];
            rel_s[t * 3 + 0] = rx; rel_s[t * 3 + 1] = ry; rel_s[t * 3 + 2] = rz;
            d2_s[t] = rx * rx + ry * ry + rz * rz;
            ea_s[t * 4 + 0] = a.x; ea_s[t * 4 + 1] = a.y;
            ea_s[t * 4 + 2] = a.z; ea_s[t * 4 + 3] = a.w;
        }
        __syncthreads();

        // Phase A: hidden -> (hi,lo) fragments, float4 gathers (4 cols per rep)
#pragma unroll
        for (int rep = 0; rep < 4; rep++) {
            int idx = t + rep * 1024;
            int e = idx >> 5, jq = idx & 31;
            int j0 = jq * 4;
            int r = row_s[e], c = col_s[e];
            int rr = r < 0 ? 0 : r;
            float4 p1 = *(const float4*)&g_P1[rr * H + j0];
            float4 p2 = *(const float4*)&g_P2[c * H + j0];
            float dd = d2_s[e];
            float v0 = p1.x + p2.x + dd * wd2_s[j0];
            float v1 = p1.y + p2.y + dd * wd2_s[j0 + 1];
            float v2 = p1.z + p2.z + dd * wd2_s[j0 + 2];
            float v3 = p1.w + p2.w + dd * wd2_s[j0 + 3];
#pragma unroll
            for (int a2 = 0; a2 < 4; a2++) {
                float eav = ea_s[e * 4 + a2];
                v0 += eav * wea_s[a2 * H + j0];
                v1 += eav * wea_s[a2 * H + j0 + 1];
                v2 += eav * wea_s[a2 * H + j0 + 2];
                v3 += eav * wea_s[a2 * H + j0 + 3];
            }
            unsigned lo;
            unsigned hi = split2(silu_f(v0), silu_f(v1), lo);
            int fi = fragAb(e, j0, 8);
            actH[fi] = hi; actL[fi] = lo;
            hi = split2(silu_f(v2), silu_f(v3), lo);
            fi = fragAb(e, j0 + 2, 8);
            actH[fi] = hi; actL[fi] = lo;
        }
        __syncthreads();

        // Phase B: m = silu(hid @ W2 + b2)
        float cB[4][4];
#pragma unroll
        for (int q = 0; q < 4; q++) {
            int jc = (ng * 4 + q) * 8 + 2 * thr;
            cB[q][0] = b2_s[jc]; cB[q][1] = b2_s[jc + 1];
            cB[q][2] = cB[q][0]; cB[q][3] = cB[q][1];
        }
#pragma unroll
        for (int kt = 0; kt < 8; kt++) {
            int aoff = (((mt * 8 + kt) << 5) + lane) << 2;
            uint4 ah = *(const uint4*)&actH[aoff];
            uint4 al = *(const uint4*)&actL[aoff];
#pragma unroll
            for (int q = 0; q < 4; q++) {
                int bi = ((((ng * 4 + q) * 8 + kt) << 5) + lane) << 1;
                uint2 bh = *(const uint2*)&w2F[bi];
                uint2 bl = *(const uint2*)&w2F[8192 + bi];
                mma3(cB[q], ah, al, bh, bl);
            }
        }
        __syncthreads();
#pragma unroll
        for (int q = 0; q < 4; q++) {
            int jq = (ng * 4 + q) * 8 + 2 * thr;
            unsigned lo0, lo1;
            unsigned hi0 = split2(silu_f(cB[q][0]), silu_f(cB[q][1]), lo0);
            unsigned hi1 = split2(silu_f(cB[q][2]), silu_f(cB[q][3]), lo1);
            int f0 = fragAb(ee0, jq, 8);
            int f1 = fragAb(ee1, jq, 8);
            actH[f0] = hi0; actL[f0] = lo0;
            actH[f1] = hi1; actL[f1] = lo1;
        }
        __syncthreads();

        // Phase C
        {
            float cC[4][4];
#pragma unroll
            for (int q = 0; q < 4; q++) {
                int jc = (ng * 4 + q) * 8 + 2 * thr;
                cC[q][0] = cb1_s[jc]; cC[q][1] = cb1_s[jc + 1];
                cC[q][2] = cC[q][0]; cC[q][3] = cC[q][1];
            }
#pragma unroll
            for (int kt = 0; kt < 8; kt++) {
                int aoff = (((mt * 8 + kt) << 5) + lane) << 2;
                uint4 ah = *(const uint4*)&actH[aoff];
                uint4 al = *(const uint4*)&actL[aoff];
#pragma unroll
                for (int q = 0; q < 4; q++) {
                    int bi = ((((ng * 4 + q) * 8 + kt) << 5) + lane) << 1;
                    uint2 bh = *(const uint2*)&c1F[bi];
                    uint2 bl = *(const uint2*)&c1F[8192 + bi];
                    mma3(cC[q], ah, al, bh, bl);
                }
            }
            float sl = 0.f, sh = 0.f;
#pragma unroll
            for (int q = 0; q < 4; q++) {
                int jq = (ng * 4 + q) * 8 + 2 * thr;
                sl += silu_f(cC[q][0]) * c2_s[jq] + silu_f(cC[q][1]) * c2_s[jq + 1];
                sh += silu_f(cC[q][2]) * c2_s[jq] + silu_f(cC[q][3]) * c2_s[jq + 1];
            }
            sl += __shfl_xor_sync(0xffffffffu, sl, 1);
            sl += __shfl_xor_sync(0xffffffffu, sl, 2);
            sh += __shfl_xor_sync(0xffffffffu, sh, 1);
            sh += __shfl_xor_sync(0xffffffffu, sh, 2);
            if (thr == 0) {
                atomicAdd(&wsum_s[ee0], sl);
                atomicAdd(&wsum_s[ee1], sh);
            }
        }
        __syncthreads();

        // Phase D: j-pair segment scan scatter
        {
            const int jp = t & 63;
            const int j0 = jp * 2;
            const int q = t >> 6;          // 0..15
            const int ebeg = q * 8;
            float acc0 = 0.f, acc1 = 0.f;
            int cur = row_s[ebeg];
#pragma unroll
            for (int i = 0; i < 8; i++) {
                int e = ebeg + i;
                int r = row_s[e];
                int fi = fragAb(e, j0, 8);
                unsigned hi = actH[fi], lo = actL[fi];
                float v0 = bfsum(hi, lo);
                float v1 = bfsum(hi >> 16, lo >> 16);
                if (r != cur) {
                    if (cur >= 0) {
                        atomicAdd(&g_agg[cur * H + j0], acc0);
                        atomicAdd(&g_agg[cur * H + j0 + 1], acc1);
                    }
                    acc0 = 0.f; acc1 = 0.f;
                    cur = r;
                }
                acc0 += v0; acc1 += v1;
            }
            if (cur >= 0) {
                atomicAdd(&g_agg[cur * H + j0], acc0);
                atomicAdd(&g_agg[cur * H + j0 + 1], acc1);
            }
        }
        if (t < 384) {
            int e = t / 3, k = t % 3;
            int r = row_s[e];
            if (r >= 0)
                atomicAdd(&g_posdelta[r * 3 + k], rel_s[e * 3 + k] * wsum_s[e]);
        }
        __syncthreads();
    }
}

// ---------------- fused node update: U = silu([h|agg]@n1+b1); h += U@n2 + b2; pos ------
__global__ __launch_bounds__(1024, 1) void k_node(int l, const float* __restrict__ b1n,
                                                  const float* __restrict__ b2n) {
    extern __shared__ float sm[];
    unsigned* wF = (unsigned*)sm;   // 16384
    unsigned* aH = wF + 16384;      // 4096
    unsigned* aL = aH + 4096;       // 4096
    const int t = threadIdx.x;
    const int n0 = blockIdx.x * 64;
    const int wid = t >> 5, lane = t & 31;
    const int mt = wid >> 3, nt0 = (wid & 7) * 2;
    const int grp = lane >> 2, thr = lane & 3;
    const int ee0 = mt * 16 + grp, ee1 = ee0 + 8;
    const int g0 = n0 + ee0, g1 = n0 + ee1;
    const int j00 = nt0 * 8 + 2 * thr, j10 = (nt0 + 1) * 8 + 2 * thr;

    // pos update (posdelta complete after edge; proj(l+1) re-zeroes it)
    if (t < 192) {
        int gi = n0 + t / 3;
        if (gi < N_NODES) {
            float d = fmaxf(g_deg[gi], 1.0f);
            g_pos[n0 * 3 + t] += g_posdelta[n0 * 3 + t] / d;
        }
    }

    float c0[4] = {0.f, 0.f, 0.f, 0.f}, c1[4] = {0.f, 0.f, 0.f, 0.f};
    for (int halfk = 0; halfk < 2; halfk++) {
        __syncthreads();
        {
            const uint4* s = (const uint4*)(g_pk_n1 + l * 32768 + halfk * 16384);
            uint4* d = (uint4*)wF;
            for (int i = t; i < 4096; i += 1024) d[i] = s[i];
        }
        const float* src = halfk ? g_agg : g_h;
        for (int i = t; i < 4096; i += 1024) {
            int n = i >> 6, jp = i & 63;
            int j0 = jp * 2;
            int gi = n0 + n;
            float2 v = make_float2(0.f, 0.f);
            if (gi < N_NODES) v = *(const float2*)&src[gi * H + j0];
            unsigned lo;
            unsigned hi = split2(v.x, v.y, lo);
            int fi = fragAb(n, j0, 8);
            aH[fi] = hi;
            aL[fi] = lo;
        }
        __syncthreads();
#pragma unroll
        for (int kt = 0; kt < 8; kt++) {
            int aoff = (((mt * 8 + kt) << 5) + lane) << 2;
            uint4 ah = *(const uint4*)&aH[aoff];
            uint4 al = *(const uint4*)&aL[aoff];
            int bi0 = (((nt0 * 8 + kt) << 5) + lane) << 1;
            int bi1 = ((((nt0 + 1) * 8 + kt) << 5) + lane) << 1;
            uint2 bh0 = *(const uint2*)&wF[bi0];
            uint2 bl0 = *(const uint2*)&wF[8192 + bi0];
            uint2 bh1 = *(const uint2*)&wF[bi1];
            uint2 bl1 = *(const uint2*)&wF[8192 + bi1];
            mma3(c0, ah, al, bh0, bl0);
            mma3(c1, ah, al, bh1, bl1);
        }
    }
    // U = silu(c + b1); write as fragments for second GEMM
    float b00 = __ldg(&b1n[j00]), b01 = __ldg(&b1n[j00 + 1]);
    float b10 = __ldg(&b1n[j10]), b11 = __ldg(&b1n[j10 + 1]);
    float u00 = silu_f(c0[0] + b00), u01 = silu_f(c0[1] + b01);
    float u02 = silu_f(c0[2] + b00), u03 = silu_f(c0[3] + b01);
    float u10 = silu_f(c1[0] + b10), u11 = silu_f(c1[1] + b11);
    float u12 = silu_f(c1[2] + b10), u13 = silu_f(c1[3] + b11);
    __syncthreads();   // all MMA reads of aH/aL/wF done
    {
        unsigned lo;
        unsigned hi;
        int fi;
        hi = split2(u00, u01, lo); fi = fragAb(ee0, j00, 8); aH[fi] = hi; aL[fi] = lo;
        hi = split2(u02, u03, lo); fi = fragAb(ee1, j00, 8); aH[fi] = hi; aL[fi] = lo;
        hi = split2(u10, u11, lo); fi = fragAb(ee0, j10, 8); aH[fi] = hi; aL[fi] = lo;
        hi = split2(u12, u13, lo); fi = fragAb(ee1, j10, 8); aH[fi] = hi; aL[fi] = lo;
    }
    {
        const uint4* s = (const uint4*)(g_pk_n2 + l * 16384);
        uint4* d = (uint4*)wF;
        for (int i = t; i < 4096; i += 1024) d[i] = s[i];
    }
    __syncthreads();

    // second GEMM: h += U @ n2 + b2
    float d0[4] = {0.f, 0.f, 0.f, 0.f}, d1[4] = {0.f, 0.f, 0.f, 0.f};
#pragma unroll
    for (int kt = 0; kt < 8; kt++) {
        int aoff = (((mt * 8 + kt) << 5) + lane) << 2;
        uint4 ah = *(const uint4*)&aH[aoff];
        uint4 al = *(const uint4*)&aL[aoff];
        int bi0 = (((nt0 * 8 + kt) << 5) + lane) << 1;
        int bi1 = ((((nt0 + 1) * 8 + kt) << 5) + lane) << 1;
        uint2 bh0 = *(const uint2*)&wF[bi0];
        uint2 bl0 = *(const uint2*)&wF[8192 + bi0];
        uint2 bh1 = *(const uint2*)&wF[bi1];
        uint2 bl1 = *(const uint2*)&wF[8192 + bi1];
        mma3(d0, ah, al, bh0, bl0);
        mma3(d1, ah, al, bh1, bl1);
    }
    float e00 = __ldg(&b2n[j00]), e01 = __ldg(&b2n[j00 + 1]);
    float e10 = __ldg(&b2n[j10]), e11 = __ldg(&b2n[j10 + 1]);
    if (g0 < N_NODES) {
        float2 h0 = *(float2*)&g_h[g0 * H + j00];
        h0.x += d0[0] + e00; h0.y += d0[1] + e01;
        *(float2*)&g_h[g0 * H + j00] = h0;
        float2 h1 = *(float2*)&g_h[g0 * H + j10];
        h1.x += d1[0] + e10; h1.y += d1[1] + e11;
        *(float2*)&g_h[g0 * H + j10] = h1;
    }
    if (g1 < N_NODES) {
        float2 h0 = *(float2*)&g_h[g1 * H + j00];
        h0.x += d0[2] + e00; h0.y += d0[3] + e01;
        *(float2*)&g_h[g1 * H + j00] = h0;
        float2 h1 = *(float2*)&g_h[g1 * H + j10];
        h1.x += d1[2] + e10; h1.y += d1[3] + e11;
        *(float2*)&g_h[g1 * H + j10] = h1;
    }
}

// ---------------- pooling + readout head fused ----------------
__global__ __launch_bounds__(512) void k_poolhead(
    const float* __restrict__ h1_w, const float* __restrict__ h1_b,
    const float* __restrict__ h2_w, const float* __restrict__ h2_b,
    const float* __restrict__ h3_w, const float* __restrict__ h3_b,
    float* __restrict__ out) {
    __shared__ float red[512], gf[256], z1[128], z2[64];
    const int g = blockIdx.x, t = threadIdx.x;
    const int j = t & 127, w = t >> 7;
    float s = 0.f;
    for (int n = w; n < NPG; n += 4) s += g_h[(g * NPG + n) * H + j];
    red[t] = s;
    __syncthreads();
    if (w == 0) {
        float tot = red[j] + red[128 + j] + red[256 + j] + red[384 + j];
        gf[j] = tot;
        gf[128 + j] = tot * (1.f / (float)NPG);
    }
    __syncthreads();
    if (t < 128) {
        float a = h1_b[t];
        for (int k = 0; k < 256; k++) a += gf[k] * h1_w[k * 128 + t];
        z1[t] = fmaxf(a, 0.f);
    }
    __syncthreads();
    if (t < 64) {
        float a2 = h2_b[t];
        for (int k = 0; k < 128; k++) a2 += z1[k] * h2_w[k * 64 + t];
        z2[t] = fmaxf(a2, 0.f);
    }
    __syncthreads();
    if (t == 0) {
        float a3 = h3_b[0];
        for (int k = 0; k < 64; k++) a3 += z2[k] * h3_w[k];
        out[g] = a3;
    }
}

// ---------------- launch ----------------
extern "C" void kernel_launch(void* const* d_in, const int* in_sizes, int n_in,
                              void* d_out, int out_size) {
    const float* x     = (const float*)d_in[0];
    const float* pos   = (const float*)d_in[1];
    const int*   ei    = (const int*)d_in[2];
    const float* eattr = (const float*)d_in[3];
    const float* Wp    = (const float*)d_in[6];
    const float* bp    = (const float*)d_in[7];
    const float* Wl    = (const float*)d_in[8];
    const float* bl    = (const float*)d_in[9];
    const float* gamma = (const float*)d_in[10];
    const float* beta  = (const float*)d_in[11];
    const float* e_w1  = (const float*)d_in[12];
    const float* e_b1  = (const float*)d_in[13];
    const float* e_w2  = (const float*)d_in[14];
    const float* e_b2  = (const float*)d_in[15];
    const float* c_w1  = (const float*)d_in[16];
    const float* c_b1  = (const float*)d_in[17];
    const float* c_w2  = (const float*)d_in[18];
    const float* n_w1  = (const float*)d_in[19];
    const float* n_b1  = (const float*)d_in[20];
    const float* n_w2  = (const float*)d_in[21];
    const float* n_b2  = (const float*)d_in[22];
    const float* h1_w  = (const float*)d_in[23];
    const float* h1_b  = (const float*)d_in[24];
    const float* h2_w  = (const float*)d_in[25];
    const float* h2_b  = (const float*)d_in[26];
    const float* h3_w  = (const float*)d_in[27];
    const float* h3_b  = (const float*)d_in[28];
    float* out = (float*)d_out;

    const int PROJ_SMEM = (32768 + 4096 + 4096) * 4;
    const int EDGE_SMEM = (16384 * 2 + 8192 * 2 + 128 * 4 + 512
                           + 128 + 384 + 512 + 128 + 128 + 128) * 4;
    const int NODE_SMEM = (16384 + 4096 + 4096) * 4;
    cudaFuncSetAttribute(k_proj, cudaFuncAttributeMaxDynamicSharedMemorySize, PROJ_SMEM);
    cudaFuncSetAttribute(k_edge, cudaFuncAttributeMaxDynamicSharedMemorySize, EDGE_SMEM);
    cudaFuncSetAttribute(k_node, cudaFuncAttributeMaxDynamicSharedMemorySize, NODE_SMEM);

    const int nblocks64 = (N_NODES + 63) / 64;   // 782

    k_embed<<<N_NODES, 128>>>(x, pos, Wp, bp, Wl, bl);
    k_prep<<<256 + DEG_BLOCKS + PACK_BLOCKS, 512>>>(ei, e_w1, e_w2, c_w1, n_w1, n_w2);
    k_bnapply_scan<<<BNA_BLOCKS + 1, 512>>>(gamma, beta);

    for (int l = 0; l < NLAYERS; l++) {
        k_proj<<<nblocks64, 1024, PROJ_SMEM>>>(l, e_b1 + l * H);
        if (l == 0) k_perm<<<(N_EDGES + 511) / 512, 512>>>(ei);
        k_edge<<<148, 1024, EDGE_SMEM>>>(eattr, l, e_b2 + l * H, c_b1 + l * H,
                                         c_w2 + l * H, e_w1 + l * 261 * H);
        k_node<<<nblocks64, 1024, NODE_SMEM>>>(l, n_b1 + l * H, n_b2 + l * H);
    }

    k_poolhead<<<G_GRAPHS, 512>>>(h1_w, h1_b, h2_w, h2_b, h3_w, h3_b, out);
}

// round 12
// speedup vs baseline: 1.6733x; 1.0077x over previous
#include <cuda_runtime.h>
#include <cuda_bf16.h>

#define N_NODES 50000
#define N_EDGES 500000
#define H 128
#define G_GRAPHS 100
#define NPG 500
#define NPROT 400
#define PN 35
#define LN 11
#define NLAYERS 4
#define EPS 1e-5f
#define NE_TILE 128

// ---------------- scratch ----------------
__device__ float g_h[N_NODES * H];
__device__ float g_P1[N_NODES * H];
__device__ float g_P2[N_NODES * H];
__device__ float g_agg[N_NODES * H];
__device__ float g_pos[N_NODES * 3];
__device__ float g_posdelta[N_NODES * 3];
__device__ float g_deg[N_NODES];
__device__ float g_bnstats[2 * H];
__device__ int g_rowcur[N_NODES];
__device__ int g_srow[N_EDGES];
__device__ int g_scol[N_EDGES];
__device__ int g_sperm[N_EDGES];
// pre-packed bf16 hi/lo weight fragments
__device__ unsigned g_pk_proj[NLAYERS * 32768];  // hi 16384 | lo 16384
__device__ unsigned g_pk_w2[NLAYERS * 16384];    // hi 8192 | lo 8192
__device__ unsigned g_pk_c1[NLAYERS * 16384];
__device__ unsigned g_pk_n1[NLAYERS * 32768];    // [half0: hi|lo][half1: hi|lo]
__device__ unsigned g_pk_n2[NLAYERS * 16384];

__device__ __forceinline__ float silu_f(float x) {
    return x / (1.f + __expf(-x));
}

// ---- bf16 m16n8k16 mma ----
__device__ __forceinline__ void mma_bf16(float* c, const uint4& a, const uint2& b) {
    asm volatile(
        "mma.sync.aligned.m16n8k16.row.col.f32.bf16.bf16.f32 "
        "{%0,%1,%2,%3}, {%4,%5,%6,%7}, {%8,%9}, {%0,%1,%2,%3};"
        : "+f"(c[0]), "+f"(c[1]), "+f"(c[2]), "+f"(c[3])
        : "r"(a.x), "r"(a.y), "r"(a.z), "r"(a.w), "r"(b.x), "r"(b.y));
}
__device__ __forceinline__ unsigned split2(float v0, float v1, unsigned& lo) {
    __nv_bfloat16 h0 = __float2bfloat16(v0);
    __nv_bfloat16 h1 = __float2bfloat16(v1);
    __nv_bfloat16 l0 = __float2bfloat16(v0 - __bfloat162float(h0));
    __nv_bfloat16 l1 = __float2bfloat16(v1 - __bfloat162float(h1));
    lo = (unsigned)__bfloat16_as_ushort(l0) | ((unsigned)__bfloat16_as_ushort(l1) << 16);
    return (unsigned)__bfloat16_as_ushort(h0) | ((unsigned)__bfloat16_as_ushort(h1) << 16);
}
__device__ __forceinline__ void mma3(float* c, const uint4& ah, const uint4& al,
                                     const uint2& bh, const uint2& bl) {
    mma_bf16(c, ah, bh);
    mma_bf16(c, ah, bl);
    mma_bf16(c, al, bh);
}
__device__ __forceinline__ int fragAb(int e, int j0, int KT) {
    int jin = j0 & 15;
    int tid = (jin & 7) >> 1;
    int reg = ((jin >> 3) << 1) | ((e >> 3) & 1);
    int lane = ((e & 7) << 2) | tid;
    return (((e >> 4) * KT + (j0 >> 4)) << 7) + (lane << 2) + reg;
}
__device__ __forceinline__ float bfsum(unsigned hi, unsigned lo) {
    return __bfloat162float(__ushort_as_bfloat16((unsigned short)(hi & 0xffffu)))
         + __bfloat162float(__ushort_as_bfloat16((unsigned short)(lo & 0xffffu)));
}

// ---------------- K1: embed ----------------
__global__ void k_embed(const float* __restrict__ x, const float* __restrict__ pos_in,
                        const float* __restrict__ Wp, const float* __restrict__ bp,
                        const float* __restrict__ Wl, const float* __restrict__ bl) {
    __shared__ float xs[PN];
    const int i = blockIdx.x;
    const int t = threadIdx.x;
    if (t < PN) xs[t] = x[i * PN + t];
    if (t == 0) g_deg[i] = 0.f;
    if (t < 3) g_pos[i * 3 + t] = pos_in[i * 3 + t];
    if (i == 0 && t < H) { g_bnstats[t] = 0.f; g_bnstats[H + t] = 0.f; }
    __syncthreads();
    const bool isp = (i % NPG) < NPROT;
    const float* W = isp ? Wp : Wl;
    const float* b = isp ? bp : bl;
    const int nk = isp ? PN : LN;
    float acc = b[t];
    for (int k = 0; k < nk; k++) acc += xs[k] * W[k * H + t];
    g_h[i * H + t] = acc;
}

// ---------------- K2: prep = bnstats + deg + weight pack ----------------
#define DEG_BLOCKS ((N_EDGES + 511) / 512)
#define PACK_PER_LAYER (16384 + 8192 + 8192 + 16384 + 8192)  // 57344
#define PACK_ITEMS (NLAYERS * PACK_PER_LAYER)
#define PACK_BLOCKS ((PACK_ITEMS + 511) / 512)
__global__ __launch_bounds__(512) void k_prep(const int* __restrict__ ei,
                                              const float* __restrict__ ew1,
                                              const float* __restrict__ ew2,
                                              const float* __restrict__ cw1,
                                              const float* __restrict__ nw1,
                                              const float* __restrict__ nw2) {
    const int t = threadIdx.x;
    if (blockIdx.x < 256) {
        const int j = t & 127;
        const int g2 = t >> 7;
        float s = 0.f, s2 = 0.f;
        for (int i = blockIdx.x * 4 + g2; i < N_NODES; i += 1024) {
            float v = g_h[i * H + j];
            s += v; s2 += v * v;
        }
        atomicAdd(&g_bnstats[j], s);
        atomicAdd(&g_bnstats[H + j], s2);
        return;
    }
    if (blockIdx.x < 256 + DEG_BLOCKS) {
        const int e = (blockIdx.x - 256) * 512 + t;
        if (e < N_EDGES) atomicAdd(&g_deg[ei[e]], 1.0f);
        return;
    }
    int idx = (blockIdx.x - 256 - DEG_BLOCKS) * 512 + t;
    if (idx >= PACK_ITEMS) return;
    int l = idx / PACK_PER_LAYER;
    int o = idx - l * PACK_PER_LAYER;
    float w0, w1;
    unsigned* hip;
    unsigned* lop;
    if (o < 16384) {            // proj
        int i = o;
        int rb = i & 1, lane = (i >> 1) & 31, kt = (i >> 6) & 7, nt = i >> 9;
        int tid = lane & 3, g = lane >> 2;
        int k0 = kt * 16 + tid * 2 + rb * 8;
        int jj = nt * 8 + g;
        const float* W = ew1 + l * 261 * H;
        int srcrow = (jj < 128) ? k0 : (128 + k0);
        int col = jj & 127;
        w0 = W[srcrow * H + col];
        w1 = W[(srcrow + 1) * H + col];
        hip = g_pk_proj + l * 32768 + i;
        lop = hip + 16384;
    } else if (o < 24576) {     // w2
        int i = o - 16384;
        int rb = i & 1, lane = (i >> 1) & 31, kt = (i >> 6) & 7, nt = i >> 9;
        int tid = lane & 3, g = lane >> 2;
        int k0 = kt * 16 + tid * 2 + rb * 8;
        int n = nt * 8 + g;
        const float* W = ew2 + l * H * H;
        w0 = W[k0 * H + n];
        w1 = W[(k0 + 1) * H + n];
        hip = g_pk_w2 + l * 16384 + i;
        lop = hip + 8192;
    } else if (o < 32768) {     // c1
        int i = o - 24576;
        int rb = i & 1, lane = (i >> 1) & 31, kt = (i >> 6) & 7, nt = i >> 9;
        int tid = lane & 3, g = lane >> 2;
        int k0 = kt * 16 + tid * 2 + rb * 8;
        int n = nt * 8 + g;
        const float* W = cw1 + l * H * H;
        w0 = W[k0 * H + n];
        w1 = W[(k0 + 1) * H + n];
        hip = g_pk_c1 + l * 16384 + i;
        lop = hip + 8192;
    } else if (o < 49152) {     // n1
        int i2 = o - 32768;
        int hk = i2 >> 13;
        int i = i2 & 8191;
        int rb = i & 1, lane = (i >> 1) & 31, kt = (i >> 6) & 7, nt = i >> 9;
        int tid = lane & 3, g = lane >> 2;
        int k0 = hk * 128 + kt * 16 + tid * 2 + rb * 8;
        int n = nt * 8 + g;
        const float* W = nw1 + l * 2 * H * H;
        w0 = W[k0 * H + n];
        w1 = W[(k0 + 1) * H + n];
        hip = g_pk_n1 + l * 32768 + hk * 16384 + i;
        lop = hip + 8192;
    } else {                    // n2
        int i = o - 49152;
        int rb = i & 1, lane = (i >> 1) & 31, kt = (i >> 6) & 7, nt = i >> 9;
        int tid = lane & 3, g = lane >> 2;
        int k0 = kt * 16 + tid * 2 + rb * 8;
        int n = nt * 8 + g;
        const float* W = nw2 + l * H * H;
        w0 = W[k0 * H + n];
        w1 = W[(k0 + 1) * H + n];
        hip = g_pk_n2 + l * 16384 + i;
        lop = hip + 8192;
    }
    unsigned lo;
    unsigned hi = split2(w0, w1, lo);
    *hip = hi;
    *lop = lo;
}

// ---------------- K3: bnapply + degree scan ----------------
#define BNA_BLOCKS ((N_NODES * H) / 512)
__global__ __launch_bounds__(512) void k_bnapply_scan(const float* __restrict__ gamma,
                                                      const float* __restrict__ beta) {
    const int t = threadIdx.x;
    if (blockIdx.x < BNA_BLOCKS) {
        const int idx = blockIdx.x * 512 + t;
        const int j = idx & (H - 1);
        const float inv_n = 1.f / (float)N_NODES;
        float mu = g_bnstats[j] * inv_n;
        float var = g_bnstats[H + j] * inv_n - mu * mu;
        g_h[idx] = (g_h[idx] - mu) * rsqrtf(var + EPS) * gamma[j] + beta[j];
    } else {
        __shared__ int sums[512];
        const int chunk = 98;
        int base = t * chunk;
        int lim = min(base + chunk, N_NODES);
        int s = 0;
        for (int i = base; i < lim; i++) s += (int)g_deg[i];
        sums[t] = s;
        __syncthreads();
        for (int off = 1; off < 512; off <<= 1) {
            int v = (t >= off) ? sums[t - off] : 0;
            __syncthreads();
            sums[t] += v;
            __syncthreads();
        }
        int run = (t == 0) ? 0 : sums[t - 1];
        for (int i = base; i < lim; i++) {
            g_rowcur[i] = run;
            run += (int)g_deg[i];
        }
    }
}

// ---------------- counting-sort scatter ----------------
__global__ __launch_bounds__(512) void k_perm(const int* __restrict__ ei) {
    const int e = blockIdx.x * 512 + threadIdx.x;
    if (e >= N_EDGES) return;
    int r = ei[e];
    int p = atomicAdd(&g_rowcur[r], 1);
    g_srow[p] = r;
    g_scol[p] = ei[N_EDGES + e];
    g_sperm[p] = e;
}

// ---------------- proj: bf16 3-MMA ----------------
__global__ __launch_bounds__(1024, 1) void k_proj(int l, const float* __restrict__ b1) {
    extern __shared__ float sm[];
    unsigned* wF = (unsigned*)sm;       // 32768
    unsigned* aH = wF + 32768;          // 4096
    unsigned* aL = aH + 4096;           // 4096
    const int t = threadIdx.x;
    const int n0 = blockIdx.x * 64;

    {
        const uint4* s = (const uint4*)(g_pk_proj + l * 32768);
        uint4* d = (uint4*)wF;
        for (int i = t; i < 8192; i += 1024) d[i] = s[i];
    }
    for (int i = t; i < 4096; i += 1024) {
        int n = i >> 6, jp = i & 63;
        int j0 = jp * 2;
        int gi = n0 + n;
        float2 v = make_float2(0.f, 0.f);
        if (gi < N_NODES) v = *(const float2*)&g_h[gi * H + j0];
        unsigned lo;
        unsigned hi = split2(v.x, v.y, lo);
        int fi = fragAb(n, j0, 8);
        aH[fi] = hi;
        aL[fi] = lo;
    }
    // zero agg (float4 stores) + posdelta
    {
        const float4 z4 = make_float4(0.f, 0.f, 0.f, 0.f);
        for (int i = t; i < 2048; i += 1024) {
            int gi = n0 + (i >> 5);
            if (gi < N_NODES) *(float4*)&g_agg[gi * H + (i & 31) * 4] = z4;
        }
    }
    if (t < 192) {
        int gi = n0 + t / 3;
        if (gi < N_NODES) g_posdelta[gi * 3 + t % 3] = 0.f;
    }
    __syncthreads();

    const int wid = t >> 5, lane = t & 31;
    const int mt = wid >> 3;
    const int ng = wid & 7;
    const int grp = lane >> 2, thr = lane & 3;
    float c[4][4];
#pragma unroll
    for (int q = 0; q < 4; q++)
#pragma unroll
        for (int r = 0; r < 4; r++) c[q][r] = 0.f;

#pragma unroll
    for (int kt = 0; kt < 8; kt++) {
        int aoff = (((mt * 8 + kt) << 5) + lane) << 2;
        uint4 ah = *(const uint4*)&aH[aoff];
        uint4 al = *(const uint4*)&aL[aoff];
#pragma unroll
        for (int q = 0; q < 4; q++) {
            int nt = ng * 4 + q;
            int bi = (((nt * 8 + kt) << 5) + lane) << 1;
            uint2 bh = *(const uint2*)&wF[bi];
            uint2 bl = *(const uint2*)&wF[16384 + bi];
            mma3(c[q], ah, al, bh, bl);
        }
    }

    const int ee0 = mt * 16 + grp, ee1 = ee0 + 8;
    const int g0 = n0 + ee0, g1 = n0 + ee1;
#pragma unroll
    for (int q = 0; q < 4; q++) {
        int nt = ng * 4 + q;
        int jj0 = nt * 8 + 2 * thr;
        int half = jj0 >> 7;
        int j = jj0 & 127;
        float* outp = half ? g_P2 : g_P1;
        float bb0 = half ? 0.f : __ldg(&b1[j]);
        float bb1 = half ? 0.f : __ldg(&b1[j + 1]);
        if (g0 < N_NODES)
            *(float2*)&outp[g0 * H + j] = make_float2(c[q][0] + bb0, c[q][1] + bb1);
        if (g1 < N_NODES)
            *(float2*)&outp[g1 * H + j] = make_float2(c[q][2] + bb0, c[q][3] + bb1);
    }
}

// ---------------- fused edge kernel ----------------
__global__ __launch_bounds__(1024, 1) void k_edge(
    const float* __restrict__ eattr, int l,
    const float* __restrict__ b2, const float* __restrict__ cb1,
    const float* __restrict__ cw2, const float* __restrict__ ew1) {
    extern __shared__ float sm[];
    unsigned* w2F = (unsigned*)sm;       // 16384
    unsigned* c1F = w2F + 16384;         // 16384
    unsigned* actH = c1F + 16384;        // 8192
    unsigned* actL = actH + 8192;        // 8192
    float* b2_s  = (float*)(actL + 8192);  // 128
    float* cb1_s = b2_s + 128;           // 128
    float* c2_s  = cb1_s + 128;          // 128
    float* wd2_s = c2_s + 128;           // 128
    float* wea_s = wd2_s + 128;          // 512
    float* d2_s  = wea_s + 512;          // 128
    float* rel_s = d2_s + 128;           // 384
    float* ea_s  = rel_s + 384;          // 512
    float* wsum_s = ea_s + 512;          // 128
    int* row_s = (int*)(wsum_s + 128);   // 128
    int* col_s = row_s + 128;            // 128

    const int t = threadIdx.x;
    {
        const uint4* s2 = (const uint4*)(g_pk_w2 + l * 16384);
        const uint4* s1 = (const uint4*)(g_pk_c1 + l * 16384);
        uint4* d2 = (uint4*)w2F;
        uint4* d1 = (uint4*)c1F;
        for (int i = t; i < 4096; i += 1024) { d2[i] = s2[i]; d1[i] = s1[i]; }
    }
    if (t < 128) {
        b2_s[t] = b2[t]; cb1_s[t] = cb1[t]; c2_s[t] = cw2[t];
        wd2_s[t] = ew1[256 * H + t];
    }
    if (t >= 128 && t < 640) wea_s[t - 128] = ew1[257 * H + (t - 128)];
    __syncthreads();

    const int w = t >> 5;
    const int lane = t & 31;
    const int mt = w >> 2;         // 0..7
    const int ng = w & 3;          // 0..3
    const int grp = lane >> 2;
    const int thr = lane & 3;
    const int ee0 = mt * 16 + grp, ee1 = ee0 + 8;
    const int ntiles = (N_EDGES + NE_TILE - 1) / NE_TILE;

    for (int tile = blockIdx.x; tile < ntiles; tile += gridDim.x) {
        const int e0 = tile * NE_TILE;
        if (t < NE_TILE) {
            wsum_s[t] = 0.f;
            int sidx = e0 + t;
            int r = -1, c = 0, pe = 0;
            if (sidx < N_EDGES) { r = g_srow[sidx]; c = g_scol[sidx]; pe = g_sperm[sidx]; }
            row_s[t] = r; col_s[t] = c;
            float4 a = make_float4(0.f, 0.f, 0.f, 0.f);
            if (r >= 0) a = *(const float4*)&eattr[pe * 4];
            int rr = r < 0 ? 0 : r;
            float rx = g_pos[rr * 3 + 0] - g_pos[c * 3 + 0];
            float ry = g_pos[rr * 3 + 1] - g_pos[c * 3 + 1];
            float rz = g_pos[rr * 3 + 2] - g_pos[c * 3 + 2];
            rel_s[t * 3 + 0] = rx; rel_s[t * 3 + 1] = ry; rel_s[t * 3 + 2] = rz;
            d2_s[t] = rx * rx + ry * ry + rz * rz;
            ea_s[t * 4 + 0] = a.x; ea_s[t * 4 + 1] = a.y;
            ea_s[t * 4 + 2] = a.z; ea_s[t * 4 + 3] = a.w;
        }
        __syncthreads();

        // Phase A: warp handles 4 CONSECUTIVE edges; sorted rows -> P1 register reuse
        {
            const int ebase4 = w * 4;
            const int j0 = lane * 4;
            int prevrow = -1;
            float4 p1;
#pragma unroll
            for (int rep = 0; rep < 4; rep++) {
                int e = ebase4 + rep;
                int r = row_s[e], c = col_s[e];
                int rr = r < 0 ? 0 : r;
                if (rr != prevrow) {          // warp-uniform branch
                    p1 = *(const float4*)&g_P1[rr * H + j0];
                    prevrow = rr;
                }
                float4 p2 = *(const float4*)&g_P2[c * H + j0];
                float dd = d2_s[e];
                float v0 = p1.x + p2.x + dd * wd2_s[j0];
                float v1 = p1.y + p2.y + dd * wd2_s[j0 + 1];
                float v2 = p1.z + p2.z + dd * wd2_s[j0 + 2];
                float v3 = p1.w + p2.w + dd * wd2_s[j0 + 3];
#pragma unroll
                for (int a2 = 0; a2 < 4; a2++) {
                    float eav = ea_s[e * 4 + a2];
                    v0 += eav * wea_s[a2 * H + j0];
                    v1 += eav * wea_s[a2 * H + j0 + 1];
                    v2 += eav * wea_s[a2 * H + j0 + 2];
                    v3 += eav * wea_s[a2 * H + j0 + 3];
                }
                unsigned lo;
                unsigned hi = split2(silu_f(v0), silu_f(v1), lo);
                int fi = fragAb(e, j0, 8);
                actH[fi] = hi; actL[fi] = lo;
                hi = split2(silu_f(v2), silu_f(v3), lo);
                fi = fragAb(e, j0 + 2, 8);
                actH[fi] = hi; actL[fi] = lo;
            }
        }
        __syncthreads();

        // Phase B: m = silu(hid @ W2 + b2)
        float cB[4][4];
#pragma unroll
        for (int q = 0; q < 4; q++) {
            int jc = (ng * 4 + q) * 8 + 2 * thr;
            cB[q][0] = b2_s[jc]; cB[q][1] = b2_s[jc + 1];
            cB[q][2] = cB[q][0]; cB[q][3] = cB[q][1];
        }
#pragma unroll
        for (int kt = 0; kt < 8; kt++) {
            int aoff = (((mt * 8 + kt) << 5) + lane) << 2;
            uint4 ah = *(const uint4*)&actH[aoff];
            uint4 al = *(const uint4*)&actL[aoff];
#pragma unroll
            for (int q = 0; q < 4; q++) {
                int bi = ((((ng * 4 + q) * 8 + kt) << 5) + lane) << 1;
                uint2 bh = *(const uint2*)&w2F[bi];
                uint2 bl = *(const uint2*)&w2F[8192 + bi];
                mma3(cB[q], ah, al, bh, bl);
            }
        }
        __syncthreads();
#pragma unroll
        for (int q = 0; q < 4; q++) {
            int jq = (ng * 4 + q) * 8 + 2 * thr;
            unsigned lo0, lo1;
            unsigned hi0 = split2(silu_f(cB[q][0]), silu_f(cB[q][1]), lo0);
            unsigned hi1 = split2(silu_f(cB[q][2]), silu_f(cB[q][3]), lo1);
            int f0 = fragAb(ee0, jq, 8);
            int f1 = fragAb(ee1, jq, 8);
            actH[f0] = hi0; actL[f0] = lo0;
            actH[f1] = hi1; actL[f1] = lo1;
        }
        __syncthreads();

        // Phase C
        {
            float cC[4][4];
#pragma unroll
            for (int q = 0; q < 4; q++) {
                int jc = (ng * 4 + q) * 8 + 2 * thr;
                cC[q][0] = cb1_s[jc]; cC[q][1] = cb1_s[jc + 1];
                cC[q][2] = cC[q][0]; cC[q][3] = cC[q][1];
            }
#pragma unroll
            for (int kt = 0; kt < 8; kt++) {
                int aoff = (((mt * 8 + kt) << 5) + lane) << 2;
                uint4 ah = *(const uint4*)&actH[aoff];
                uint4 al = *(const uint4*)&actL[aoff];
#pragma unroll
                for (int q = 0; q < 4; q++) {
                    int bi = ((((ng * 4 + q) * 8 + kt) << 5) + lane) << 1;
                    uint2 bh = *(const uint2*)&c1F[bi];
                    uint2 bl = *(const uint2*)&c1F[8192 + bi];
                    mma3(cC[q], ah, al, bh, bl);
                }
            }
            float sl = 0.f, sh = 0.f;
#pragma unroll
            for (int q = 0; q < 4; q++) {
                int jq = (ng * 4 + q) * 8 + 2 * thr;
                sl += silu_f(cC[q][0]) * c2_s[jq] + silu_f(cC[q][1]) * c2_s[jq + 1];
                sh += silu_f(cC[q][2]) * c2_s[jq] + silu_f(cC[q][3]) * c2_s[jq + 1];
            }
            sl += __shfl_xor_sync(0xffffffffu, sl, 1);
            sl += __shfl_xor_sync(0xffffffffu, sl, 2);
            sh += __shfl_xor_sync(0xffffffffu, sh, 1);
            sh += __shfl_xor_sync(0xffffffffu, sh, 2);
            if (thr == 0) {
                atomicAdd(&wsum_s[ee0], sl);
                atomicAdd(&wsum_s[ee1], sh);
            }
        }
        __syncthreads();

        // Phase D: j-pair segment scan scatter
        {
            const int jp = t & 63;
            const int j0 = jp * 2;
            const int q = t >> 6;          // 0..15
            const int ebeg = q * 8;
            float acc0 = 0.f, acc1 = 0.f;
            int cur = row_s[ebeg];
#pragma unroll
            for (int i = 0; i < 8; i++) {
                int e = ebeg + i;
                int r = row_s[e];
                int fi = fragAb(e, j0, 8);
                unsigned hi = actH[fi], lo = actL[fi];
                float v0 = bfsum(hi, lo);
                float v1 = bfsum(hi >> 16, lo >> 16);
                if (r != cur) {
                    if (cur >= 0) {
                        atomicAdd(&g_agg[cur * H + j0], acc0);
                        atomicAdd(&g_agg[cur * H + j0 + 1], acc1);
                    }
                    acc0 = 0.f; acc1 = 0.f;
                    cur = r;
                }
                acc0 += v0; acc1 += v1;
            }
            if (cur >= 0) {
                atomicAdd(&g_agg[cur * H + j0], acc0);
                atomicAdd(&g_agg[cur * H + j0 + 1], acc1);
            }
        }
        if (t < 384) {
            int e = t / 3, k = t % 3;
            int r = row_s[e];
            if (r >= 0)
                atomicAdd(&g_posdelta[r * 3 + k], rel_s[e * 3 + k] * wsum_s[e]);
        }
        __syncthreads();
    }
}

// ---------------- fused node update: U = silu([h|agg]@n1+b1); h += U@n2 + b2; pos ------
__global__ __launch_bounds__(1024, 1) void k_node(int l, const float* __restrict__ b1n,
                                                  const float* __restrict__ b2n) {
    extern __shared__ float sm[];
    unsigned* wF = (unsigned*)sm;   // 16384
    unsigned* aH = wF + 16384;      // 4096
    unsigned* aL = aH + 4096;       // 4096
    const int t = threadIdx.x;
    const int n0 = blockIdx.x * 64;
    const int wid = t >> 5, lane = t & 31;
    const int mt = wid >> 3, nt0 = (wid & 7) * 2;
    const int grp = lane >> 2, thr = lane & 3;
    const int ee0 = mt * 16 + grp, ee1 = ee0 + 8;
    const int g0 = n0 + ee0, g1 = n0 + ee1;
    const int j00 = nt0 * 8 + 2 * thr, j10 = (nt0 + 1) * 8 + 2 * thr;

    // pos update
    if (t < 192) {
        int gi = n0 + t / 3;
        if (gi < N_NODES) {
            float d = fmaxf(g_deg[gi], 1.0f);
            g_pos[n0 * 3 + t] += g_posdelta[n0 * 3 + t] / d;
        }
    }

    float c0[4] = {0.f, 0.f, 0.f, 0.f}, c1[4] = {0.f, 0.f, 0.f, 0.f};
    for (int halfk = 0; halfk < 2; halfk++) {
        __syncthreads();
        {
            const uint4* s = (const uint4*)(g_pk_n1 + l * 32768 + halfk * 16384);
            uint4* d = (uint4*)wF;
            for (int i = t; i < 4096; i += 1024) d[i] = s[i];
        }
        const float* src = halfk ? g_agg : g_h;
        for (int i = t; i < 4096; i += 1024) {
            int n = i >> 6, jp = i & 63;
            int j0 = jp * 2;
            int gi = n0 + n;
            float2 v = make_float2(0.f, 0.f);
            if (gi < N_NODES) v = *(const float2*)&src[gi * H + j0];
            unsigned lo;
            unsigned hi = split2(v.x, v.y, lo);
            int fi = fragAb(n, j0, 8);
            aH[fi] = hi;
            aL[fi] = lo;
        }
        __syncthreads();
#pragma unroll
        for (int kt = 0; kt < 8; kt++) {
            int aoff = (((mt * 8 + kt) << 5) + lane) << 2;
            uint4 ah = *(const uint4*)&aH[aoff];
            uint4 al = *(const uint4*)&aL[aoff];
            int bi0 = (((nt0 * 8 + kt) << 5) + lane) << 1;
            int bi1 = ((((nt0 + 1) * 8 + kt) << 5) + lane) << 1;
            uint2 bh0 = *(const uint2*)&wF[bi0];
            uint2 bl0 = *(const uint2*)&wF[8192 + bi0];
            uint2 bh1 = *(const uint2*)&wF[bi1];
            uint2 bl1 = *(const uint2*)&wF[8192 + bi1];
            mma3(c0, ah, al, bh0, bl0);
            mma3(c1, ah, al, bh1, bl1);
        }
    }
    // U = silu(c + b1)
    float b00 = __ldg(&b1n[j00]), b01 = __ldg(&b1n[j00 + 1]);
    float b10 = __ldg(&b1n[j10]), b11 = __ldg(&b1n[j10 + 1]);
    float u00 = silu_f(c0[0] + b00), u01 = silu_f(c0[1] + b01);
    float u02 = silu_f(c0[2] + b00), u03 = silu_f(c0[3] + b01);
    float u10 = silu_f(c1[0] + b10), u11 = silu_f(c1[1] + b11);
    float u12 = silu_f(c1[2] + b10), u13 = silu_f(c1[3] + b11);
    __syncthreads();
    {
        unsigned lo;
        unsigned hi;
        int fi;
        hi = split2(u00, u01, lo); fi = fragAb(ee0, j00, 8); aH[fi] = hi; aL[fi] = lo;
        hi = split2(u02, u03, lo); fi = fragAb(ee1, j00, 8); aH[fi] = hi; aL[fi] = lo;
        hi = split2(u10, u11, lo); fi = fragAb(ee0, j10, 8); aH[fi] = hi; aL[fi] = lo;
        hi = split2(u12, u13, lo); fi = fragAb(ee1, j10, 8); aH[fi] = hi; aL[fi] = lo;
    }
    {
        const uint4* s = (const uint4*)(g_pk_n2 + l * 16384);
        uint4* d = (uint4*)wF;
        for (int i = t; i < 4096; i += 1024) d[i] = s[i];
    }
    __syncthreads();

    // second GEMM: h += U @ n2 + b2
    float d0[4] = {0.f, 0.f, 0.f, 0.f}, d1[4] = {0.f, 0.f, 0.f, 0.f};
#pragma unroll
    for (int kt = 0; kt < 8; kt++) {
        int aoff = (((mt * 8 + kt) << 5) + lane) << 2;
        uint4 ah = *(const uint4*)&aH[aoff];
        uint4 al = *(const uint4*)&aL[aoff];
        int bi0 = (((nt0 * 8 + kt) << 5) + lane) << 1;
        int bi1 = ((((nt0 + 1) * 8 + kt) << 5) + lane) << 1;
        uint2 bh0 = *(const uint2*)&wF[bi0];
        uint2 bl0 = *(const uint2*)&wF[8192 + bi0];
        uint2 bh1 = *(const uint2*)&wF[bi1];
        uint2 bl1 = *(const uint2*)&wF[8192 + bi1];
        mma3(d0, ah, al, bh0, bl0);
        mma3(d1, ah, al, bh1, bl1);
    }
    float e00 = __ldg(&b2n[j00]), e01 = __ldg(&b2n[j00 + 1]);
    float e10 = __ldg(&b2n[j10]), e11 = __ldg(&b2n[j10 + 1]);
    if (g0 < N_NODES) {
        float2 h0 = *(float2*)&g_h[g0 * H + j00];
        h0.x += d0[0] + e00; h0.y += d0[1] + e01;
        *(float2*)&g_h[g0 * H + j00] = h0;
        float2 h1 = *(float2*)&g_h[g0 * H + j10];
        h1.x += d1[0] + e10; h1.y += d1[1] + e11;
        *(float2*)&g_h[g0 * H + j10] = h1;
    }
    if (g1 < N_NODES) {
        float2 h0 = *(float2*)&g_h[g1 * H + j00];
        h0.x += d0[2] + e00; h0.y += d0[3] + e01;
        *(float2*)&g_h[g1 * H + j00] = h0;
        float2 h1 = *(float2*)&g_h[g1 * H + j10];
        h1.x += d1[2] + e10; h1.y += d1[3] + e11;
        *(float2*)&g_h[g1 * H + j10] = h1;
    }
}

// ---------------- pooling + readout head fused ----------------
__global__ __launch_bounds__(512) void k_poolhead(
    const float* __restrict__ h1_w, const float* __restrict__ h1_b,
    const float* __restrict__ h2_w, const float* __restrict__ h2_b,
    const float* __restrict__ h3_w, const float* __restrict__ h3_b,
    float* __restrict__ out) {
    __shared__ float red[512], gf[256], z1[128], z2[64];
    const int g = blockIdx.x, t = threadIdx.x;
    const int j = t & 127, w = t >> 7;
    float s = 0.f;
    for (int n = w; n < NPG; n += 4) s += g_h[(g * NPG + n) * H + j];
    red[t] = s;
    __syncthreads();
    if (w == 0) {
        float tot = red[j] + red[128 + j] + red[256 + j] + red[384 + j];
        gf[j] = tot;
        gf[128 + j] = tot * (1.f / (float)NPG);
    }
    __syncthreads();
    if (t < 128) {
        float a = h1_b[t];
        for (int k = 0; k < 256; k++) a += gf[k] * h1_w[k * 128 + t];
        z1[t] = fmaxf(a, 0.f);
    }
    __syncthreads();
    if (t < 64) {
        float a2 = h2_b[t];
        for (int k = 0; k < 128; k++) a2 += z1[k] * h2_w[k * 64 + t];
        z2[t] = fmaxf(a2, 0.f);
    }
    __syncthreads();
    if (t == 0) {
        float a3 = h3_b[0];
        for (int k = 0; k < 64; k++) a3 += z2[k] * h3_w[k];
        out[g] = a3;
    }
}

// ---------------- launch ----------------
extern "C" void kernel_launch(void* const* d_in, const int* in_sizes, int n_in,
                              void* d_out, int out_size) {
    const float* x     = (const float*)d_in[0];
    const float* pos   = (const float*)d_in[1];
    const int*   ei    = (const int*)d_in[2];
    const float* eattr = (const float*)d_in[3];
    const float* Wp    = (const float*)d_in[6];
    const float* bp    = (const float*)d_in[7];
    const float* Wl    = (const float*)d_in[8];
    const float* bl    = (const float*)d_in[9];
    const float* gamma = (const float*)d_in[10];
    const float* beta  = (const float*)d_in[11];
    const float* e_w1  = (const float*)d_in[12];
    const float* e_b1  = (const float*)d_in[13];
    const float* e_w2  = (const float*)d_in[14];
    const float* e_b2  = (const float*)d_in[15];
    const float* c_w1  = (const float*)d_in[16];
    const float* c_b1  = (const float*)d_in[17];
    const float* c_w2  = (const float*)d_in[18];
    const float* n_w1  = (const float*)d_in[19];
    const float* n_b1  = (const float*)d_in[20];
    const float* n_w2  = (const float*)d_in[21];
    const float* n_b2  = (const float*)d_in[22];
    const float* h1_w  = (const float*)d_in[23];
    const float* h1_b  = (const float*)d_in[24];
    const float* h2_w  = (const float*)d_in[25];
    const float* h2_b  = (const float*)d_in[26];
    const float* h3_w  = (const float*)d_in[27];
    const float* h3_b  = (const float*)d_in[28];
    float* out = (float*)d_out;

    const int PROJ_SMEM = (32768 + 4096 + 4096) * 4;
    const int EDGE_SMEM = (16384 * 2 + 8192 * 2 + 128 * 4 + 512
                           + 128 + 384 + 512 + 128 + 128 + 128) * 4;
    const int NODE_SMEM = (16384 + 4096 + 4096) * 4;
    cudaFuncSetAttribute(k_proj, cudaFuncAttributeMaxDynamicSharedMemorySize, PROJ_SMEM);
    cudaFuncSetAttribute(k_edge, cudaFuncAttributeMaxDynamicSharedMemorySize, EDGE_SMEM);
    cudaFuncSetAttribute(k_node, cudaFuncAttributeMaxDynamicSharedMemorySize, NODE_SMEM);

    const int nblocks64 = (N_NODES + 63) / 64;   // 782

    k_embed<<<N_NODES, 128>>>(x, pos, Wp, bp, Wl, bl);
    k_prep<<<256 + DEG_BLOCKS + PACK_BLOCKS, 512>>>(ei, e_w1, e_w2, c_w1, n_w1, n_w2);
    k_bnapply_scan<<<BNA_BLOCKS + 1, 512>>>(gamma, beta);

    for (int l = 0; l < NLAYERS; l++) {
        k_proj<<<nblocks64, 1024, PROJ_SMEM>>>(l, e_b1 + l * H);
        if (l == 0) k_perm<<<(N_EDGES + 511) / 512, 512>>>(ei);
        k_edge<<<148, 1024, EDGE_SMEM>>>(eattr, l, e_b2 + l * H, c_b1 + l * H,
                                         c_w2 + l * H, e_w1 + l * 261 * H);
        k_node<<<nblocks64, 1024, NODE_SMEM>>>(l, n_b1 + l * H, n_b2 + l * H);
    }

    k_poolhead<<<G_GRAPHS, 512>>>(h1_w, h1_b, h2_w, h2_b, h3_w, h3_b, out);
}

// round 13
// speedup vs baseline: 1.7237x; 1.0301x over previous
#include <cuda_runtime.h>
#include <cuda_bf16.h>

#define N_NODES 50000
#define N_EDGES 500000
#define H 128
#define G_GRAPHS 100
#define NPG 500
#define NPROT 400
#define PN 35
#define LN 11
#define NLAYERS 4
#define EPS 1e-5f

// ---------------- scratch ----------------
__device__ float g_h[N_NODES * H];
__device__ float g_P1[N_NODES * H];
__device__ float g_P2[N_NODES * H];
__device__ float g_agg[N_NODES * H];
__device__ float g_pos[N_NODES * 3];
__device__ float g_posdelta[N_NODES * 3];
__device__ float g_deg[N_NODES];
__device__ float g_bnstats[2 * H];
__device__ int g_rowcur[N_NODES];
__device__ int g_srow[N_EDGES];
__device__ int g_scol[N_EDGES];
__device__ int g_sperm[N_EDGES];
// pre-packed bf16 hi/lo weight fragments
__device__ unsigned g_pk_proj[NLAYERS * 32768];  // hi 16384 | lo 16384
__device__ unsigned g_pk_w2[NLAYERS * 16384];    // hi 8192 | lo 8192
__device__ unsigned g_pk_c1[NLAYERS * 16384];
__device__ unsigned g_pk_n1[NLAYERS * 32768];    // [half0: hi|lo][half1: hi|lo]
__device__ unsigned g_pk_n2[NLAYERS * 16384];

__device__ __forceinline__ float silu_f(float x) {
    return x / (1.f + __expf(-x));
}

// ---- bf16 m16n8k16 mma ----
__device__ __forceinline__ void mma_bf16(float* c, const uint4& a, const uint2& b) {
    asm volatile(
        "mma.sync.aligned.m16n8k16.row.col.f32.bf16.bf16.f32 "
        "{%0,%1,%2,%3}, {%4,%5,%6,%7}, {%8,%9}, {%0,%1,%2,%3};"
        : "+f"(c[0]), "+f"(c[1]), "+f"(c[2]), "+f"(c[3])
        : "r"(a.x), "r"(a.y), "r"(a.z), "r"(a.w), "r"(b.x), "r"(b.y));
}
__device__ __forceinline__ unsigned split2(float v0, float v1, unsigned& lo) {
    __nv_bfloat16 h0 = __float2bfloat16(v0);
    __nv_bfloat16 h1 = __float2bfloat16(v1);
    __nv_bfloat16 l0 = __float2bfloat16(v0 - __bfloat162float(h0));
    __nv_bfloat16 l1 = __float2bfloat16(v1 - __bfloat162float(h1));
    lo = (unsigned)__bfloat16_as_ushort(l0) | ((unsigned)__bfloat16_as_ushort(l1) << 16);
    return (unsigned)__bfloat16_as_ushort(h0) | ((unsigned)__bfloat16_as_ushort(h1) << 16);
}
__device__ __forceinline__ void mma3(float* c, const uint4& ah, const uint4& al,
                                     const uint2& bh, const uint2& bl) {
    mma_bf16(c, ah, bh);
    mma_bf16(c, ah, bl);
    mma_bf16(c, al, bh);
}
__device__ __forceinline__ int fragAb(int e, int j0, int KT) {
    int jin = j0 & 15;
    int tid = (jin & 7) >> 1;
    int reg = ((jin >> 3) << 1) | ((e >> 3) & 1);
    int lane = ((e & 7) << 2) | tid;
    return (((e >> 4) * KT + (j0 >> 4)) << 7) + (lane << 2) + reg;
}
__device__ __forceinline__ float bfsum(unsigned hi, unsigned lo) {
    return __bfloat162float(__ushort_as_bfloat16((unsigned short)(hi & 0xffffu)))
         + __bfloat162float(__ushort_as_bfloat16((unsigned short)(lo & 0xffffu)));
}
#define BARH(hid) asm volatile("bar.sync %0, %1;" :: "r"((hid) + 1), "r"(512) : "memory")

// ---------------- K1: embed ----------------
__global__ void k_embed(const float* __restrict__ x, const float* __restrict__ pos_in,
                        const float* __restrict__ Wp, const float* __restrict__ bp,
                        const float* __restrict__ Wl, const float* __restrict__ bl) {
    __shared__ float xs[PN];
    const int i = blockIdx.x;
    const int t = threadIdx.x;
    if (t < PN) xs[t] = x[i * PN + t];
    if (t == 0) g_deg[i] = 0.f;
    if (t < 3) g_pos[i * 3 + t] = pos_in[i * 3 + t];
    if (i == 0 && t < H) { g_bnstats[t] = 0.f; g_bnstats[H + t] = 0.f; }
    __syncthreads();
    const bool isp = (i % NPG) < NPROT;
    const float* W = isp ? Wp : Wl;
    const float* b = isp ? bp : bl;
    const int nk = isp ? PN : LN;
    float acc = b[t];
    for (int k = 0; k < nk; k++) acc += xs[k] * W[k * H + t];
    g_h[i * H + t] = acc;
}

// ---------------- K2: prep = bnstats + deg + weight pack ----------------
#define DEG_BLOCKS ((N_EDGES + 511) / 512)
#define PACK_PER_LAYER (16384 + 8192 + 8192 + 16384 + 8192)  // 57344
#define PACK_ITEMS (NLAYERS * PACK_PER_LAYER)
#define PACK_BLOCKS ((PACK_ITEMS + 511) / 512)
__global__ __launch_bounds__(512) void k_prep(const int* __restrict__ ei,
                                              const float* __restrict__ ew1,
                                              const float* __restrict__ ew2,
                                              const float* __restrict__ cw1,
                                              const float* __restrict__ nw1,
                                              const float* __restrict__ nw2) {
    const int t = threadIdx.x;
    if (blockIdx.x < 256) {
        const int j = t & 127;
        const int g2 = t >> 7;
        float s = 0.f, s2 = 0.f;
        for (int i = blockIdx.x * 4 + g2; i < N_NODES; i += 1024) {
            float v = g_h[i * H + j];
            s += v; s2 += v * v;
        }
        atomicAdd(&g_bnstats[j], s);
        atomicAdd(&g_bnstats[H + j], s2);
        return;
    }
    if (blockIdx.x < 256 + DEG_BLOCKS) {
        const int e = (blockIdx.x - 256) * 512 + t;
        if (e < N_EDGES) atomicAdd(&g_deg[ei[e]], 1.0f);
        return;
    }
    int idx = (blockIdx.x - 256 - DEG_BLOCKS) * 512 + t;
    if (idx >= PACK_ITEMS) return;
    int l = idx / PACK_PER_LAYER;
    int o = idx - l * PACK_PER_LAYER;
    float w0, w1;
    unsigned* hip;
    unsigned* lop;
    if (o < 16384) {            // proj
        int i = o;
        int rb = i & 1, lane = (i >> 1) & 31, kt = (i >> 6) & 7, nt = i >> 9;
        int tid = lane & 3, g = lane >> 2;
        int k0 = kt * 16 + tid * 2 + rb * 8;
        int jj = nt * 8 + g;
        const float* W = ew1 + l * 261 * H;
        int srcrow = (jj < 128) ? k0 : (128 + k0);
        int col = jj & 127;
        w0 = W[srcrow * H + col];
        w1 = W[(srcrow + 1) * H + col];
        hip = g_pk_proj + l * 32768 + i;
        lop = hip + 16384;
    } else if (o < 24576) {     // w2
        int i = o - 16384;
        int rb = i & 1, lane = (i >> 1) & 31, kt = (i >> 6) & 7, nt = i >> 9;
        int tid = lane & 3, g = lane >> 2;
        int k0 = kt * 16 + tid * 2 + rb * 8;
        int n = nt * 8 + g;
        const float* W = ew2 + l * H * H;
        w0 = W[k0 * H + n];
        w1 = W[(k0 + 1) * H + n];
        hip = g_pk_w2 + l * 16384 + i;
        lop = hip + 8192;
    } else if (o < 32768) {     // c1
        int i = o - 24576;
        int rb = i & 1, lane = (i >> 1) & 31, kt = (i >> 6) & 7, nt = i >> 9;
        int tid = lane & 3, g = lane >> 2;
        int k0 = kt * 16 + tid * 2 + rb * 8;
        int n = nt * 8 + g;
        const float* W = cw1 + l * H * H;
        w0 = W[k0 * H + n];
        w1 = W[(k0 + 1) * H + n];
        hip = g_pk_c1 + l * 16384 + i;
        lop = hip + 8192;
    } else if (o < 49152) {     // n1
        int i2 = o - 32768;
        int hk = i2 >> 13;
        int i = i2 & 8191;
        int rb = i & 1, lane = (i >> 1) & 31, kt = (i >> 6) & 7, nt = i >> 9;
        int tid = lane & 3, g = lane >> 2;
        int k0 = hk * 128 + kt * 16 + tid * 2 + rb * 8;
        int n = nt * 8 + g;
        const float* W = nw1 + l * 2 * H * H;
        w0 = W[k0 * H + n];
        w1 = W[(k0 + 1) * H + n];
        hip = g_pk_n1 + l * 32768 + hk * 16384 + i;
        lop = hip + 8192;
    } else {                    // n2
        int i = o - 49152;
        int rb = i & 1, lane = (i >> 1) & 31, kt = (i >> 6) & 7, nt = i >> 9;
        int tid = lane & 3, g = lane >> 2;
        int k0 = kt * 16 + tid * 2 + rb * 8;
        int n = nt * 8 + g;
        const float* W = nw2 + l * H * H;
        w0 = W[k0 * H + n];
        w1 = W[(k0 + 1) * H + n];
        hip = g_pk_n2 + l * 16384 + i;
        lop = hip + 8192;
    }
    unsigned lo;
    unsigned hi = split2(w0, w1, lo);
    *hip = hi;
    *lop = lo;
}

// ---------------- K3: bnapply + degree scan ----------------
#define BNA_BLOCKS ((N_NODES * H) / 512)
__global__ __launch_bounds__(512) void k_bnapply_scan(const float* __restrict__ gamma,
                                                      const float* __restrict__ beta) {
    const int t = threadIdx.x;
    if (blockIdx.x < BNA_BLOCKS) {
        const int idx = blockIdx.x * 512 + t;
        const int j = idx & (H - 1);
        const float inv_n = 1.f / (float)N_NODES;
        float mu = g_bnstats[j] * inv_n;
        float var = g_bnstats[H + j] * inv_n - mu * mu;
        g_h[idx] = (g_h[idx] - mu) * rsqrtf(var + EPS) * gamma[j] + beta[j];
    } else {
        __shared__ int sums[512];
        const int chunk = 98;
        int base = t * chunk;
        int lim = min(base + chunk, N_NODES);
        int s = 0;
        for (int i = base; i < lim; i++) s += (int)g_deg[i];
        sums[t] = s;
        __syncthreads();
        for (int off = 1; off < 512; off <<= 1) {
            int v = (t >= off) ? sums[t - off] : 0;
            __syncthreads();
            sums[t] += v;
            __syncthreads();
        }
        int run = (t == 0) ? 0 : sums[t - 1];
        for (int i = base; i < lim; i++) {
            g_rowcur[i] = run;
            run += (int)g_deg[i];
        }
    }
}

// ---------------- counting-sort scatter ----------------
__global__ __launch_bounds__(512) void k_perm(const int* __restrict__ ei) {
    const int e = blockIdx.x * 512 + threadIdx.x;
    if (e >= N_EDGES) return;
    int r = ei[e];
    int p = atomicAdd(&g_rowcur[r], 1);
    g_srow[p] = r;
    g_scol[p] = ei[N_EDGES + e];
    g_sperm[p] = e;
}

// ---------------- proj: bf16 3-MMA ----------------
__global__ __launch_bounds__(1024, 1) void k_proj(int l, const float* __restrict__ b1) {
    extern __shared__ float sm[];
    unsigned* wF = (unsigned*)sm;       // 32768
    unsigned* aH = wF + 32768;          // 4096
    unsigned* aL = aH + 4096;           // 4096
    const int t = threadIdx.x;
    const int n0 = blockIdx.x * 64;

    {
        const uint4* s = (const uint4*)(g_pk_proj + l * 32768);
        uint4* d = (uint4*)wF;
        for (int i = t; i < 8192; i += 1024) d[i] = s[i];
    }
    for (int i = t; i < 4096; i += 1024) {
        int n = i >> 6, jp = i & 63;
        int j0 = jp * 2;
        int gi = n0 + n;
        float2 v = make_float2(0.f, 0.f);
        if (gi < N_NODES) v = *(const float2*)&g_h[gi * H + j0];
        unsigned lo;
        unsigned hi = split2(v.x, v.y, lo);
        int fi = fragAb(n, j0, 8);
        aH[fi] = hi;
        aL[fi] = lo;
    }
    {
        const float4 z4 = make_float4(0.f, 0.f, 0.f, 0.f);
        for (int i = t; i < 2048; i += 1024) {
            int gi = n0 + (i >> 5);
            if (gi < N_NODES) *(float4*)&g_agg[gi * H + (i & 31) * 4] = z4;
        }
    }
    if (t < 192) {
        int gi = n0 + t / 3;
        if (gi < N_NODES) g_posdelta[gi * 3 + t % 3] = 0.f;
    }
    __syncthreads();

    const int wid = t >> 5, lane = t & 31;
    const int mt = wid >> 3;
    const int ng = wid & 7;
    const int grp = lane >> 2, thr = lane & 3;
    float c[4][4];
#pragma unroll
    for (int q = 0; q < 4; q++)
#pragma unroll
        for (int r = 0; r < 4; r++) c[q][r] = 0.f;

#pragma unroll
    for (int kt = 0; kt < 8; kt++) {
        int aoff = (((mt * 8 + kt) << 5) + lane) << 2;
        uint4 ah = *(const uint4*)&aH[aoff];
        uint4 al = *(const uint4*)&aL[aoff];
#pragma unroll
        for (int q = 0; q < 4; q++) {
            int nt = ng * 4 + q;
            int bi = (((nt * 8 + kt) << 5) + lane) << 1;
            uint2 bh = *(const uint2*)&wF[bi];
            uint2 bl = *(const uint2*)&wF[16384 + bi];
            mma3(c[q], ah, al, bh, bl);
        }
    }

    const int ee0 = mt * 16 + grp, ee1 = ee0 + 8;
    const int g0 = n0 + ee0, g1 = n0 + ee1;
#pragma unroll
    for (int q = 0; q < 4; q++) {
        int nt = ng * 4 + q;
        int jj0 = nt * 8 + 2 * thr;
        int half = jj0 >> 7;
        int j = jj0 & 127;
        float* outp = half ? g_P2 : g_P1;
        float bb0 = half ? 0.f : __ldg(&b1[j]);
        float bb1 = half ? 0.f : __ldg(&b1[j + 1]);
        if (g0 < N_NODES)
            *(float2*)&outp[g0 * H + j] = make_float2(c[q][0] + bb0, c[q][1] + bb1);
        if (g1 < N_NODES)
            *(float2*)&outp[g1 * H + j] = make_float2(c[q][2] + bb0, c[q][3] + bb1);
    }
}

// ---------------- fused edge kernel: TWO independent 512-thread pipelines ----------------
__global__ __launch_bounds__(1024, 1) void k_edge(
    const float* __restrict__ eattr, int l,
    const float* __restrict__ b2, const float* __restrict__ cb1,
    const float* __restrict__ cw2, const float* __restrict__ ew1) {
    extern __shared__ float sm[];
    unsigned* w2F = (unsigned*)sm;       // 16384 (hi 8192 | lo 8192)
    unsigned* c1F = w2F + 16384;         // 16384
    unsigned* actH = c1F + 16384;        // 8192 (two halves of 4096)
    unsigned* actL = actH + 8192;        // 8192
    float* b2_s  = (float*)(actL + 8192);  // 128
    float* cb1_s = b2_s + 128;           // 128
    float* c2_s  = cb1_s + 128;          // 128
    float* wd2_s = c2_s + 128;           // 128
    float* wea_s = wd2_s + 128;          // 512
    float* d2_s  = wea_s + 512;          // 128
    float* rel_s = d2_s + 128;           // 384
    float* ea_s  = rel_s + 384;          // 512
    float* wsum_s = ea_s + 512;          // 128
    int* row_s = (int*)(wsum_s + 128);   // 128
    int* col_s = row_s + 128;            // 128

    const int t = threadIdx.x;
    {
        const uint4* s2 = (const uint4*)(g_pk_w2 + l * 16384);
        const uint4* s1 = (const uint4*)(g_pk_c1 + l * 16384);
        uint4* d2 = (uint4*)w2F;
        uint4* d1 = (uint4*)c1F;
        for (int i = t; i < 4096; i += 1024) { d2[i] = s2[i]; d1[i] = s1[i]; }
    }
    if (t < 128) {
        b2_s[t] = b2[t]; cb1_s[t] = cb1[t]; c2_s[t] = cw2[t];
        wd2_s[t] = ew1[256 * H + t];
    }
    if (t >= 128 && t < 640) wea_s[t - 128] = ew1[257 * H + (t - 128)];
    __syncthreads();

    const int half = t >> 9;       // 0..1  pipeline id
    const int t5 = t & 511;
    const int w5 = t5 >> 5;        // 0..15
    const int lane = t5 & 31;
    const int mt5 = w5 >> 2;       // 0..3  (16 edges each)
    const int ng = w5 & 3;         // 0..3  (4 n-tiles each)
    const int grp = lane >> 2;
    const int thr = lane & 3;
    const int ee0 = mt5 * 16 + grp, ee1 = ee0 + 8;
    const int hb = half * 4096;    // fragment base
    const int he = half * 64;      // metadata base
    const int NT64 = (N_EDGES + 63) / 64;   // 7813

    for (int tile = blockIdx.x * 2 + half; tile < NT64; tile += 2 * gridDim.x) {
        const int e0 = tile * 64;
        if (t5 < 64) {
            wsum_s[he + t5] = 0.f;
            int sidx = e0 + t5;
            int r = -1, c = 0, pe = 0;
            if (sidx < N_EDGES) { r = g_srow[sidx]; c = g_scol[sidx]; pe = g_sperm[sidx]; }
            row_s[he + t5] = r; col_s[he + t5] = c;
            float4 a = make_float4(0.f, 0.f, 0.f, 0.f);
            if (r >= 0) a = *(const float4*)&eattr[pe * 4];
            int rr = r < 0 ? 0 : r;
            float rx = g_pos[rr * 3 + 0] - g_pos[c * 3 + 0];
            float ry = g_pos[rr * 3 + 1] - g_pos[c * 3 + 1];
            float rz = g_pos[rr * 3 + 2] - g_pos[c * 3 + 2];
            rel_s[(he + t5) * 3 + 0] = rx; rel_s[(he + t5) * 3 + 1] = ry;
            rel_s[(he + t5) * 3 + 2] = rz;
            d2_s[he + t5] = rx * rx + ry * ry + rz * rz;
            ea_s[(he + t5) * 4 + 0] = a.x; ea_s[(he + t5) * 4 + 1] = a.y;
            ea_s[(he + t5) * 4 + 2] = a.z; ea_s[(he + t5) * 4 + 3] = a.w;
        }
        BARH(half);

        // Phase A: warp handles 4 consecutive edges (sorted rows -> P1 reuse)
        {
            const int j0 = lane * 4;
            int prevrow = -1;
            float4 p1;
#pragma unroll
            for (int rep = 0; rep < 4; rep++) {
                int e = w5 * 4 + rep;
                int r = row_s[he + e], c = col_s[he + e];
                int rr = r < 0 ? 0 : r;
                if (rr != prevrow) {
                    p1 = *(const float4*)&g_P1[rr * H + j0];
                    prevrow = rr;
                }
                float4 p2 = *(const float4*)&g_P2[c * H + j0];
                float dd = d2_s[he + e];
                float v0 = p1.x + p2.x + dd * wd2_s[j0];
                float v1 = p1.y + p2.y + dd * wd2_s[j0 + 1];
                float v2 = p1.z + p2.z + dd * wd2_s[j0 + 2];
                float v3 = p1.w + p2.w + dd * wd2_s[j0 + 3];
#pragma unroll
                for (int a2 = 0; a2 < 4; a2++) {
                    float eav = ea_s[(he + e) * 4 + a2];
                    v0 += eav * wea_s[a2 * H + j0];
                    v1 += eav * wea_s[a2 * H + j0 + 1];
                    v2 += eav * wea_s[a2 * H + j0 + 2];
                    v3 += eav * wea_s[a2 * H + j0 + 3];
                }
                unsigned lo;
                unsigned hi = split2(silu_f(v0), silu_f(v1), lo);
                int fi = hb + fragAb(e, j0, 8);
                actH[fi] = hi; actL[fi] = lo;
                hi = split2(silu_f(v2), silu_f(v3), lo);
                fi = hb + fragAb(e, j0 + 2, 8);
                actH[fi] = hi; actL[fi] = lo;
            }
        }
        BARH(half);

        // Phase B: m = silu(hid @ W2 + b2)
        float cB[4][4];
#pragma unroll
        for (int q = 0; q < 4; q++) {
            int jc = (ng * 4 + q) * 8 + 2 * thr;
            cB[q][0] = b2_s[jc]; cB[q][1] = b2_s[jc + 1];
            cB[q][2] = cB[q][0]; cB[q][3] = cB[q][1];
        }
#pragma unroll
        for (int kt = 0; kt < 8; kt++) {
            int aoff = hb + ((((mt5 * 8 + kt) << 5) + lane) << 2);
            uint4 ah = *(const uint4*)&actH[aoff];
            uint4 al = *(const uint4*)&actL[aoff];
#pragma unroll
            for (int q = 0; q < 4; q++) {
                int bi = ((((ng * 4 + q) * 8 + kt) << 5) + lane) << 1;
                uint2 bh = *(const uint2*)&w2F[bi];
                uint2 bl = *(const uint2*)&w2F[8192 + bi];
                mma3(cB[q], ah, al, bh, bl);
            }
        }
        BARH(half);
#pragma unroll
        for (int q = 0; q < 4; q++) {
            int jq = (ng * 4 + q) * 8 + 2 * thr;
            unsigned lo0, lo1;
            unsigned hi0 = split2(silu_f(cB[q][0]), silu_f(cB[q][1]), lo0);
            unsigned hi1 = split2(silu_f(cB[q][2]), silu_f(cB[q][3]), lo1);
            int f0 = hb + fragAb(ee0, jq, 8);
            int f1 = hb + fragAb(ee1, jq, 8);
            actH[f0] = hi0; actL[f0] = lo0;
            actH[f1] = hi1; actL[f1] = lo1;
        }
        BARH(half);

        // Phase C: w = silu(m@C1 + cb1) @ C2
        {
            float cC[4][4];
#pragma unroll
            for (int q = 0; q < 4; q++) {
                int jc = (ng * 4 + q) * 8 + 2 * thr;
                cC[q][0] = cb1_s[jc]; cC[q][1] = cb1_s[jc + 1];
                cC[q][2] = cC[q][0]; cC[q][3] = cC[q][1];
            }
#pragma unroll
            for (int kt = 0; kt < 8; kt++) {
                int aoff = hb + ((((mt5 * 8 + kt) << 5) + lane) << 2);
                uint4 ah = *(const uint4*)&actH[aoff];
                uint4 al = *(const uint4*)&actL[aoff];
#pragma unroll
                for (int q = 0; q < 4; q++) {
                    int bi = ((((ng * 4 + q) * 8 + kt) << 5) + lane) << 1;
                    uint2 bh = *(const uint2*)&c1F[bi];
                    uint2 bl = *(const uint2*)&c1F[8192 + bi];
                    mma3(cC[q], ah, al, bh, bl);
                }
            }
            float sl = 0.f, sh = 0.f;
#pragma unroll
            for (int q = 0; q < 4; q++) {
                int jq = (ng * 4 + q) * 8 + 2 * thr;
                sl += silu_f(cC[q][0]) * c2_s[jq] + silu_f(cC[q][1]) * c2_s[jq + 1];
                sh += silu_f(cC[q][2]) * c2_s[jq] + silu_f(cC[q][3]) * c2_s[jq + 1];
            }
            sl += __shfl_xor_sync(0xffffffffu, sl, 1);
            sl += __shfl_xor_sync(0xffffffffu, sl, 2);
            sh += __shfl_xor_sync(0xffffffffu, sh, 1);
            sh += __shfl_xor_sync(0xffffffffu, sh, 2);
            if (thr == 0) {
                atomicAdd(&wsum_s[he + ee0], sl);
                atomicAdd(&wsum_s[he + ee1], sh);
            }
        }
        BARH(half);

        // Phase D: j-pair segment scan scatter (64 edges, 8 groups of 8)
        {
            const int jp = t5 & 63;
            const int j0 = jp * 2;
            const int q = t5 >> 6;          // 0..7
            const int ebeg = q * 8;
            float acc0 = 0.f, acc1 = 0.f;
            int cur = row_s[he + ebeg];
#pragma unroll
            for (int i = 0; i < 8; i++) {
                int e = ebeg + i;
                int r = row_s[he + e];
                int fi = hb + fragAb(e, j0, 8);
                unsigned hi = actH[fi], lo = actL[fi];
                float v0 = bfsum(hi, lo);
                float v1 = bfsum(hi >> 16, lo >> 16);
                if (r != cur) {
                    if (cur >= 0) {
                        atomicAdd(&g_agg[cur * H + j0], acc0);
                        atomicAdd(&g_agg[cur * H + j0 + 1], acc1);
                    }
                    acc0 = 0.f; acc1 = 0.f;
                    cur = r;
                }
                acc0 += v0; acc1 += v1;
            }
            if (cur >= 0) {
                atomicAdd(&g_agg[cur * H + j0], acc0);
                atomicAdd(&g_agg[cur * H + j0 + 1], acc1);
            }
        }
        if (t5 < 192) {
            int e = t5 / 3, k = t5 % 3;
            int r = row_s[he + e];
            if (r >= 0)
                atomicAdd(&g_posdelta[r * 3 + k], rel_s[(he + e) * 3 + k] * wsum_s[he + e]);
        }
        BARH(half);
    }
}

// ---------------- fused node update ----------------
__global__ __launch_bounds__(1024, 1) void k_node(int l, const float* __restrict__ b1n,
                                                  const float* __restrict__ b2n) {
    extern __shared__ float sm[];
    unsigned* wF = (unsigned*)sm;   // 16384
    unsigned* aH = wF + 16384;      // 4096
    unsigned* aL = aH + 4096;       // 4096
    const int t = threadIdx.x;
    const int n0 = blockIdx.x * 64;
    const int wid = t >> 5, lane = t & 31;
    const int mt = wid >> 3, nt0 = (wid & 7) * 2;
    const int grp = lane >> 2, thr = lane & 3;
    const int ee0 = mt * 16 + grp, ee1 = ee0 + 8;
    const int g0 = n0 + ee0, g1 = n0 + ee1;
    const int j00 = nt0 * 8 + 2 * thr, j10 = (nt0 + 1) * 8 + 2 * thr;

    if (t < 192) {
        int gi = n0 + t / 3;
        if (gi < N_NODES) {
            float d = fmaxf(g_deg[gi], 1.0f);
            g_pos[n0 * 3 + t] += g_posdelta[n0 * 3 + t] / d;
        }
    }

    float c0[4] = {0.f, 0.f, 0.f, 0.f}, c1[4] = {0.f, 0.f, 0.f, 0.f};
    for (int halfk = 0; halfk < 2; halfk++) {
        __syncthreads();
        {
            const uint4* s = (const uint4*)(g_pk_n1 + l * 32768 + halfk * 16384);
            uint4* d = (uint4*)wF;
            for (int i = t; i < 4096; i += 1024) d[i] = s[i];
        }
        const float* src = halfk ? g_agg : g_h;
        for (int i = t; i < 4096; i += 1024) {
            int n = i >> 6, jp = i & 63;
            int j0 = jp * 2;
            int gi = n0 + n;
            float2 v = make_float2(0.f, 0.f);
            if (gi < N_NODES) v = *(const float2*)&src[gi * H + j0];
            unsigned lo;
            unsigned hi = split2(v.x, v.y, lo);
            int fi = fragAb(n, j0, 8);
            aH[fi] = hi;
            aL[fi] = lo;
        }
        __syncthreads();
#pragma unroll
        for (int kt = 0; kt < 8; kt++) {
            int aoff = (((mt * 8 + kt) << 5) + lane) << 2;
            uint4 ah = *(const uint4*)&aH[aoff];
            uint4 al = *(const uint4*)&aL[aoff];
            int bi0 = (((nt0 * 8 + kt) << 5) + lane) << 1;
            int bi1 = ((((nt0 + 1) * 8 + kt) << 5) + lane) << 1;
            uint2 bh0 = *(const uint2*)&wF[bi0];
            uint2 bl0 = *(const uint2*)&wF[8192 + bi0];
            uint2 bh1 = *(const uint2*)&wF[bi1];
            uint2 bl1 = *(const uint2*)&wF[8192 + bi1];
            mma3(c0, ah, al, bh0, bl0);
            mma3(c1, ah, al, bh1, bl1);
        }
    }
    float b00 = __ldg(&b1n[j00]), b01 = __ldg(&b1n[j00 + 1]);
    float b10 = __ldg(&b1n[j10]), b11 = __ldg(&b1n[j10 + 1]);
    float u00 = silu_f(c0[0] + b00), u01 = silu_f(c0[1] + b01);
    float u02 = silu_f(c0[2] + b00), u03 = silu_f(c0[3] + b01);
    float u10 = silu_f(c1[0] + b10), u11 = silu_f(c1[1] + b11);
    float u12 = silu_f(c1[2] + b10), u13 = silu_f(c1[3] + b11);
    __syncthreads();
    {
        unsigned lo;
        unsigned hi;
        int fi;
        hi = split2(u00, u01, lo); fi = fragAb(ee0, j00, 8); aH[fi] = hi; aL[fi] = lo;
        hi = split2(u02, u03, lo); fi = fragAb(ee1, j00, 8); aH[fi] = hi; aL[fi] = lo;
        hi = split2(u10, u11, lo); fi = fragAb(ee0, j10, 8); aH[fi] = hi; aL[fi] = lo;
        hi = split2(u12, u13, lo); fi = fragAb(ee1, j10, 8); aH[fi] = hi; aL[fi] = lo;
    }
    {
        const uint4* s = (const uint4*)(g_pk_n2 + l * 16384);
        uint4* d = (uint4*)wF;
        for (int i = t; i < 4096; i += 1024) d[i] = s[i];
    }
    __syncthreads();

    float d0[4] = {0.f, 0.f, 0.f, 0.f}, d1[4] = {0.f, 0.f, 0.f, 0.f};
#pragma unroll
    for (int kt = 0; kt < 8; kt++) {
        int aoff = (((mt * 8 + kt) << 5) + lane) << 2;
        uint4 ah = *(const uint4*)&aH[aoff];
        uint4 al = *(const uint4*)&aL[aoff];
        int bi0 = (((nt0 * 8 + kt) << 5) + lane) << 1;
        int bi1 = ((((nt0 + 1) * 8 + kt) << 5) + lane) << 1;
        uint2 bh0 = *(const uint2*)&wF[bi0];
        uint2 bl0 = *(const uint2*)&wF[8192 + bi0];
        uint2 bh1 = *(const uint2*)&wF[bi1];
        uint2 bl1 = *(const uint2*)&wF[8192 + bi1];
        mma3(d0, ah, al, bh0, bl0);
        mma3(d1, ah, al, bh1, bl1);
    }
    float e00 = __ldg(&b2n[j00]), e01 = __ldg(&b2n[j00 + 1]);
    float e10 = __ldg(&b2n[j10]), e11 = __ldg(&b2n[j10 + 1]);
    if (g0 < N_NODES) {
        float2 h0 = *(float2*)&g_h[g0 * H + j00];
        h0.x += d0[0] + e00; h0.y += d0[1] + e01;
        *(float2*)&g_h[g0 * H + j00] = h0;
        float2 h1 = *(float2*)&g_h[g0 * H + j10];
        h1.x += d1[0] + e10; h1.y += d1[1] + e11;
        *(float2*)&g_h[g0 * H + j10] = h1;
    }
    if (g1 < N_NODES) {
        float2 h0 = *(float2*)&g_h[g1 * H + j00];
        h0.x += d0[2] + e00; h0.y += d0[3] + e01;
        *(float2*)&g_h[g1 * H + j00] = h0;
        float2 h1 = *(float2*)&g_h[g1 * H + j10];
        h1.x += d1[2] + e10; h1.y += d1[3] + e11;
        *(float2*)&g_h[g1 * H + j10] = h1;
    }
}

// ---------------- pooling + readout head fused ----------------
__global__ __launch_bounds__(512) void k_poolhead(
    const float* __restrict__ h1_w, const float* __restrict__ h1_b,
    const float* __restrict__ h2_w, const float* __restrict__ h2_b,
    const float* __restrict__ h3_w, const float* __restrict__ h3_b,
    float* __restrict__ out) {
    __shared__ float red[512], gf[256], z1[128], z2[64];
    const int g = blockIdx.x, t = threadIdx.x;
    const int j = t & 127, w = t >> 7;
    float s = 0.f;
    for (int n = w; n < NPG; n += 4) s += g_h[(g * NPG + n) * H + j];
    red[t] = s;
    __syncthreads();
    if (w == 0) {
        float tot = red[j] + red[128 + j] + red[256 + j] + red[384 + j];
        gf[j] = tot;
        gf[128 + j] = tot * (1.f / (float)NPG);
    }
    __syncthreads();
    if (t < 128) {
        float a = h1_b[t];
        for (int k = 0; k < 256; k++) a += gf[k] * h1_w[k * 128 + t];
        z1[t] = fmaxf(a, 0.f);
    }
    __syncthreads();
    if (t < 64) {
        float a2 = h2_b[t];
        for (int k = 0; k < 128; k++) a2 += z1[k] * h2_w[k * 64 + t];
        z2[t] = fmaxf(a2, 0.f);
    }
    __syncthreads();
    if (t == 0) {
        float a3 = h3_b[0];
        for (int k = 0; k < 64; k++) a3 += z2[k] * h3_w[k];
        out[g] = a3;
    }
}

// ---------------- launch ----------------
extern "C" void kernel_launch(void* const* d_in, const int* in_sizes, int n_in,
                              void* d_out, int out_size) {
    const float* x     = (const float*)d_in[0];
    const float* pos   = (const float*)d_in[1];
    const int*   ei    = (const int*)d_in[2];
    const float* eattr = (const float*)d_in[3];
    const float* Wp    = (const float*)d_in[6];
    const float* bp    = (const float*)d_in[7];
    const float* Wl    = (const float*)d_in[8];
    const float* bl    = (const float*)d_in[9];
    const float* gamma = (const float*)d_in[10];
    const float* beta  = (const float*)d_in[11];
    const float* e_w1  = (const float*)d_in[12];
    const float* e_b1  = (const float*)d_in[13];
    const float* e_w2  = (const float*)d_in[14];
    const float* e_b2  = (const float*)d_in[15];
    const float* c_w1  = (const float*)d_in[16];
    const float* c_b1  = (const float*)d_in[17];
    const float* c_w2  = (const float*)d_in[18];
    const float* n_w1  = (const float*)d_in[19];
    const float* n_b1  = (const float*)d_in[20];
    const float* n_w2  = (const float*)d_in[21];
    const float* n_b2  = (const float*)d_in[22];
    const float* h1_w  = (const float*)d_in[23];
    const float* h1_b  = (const float*)d_in[24];
    const float* h2_w  = (const float*)d_in[25];
    const float* h2_b  = (const float*)d_in[26];
    const float* h3_w  = (const float*)d_in[27];
    const float* h3_b  = (const float*)d_in[28];
    float* out = (float*)d_out;

    const int PROJ_SMEM = (32768 + 4096 + 4096) * 4;
    const int EDGE_SMEM = (16384 * 2 + 8192 * 2 + 128 * 4 + 512
                           + 128 + 384 + 512 + 128 + 128 + 128) * 4;
    const int NODE_SMEM = (16384 + 4096 + 4096) * 4;
    cudaFuncSetAttribute(k_proj, cudaFuncAttributeMaxDynamicSharedMemorySize, PROJ_SMEM);
    cudaFuncSetAttribute(k_edge, cudaFuncAttributeMaxDynamicSharedMemorySize, EDGE_SMEM);
    cudaFuncSetAttribute(k_node, cudaFuncAttributeMaxDynamicSharedMemorySize, NODE_SMEM);

    const int nblocks64 = (N_NODES + 63) / 64;   // 782

    k_embed<<<N_NODES, 128>>>(x, pos, Wp, bp, Wl, bl);
    k_prep<<<256 + DEG_BLOCKS + PACK_BLOCKS, 512>>>(ei, e_w1, e_w2, c_w1, n_w1, n_w2);
    k_bnapply_scan<<<BNA_BLOCKS + 1, 512>>>(gamma, beta);

    for (int l = 0; l < NLAYERS; l++) {
        k_proj<<<nblocks64, 1024, PROJ_SMEM>>>(l, e_b1 + l * H);
        if (l == 0) k_perm<<<(N_EDGES + 511) / 512, 512>>>(ei);
        k_edge<<<148, 1024, EDGE_SMEM>>>(eattr, l, e_b2 + l * H, c_b1 + l * H,
                                         c_w2 + l * H, e_w1 + l * 261 * H);
        k_node<<<nblocks64, 1024, NODE_SMEM>>>(l, n_b1 + l * H, n_b2 + l * H);
    }

    k_poolhead<<<G_GRAPHS, 512>>>(h1_w, h1_b, h2_w, h2_b, h3_w, h3_b, out);
}